// round 7
// baseline (speedup 1.0000x reference)
#include <cuda_runtime.h>
#include <cuda_bf16.h>
#include <cstdint>
#include <cstddef>

#define DEVI __device__ __forceinline__

// ------------------------------------------------------------------
// Scratch (__device__ globals; allocation-free rule)
// ------------------------------------------------------------------
__device__ float g_scale[2][8192];
__device__ float g_rmax[8192];
__device__ float g_wmax[9][768];
// int8 planes, pre-permuted to mma fragment layout
__device__ int8_t g_Ah[8192ull * 768];
__device__ int8_t g_Am[8192ull * 768];
__device__ int8_t g_Bh[9ull * 768 * 768];
__device__ int8_t g_Bm[9ull * 768 * 768];
// pre-split bf16 Q/K/V planes [br][b][h][n][64] (attention input)
__device__ __nv_bfloat16 g_Qh[3ull * 8 * 12 * 1024 * 64];
__device__ __nv_bfloat16 g_Qm[3ull * 8 * 12 * 1024 * 64];
__device__ __nv_bfloat16 g_Kh[3ull * 8 * 12 * 1024 * 64];
__device__ __nv_bfloat16 g_Km[3ull * 8 * 12 * 1024 * 64];
__device__ __nv_bfloat16 g_Vh[3ull * 8 * 12 * 1024 * 64];
__device__ __nv_bfloat16 g_Vm[3ull * 8 * 12 * 1024 * 64];

// ------------------------------------------------------------------
// Helpers
// ------------------------------------------------------------------
DEVI uint32_t smaddr(const void* p) { return (uint32_t)__cvta_generic_to_shared(p); }

DEVI uint32_t packh(float a, float b) {
    __nv_bfloat16 ha = __float2bfloat16(a), hb = __float2bfloat16(b);
    uint16_t ua, ub;
    memcpy(&ua, &ha, 2); memcpy(&ub, &hb, 2);
    return ((uint32_t)ub << 16) | ua;
}
DEVI uint32_t packm(float a, float b, uint32_t h) {
    uint16_t ua = (uint16_t)(h & 0xffffu), ub = (uint16_t)(h >> 16);
    __nv_bfloat16 ha, hb;
    memcpy(&ha, &ua, 2); memcpy(&hb, &ub, 2);
    return packh(a - __bfloat162float(ha), b - __bfloat162float(hb));
}

DEVI void cp16(uint32_t dst, const void* src) {
    asm volatile("cp.async.cg.shared.global [%0], [%1], 16;" :: "r"(dst), "l"(src) : "memory");
}
DEVI void cp8(uint32_t dst, const void* src) {
    asm volatile("cp.async.ca.shared.global [%0], [%1], 8;" :: "r"(dst), "l"(src) : "memory");
}
DEVI void cp_commit() { asm volatile("cp.async.commit_group;" ::: "memory"); }
DEVI void cp_wait0()  { asm volatile("cp.async.wait_group 0;" ::: "memory"); }
DEVI void cp_wait1()  { asm volatile("cp.async.wait_group 1;" ::: "memory"); }

DEVI void ldsm4(uint32_t r[4], uint32_t a) {
    asm volatile("ldmatrix.sync.aligned.m8n8.x4.shared.b16 {%0,%1,%2,%3}, [%4];"
                 : "=r"(r[0]), "=r"(r[1]), "=r"(r[2]), "=r"(r[3]) : "r"(a));
}
DEVI void ldsm4t(uint32_t r[4], uint32_t a) {
    asm volatile("ldmatrix.sync.aligned.m8n8.x4.trans.shared.b16 {%0,%1,%2,%3}, [%4];"
                 : "=r"(r[0]), "=r"(r[1]), "=r"(r[2]), "=r"(r[3]) : "r"(a));
}
DEVI void mma16(float d[4], const uint32_t a[4], const uint32_t b[2]) {
    asm volatile(
        "mma.sync.aligned.m16n8k16.row.col.f32.bf16.bf16.f32 "
        "{%0,%1,%2,%3}, {%4,%5,%6,%7}, {%8,%9}, {%0,%1,%2,%3};"
        : "+f"(d[0]), "+f"(d[1]), "+f"(d[2]), "+f"(d[3])
        : "r"(a[0]), "r"(a[1]), "r"(a[2]), "r"(a[3]), "r"(b[0]), "r"(b[1]));
}
DEVI void mma8i(int d[4], const uint32_t a[4], const uint32_t b[2]) {
    asm volatile(
        "mma.sync.aligned.m16n8k32.row.col.s32.s8.s8.s32 "
        "{%0,%1,%2,%3}, {%4,%5,%6,%7}, {%8,%9}, {%0,%1,%2,%3};"
        : "+r"(d[0]), "+r"(d[1]), "+r"(d[2]), "+r"(d[3])
        : "r"(a[0]), "r"(a[1]), "r"(a[2]), "r"(a[3]), "r"(b[0]), "r"(b[1]));
}

// encode 4 floats -> 4 hi-bytes + 4 mid-bytes (x = s*(256*i1 + i2))
DEVI void enc4(float4 v, float f, uint32_t& hi, uint32_t& mi) {
    uint32_t h = 0, m = 0;
    float vv[4] = { v.x, v.y, v.z, v.w };
#pragma unroll
    for (int i = 0; i < 4; ++i) {
        float q  = vv[i] * f;
        float i1 = fminf(fmaxf(rintf(q * 0.00390625f), -127.f), 127.f);
        float i2 = fminf(fmaxf(rintf(fmaf(-256.f, i1, q)), -127.f), 127.f);
        h |= ((uint32_t)(int)i1 & 0xffu) << (8 * i);
        m |= ((uint32_t)(int)i2 & 0xffu) << (8 * i);
    }
    hi = h; mi = m;
}

// ------------------------------------------------------------------
// Kernel 1: per-row branch scalars + row max
// ------------------------------------------------------------------
__global__ __launch_bounds__(256) void scales_kernel(const float* __restrict__ x) {
    __shared__ float red[8], redm[8];
    const int row = blockIdx.x;
    const float* xr = x + (size_t)row * 768;
    float ss = 0.f, mx = 0.f;
    for (int i = threadIdx.x; i < 768; i += 256) {
        float v = xr[i];
        ss = fmaf(v, v, ss);
        mx = fmaxf(mx, fabsf(v));
    }
#pragma unroll
    for (int o = 16; o; o >>= 1) {
        ss += __shfl_xor_sync(0xffffffffu, ss, o);
        mx = fmaxf(mx, __shfl_xor_sync(0xffffffffu, mx, o));
    }
    if ((threadIdx.x & 31) == 0) { red[threadIdx.x >> 5] = ss; redm[threadIdx.x >> 5] = mx; }
    __syncthreads();
    if (threadIdx.x == 0) {
        float t = 0.f, m = 1e-30f;
#pragma unroll
        for (int i = 0; i < 8; ++i) { t += red[i]; m = fmaxf(m, redm[i]); }
        g_rmax[row] = m;
        float n = fmaxf(sqrtf(t), 1e-5f);
        const float sc = 0.316227766016837933f;     // sqrt(0.1)
        float a = sc * n;
        float th = tanhf(a);
        float s_pre = th / a;
        float norm_h = th / sc;
        float maxn = (1.0f - 4e-3f) / sc;
        float s_h = (norm_h > maxn) ? s_pre * (maxn / norm_h) : s_pre;
        float arg = fminf(a, 1.0f - 1e-5f);
        float art = 0.5f * logf((1.0f + arg) / (1.0f - arg));
        float s_s = art / (n * sc);
        g_scale[0][row] = s_h;
        g_scale[1][row] = s_s;
    }
}

// ------------------------------------------------------------------
// Kernel 1b: encode x into int8 planes, fragment-linear layout.
// unit = rb*24 + kb; bytes of thread = A-fragment of (16-row blk, 32-k blk)
// ------------------------------------------------------------------
__global__ __launch_bounds__(256) void prep_x_i8(const float* __restrict__ x) {
    const int id = blockIdx.x * 256 + threadIdx.x;   // 512*24*32 threads
    const int lane = id & 31, unit = id >> 5;
    const int kb = unit % 24, rb = unit / 24;
    const int g = lane >> 2, tg = lane & 3;
    const int r0 = rb * 16 + g, r1 = r0 + 8;
    const int k0 = kb * 32 + tg * 4;
    const float f0 = 32639.f / g_rmax[r0];
    const float f1 = 32639.f / g_rmax[r1];
    float4 v00 = *(const float4*)&x[(size_t)r0 * 768 + k0];
    float4 v10 = *(const float4*)&x[(size_t)r1 * 768 + k0];
    float4 v01 = *(const float4*)&x[(size_t)r0 * 768 + k0 + 16];
    float4 v11 = *(const float4*)&x[(size_t)r1 * 768 + k0 + 16];
    uint32_t h0, m0, h1, m1, h2, m2, h3, m3;
    enc4(v00, f0, h0, m0); enc4(v10, f1, h1, m1);
    enc4(v01, f0, h2, m2); enc4(v11, f1, h3, m3);
    size_t o = ((size_t)unit * 32 + lane) * 16;
    *(uint4*)&g_Ah[o] = make_uint4(h0, h1, h2, h3);
    *(uint4*)&g_Am[o] = make_uint4(m0, m1, m2, m3);
}

// ------------------------------------------------------------------
// Kernel 1c: W row max, then encode W into int8 planes (B-fragment layout)
// ------------------------------------------------------------------
__global__ __launch_bounds__(256) void wmax_kernel(
    const float* __restrict__ wq, const float* __restrict__ wk, const float* __restrict__ wv) {
    __shared__ float redm[8];
    const int row = blockIdx.x, mat = blockIdx.y;
    const int typ = mat / 3, br = mat % 3;
    const float* W = (typ == 0 ? wq : typ == 1 ? wk : wv) + (size_t)br * 768 * 768 + (size_t)row * 768;
    float mx = 0.f;
    for (int i = threadIdx.x; i < 768; i += 256) mx = fmaxf(mx, fabsf(W[i]));
#pragma unroll
    for (int o = 16; o; o >>= 1) mx = fmaxf(mx, __shfl_xor_sync(0xffffffffu, mx, o));
    if ((threadIdx.x & 31) == 0) redm[threadIdx.x >> 5] = mx;
    __syncthreads();
    if (threadIdx.x == 0) {
        float m = 1e-30f;
#pragma unroll
        for (int i = 0; i < 8; ++i) m = fmaxf(m, redm[i]);
        g_wmax[mat][row] = m;
    }
}

__global__ __launch_bounds__(256) void prep_w_i8(
    const float* __restrict__ wq, const float* __restrict__ wk, const float* __restrict__ wv) {
    const int id = blockIdx.x * 256 + threadIdx.x;   // 9*96*24*32 threads
    const int lane = id & 31, unit = id >> 5;
    const int kb = unit % 24, t = unit / 24;
    const int nb = t % 96, mat = t / 96;
    const int typ = mat / 3, br = mat % 3;
    const float* W = (typ == 0 ? wq : typ == 1 ? wk : wv) + (size_t)br * 768 * 768;
    const int g = lane >> 2, tg = lane & 3;
    const int row = nb * 8 + g;
    const int k0 = kb * 32 + tg * 4;
    const float f = 32639.f / g_wmax[mat][row];
    float4 a = *(const float4*)&W[(size_t)row * 768 + k0];
    float4 b = *(const float4*)&W[(size_t)row * 768 + k0 + 16];
    uint32_t h0, m0, h1, m1;
    enc4(a, f, h0, m0); enc4(b, f, h1, m1);
    size_t o = ((size_t)unit * 32 + lane) * 8;
    *(uint2*)&g_Bh[o] = make_uint2(h0, h1);
    *(uint2*)&g_Bm[o] = make_uint2(m0, m1);
}

// ------------------------------------------------------------------
// Kernel 2: int8 projection GEMM. CTA = 128x64 tile, warp = 32x32.
// Two s32 accumulators (hh weight 2^16, cross weight 2^8), mm dropped.
// ------------------------------------------------------------------
#define PI_STAGE 12288

__global__ __launch_bounds__(256, 2) void proj_i8(
    const float* __restrict__ bq, const float* __restrict__ bk, const float* __restrict__ bv)
{
    __shared__ char sm[2 * PI_STAGE];
    const int mat = blockIdx.z, br = mat % 3, typ = mat / 3;
    const int rt = blockIdx.x, ct = blockIdx.y;
    const int tid = threadIdx.x, lane = tid & 31, warp = tid >> 5;
    const int wr = warp >> 1, wc = warp & 1;     // warp tile 32x32
    const int g = lane >> 2, tg = lane & 3;
    const uint32_t smb = smaddr(sm);

    const int8_t* gA[2] = { g_Ah, g_Am };
    const int8_t* gB[2] = { g_Bh, g_Bm };

    int acch[2][4][4], accc[2][4][4];
#pragma unroll
    for (int i = 0; i < 2; ++i)
#pragma unroll
        for (int j = 0; j < 4; ++j)
#pragma unroll
            for (int k = 0; k < 4; ++k) { acch[i][j][k] = 0; accc[i][j][k] = 0; }

    auto load_chunk = [&](int kb, int st) {
        const uint32_t base = smb + st * PI_STAGE;
#pragma unroll
        for (int it = 0; it < 2; ++it) {         // A: 512 x 16B
            int idx = it * 256 + tid;
            int ln = idx & 31, rbl = (idx >> 5) & 7, pl = idx >> 8;
            cp16(base + pl * 4096 + rbl * 512 + ln * 16,
                 gA[pl] + (((size_t)(rt * 8 + rbl) * 24 + kb) * 32 + ln) * 16);
        }
#pragma unroll
        for (int it = 0; it < 2; ++it) {         // B: 512 x 8B
            int idx = it * 256 + tid;
            int ln = idx & 31, nbl = (idx >> 5) & 7, pl = idx >> 8;
            cp8(base + 8192 + pl * 2048 + nbl * 256 + ln * 8,
                gB[pl] + (((size_t)(mat * 96 + ct * 8 + nbl) * 24 + kb) * 32 + ln) * 8);
        }
    };

    load_chunk(0, 0);
    cp_commit();

    for (int kb = 0; kb < 24; ++kb) {
        const int st = kb & 1;
        if (kb < 23) { load_chunk(kb + 1, st ^ 1); cp_commit(); cp_wait1(); }
        else cp_wait0();
        __syncthreads();

        const char* base = sm + st * PI_STAGE;
        uint4 ahv[2], amv[2];
#pragma unroll
        for (int mt = 0; mt < 2; ++mt) {
            ahv[mt] = *(const uint4*)(base + (wr * 2 + mt) * 512 + lane * 16);
            amv[mt] = *(const uint4*)(base + 4096 + (wr * 2 + mt) * 512 + lane * 16);
        }
        uint2 bhv[4], bmv[4];
#pragma unroll
        for (int p = 0; p < 4; ++p) {
            bhv[p] = *(const uint2*)(base + 8192 + (wc * 4 + p) * 256 + lane * 8);
            bmv[p] = *(const uint2*)(base + 8192 + 2048 + (wc * 4 + p) * 256 + lane * 8);
        }
#pragma unroll
        for (int mt = 0; mt < 2; ++mt) {
            const uint32_t ah[4] = { ahv[mt].x, ahv[mt].y, ahv[mt].z, ahv[mt].w };
            const uint32_t am[4] = { amv[mt].x, amv[mt].y, amv[mt].z, amv[mt].w };
#pragma unroll
            for (int p = 0; p < 4; ++p) {
                const uint32_t bh[2] = { bhv[p].x, bhv[p].y };
                const uint32_t bm[2] = { bmv[p].x, bmv[p].y };
                mma8i(acch[mt][p], ah, bh);
                mma8i(accc[mt][p], ah, bm);
                mma8i(accc[mt][p], am, bh);
            }
        }
        __syncthreads();
    }

    // epilogue: scale + bias, split to bf16 hi/mid planes [br][b][h][n][64]
    const float* Bb = (typ == 0 ? bq : typ == 1 ? bk : bv) + br * 768;
    __nv_bfloat16* dh = (typ == 0 ? g_Qh : typ == 1 ? g_Kh : g_Vh);
    __nv_bfloat16* dm = (typ == 0 ? g_Qm : typ == 1 ? g_Km : g_Vm);
    const int h = ct;
    const float inv = 1.f / 32639.f;
#pragma unroll
    for (int mt = 0; mt < 2; ++mt) {
        int r0 = rt * 128 + wr * 32 + mt * 16 + g;
#pragma unroll
        for (int rr = 0; rr < 2; ++rr) {
            int R = r0 + rr * 8;
            float sb = (br == 0) ? 1.0f : g_scale[br - 1][R];
            float sa = sb * g_rmax[R] * inv;
            int b = R >> 10, n = R & 1023;
#pragma unroll
            for (int p = 0; p < 4; ++p) {
                int d = wc * 32 + p * 8 + tg * 2;
                int col = ct * 64 + d;
                float sw0 = g_wmax[mat][col] * inv;
                float sw1 = g_wmax[mat][col + 1] * inv;
                float2 bi = *(const float2*)&Bb[col];
                int c0 = rr * 2, c1 = rr * 2 + 1;
                float v0 = sa * sw0 * fmaf(65536.f, (float)acch[mt][p][c0], 256.f * (float)accc[mt][p][c0]) + bi.x;
                float v1 = sa * sw1 * fmaf(65536.f, (float)acch[mt][p][c1], 256.f * (float)accc[mt][p][c1]) + bi.y;
                size_t base = (((size_t)(br * 8 + b) * 12 + h) * 1024 + n) * 64 + d;
                uint32_t hh = packh(v0, v1);
                *(uint32_t*)&dh[base] = hh;
                *(uint32_t*)&dm[base] = packm(v0, v1, hh);
            }
        }
    }
}

// ------------------------------------------------------------------
// Kernel 3: flash attention, bf16 3-pass (unchanged from R6).
// ------------------------------------------------------------------
#define AQ_PLANE 9216
#define AKV_PLANE 4608
#define SKV_(st, pl) ((__nv_bfloat16(*)[72])(as_ + 2 * AQ_PLANE + ((st) * 4 + (pl)) * AKV_PLANE))
#define A_SMEM ((2 * AQ_PLANE + 8 * AKV_PLANE) * 2)

__global__ __launch_bounds__(256, 2) void attn_kernel(float* __restrict__ out) {
    extern __shared__ __nv_bfloat16 as_[];
    __nv_bfloat16 (*sQh)[72] = (__nv_bfloat16(*)[72])(as_);
    __nv_bfloat16 (*sQm)[72] = (__nv_bfloat16(*)[72])(as_ + AQ_PLANE);

    const int qt = blockIdx.x, h = blockIdx.y, bb = blockIdx.z;
    const int tid = threadIdx.x, lane = tid & 31, warp = tid >> 5;
    const int g = lane >> 2, tg = lane & 3;
    const int l7 = lane & 7, l8 = lane & 8, l16 = (lane & 16) >> 1;
    const int r0 = warp * 16 + g;

    for (int brn = 0; brn < 3; ++brn) {
        const size_t hb = (((size_t)brn * 8 + bb) * 12 + h) * (size_t)(1024 * 64);
        const __nv_bfloat16* KVp[4] = { g_Kh + hb, g_Km + hb, g_Vh + hb, g_Vm + hb };
        const __nv_bfloat16* Qp[2]  = { g_Qh + hb + (size_t)qt * 128 * 64,
                                        g_Qm + hb + (size_t)qt * 128 * 64 };

        auto loadKV = [&](int jt, int st) {
#pragma unroll
            for (int i = 0; i < 8; ++i) {
                int idx = i * 256 + tid;
                int seg = idx & 7, row = (idx >> 3) & 63, pl = idx >> 9;
                cp16(smaddr(&SKV_(st, pl)[row][seg * 8]),
                     KVp[pl] + (size_t)(jt * 64 + row) * 64 + seg * 8);
            }
        };

#pragma unroll
        for (int i = 0; i < 8; ++i) {
            int idx = i * 256 + tid;
            int seg = idx & 7, row = (idx >> 3) & 127, pl = idx >> 10;
            cp16(smaddr(&(pl ? sQm : sQh)[row][seg * 8]),
                 Qp[pl] + (size_t)row * 64 + seg * 8);
        }
        loadKV(0, 0);
        cp_commit();

        float m0 = -1e30f, m1 = -1e30f, l0 = 0.f, l1 = 0.f;
        float oa[8][4];
#pragma unroll
        for (int i = 0; i < 8; ++i)
#pragma unroll
            for (int j = 0; j < 4; ++j) oa[i][j] = 0.f;

        for (int jt = 0; jt < 16; ++jt) {
            const int st = jt & 1;
            if (jt < 15) { loadKV(jt + 1, st ^ 1); cp_commit(); cp_wait1(); }
            else cp_wait0();
            __syncthreads();

            __nv_bfloat16 (*sKh)[72] = SKV_(st, 0), (*sKm)[72] = SKV_(st, 1);
            __nv_bfloat16 (*sVh)[72] = SKV_(st, 2), (*sVm)[72] = SKV_(st, 3);

            float sf[8][4];
#pragma unroll
            for (int i = 0; i < 8; ++i)
#pragma unroll
                for (int j = 0; j < 4; ++j) sf[i][j] = 0.f;
#pragma unroll
            for (int ks = 0; ks < 4; ++ks) {
                const int k0 = ks * 16;
                uint32_t qh[4], qm[4];
                ldsm4(qh, smaddr(&sQh[warp * 16 + l7 + l8][k0 + l16]));
                ldsm4(qm, smaddr(&sQm[warp * 16 + l7 + l8][k0 + l16]));
                uint32_t kh_[4][4], km_[4][4];
#pragma unroll
                for (int p = 0; p < 4; ++p) {
                    int n0 = p * 16 + l7 + l16;
                    ldsm4(kh_[p], smaddr(&sKh[n0][k0 + l8]));
                    ldsm4(km_[p], smaddr(&sKm[n0][k0 + l8]));
                }
#pragma unroll
                for (int p = 0; p < 4; ++p) {
                    mma16(sf[2 * p],     qh, kh_[p]);
                    mma16(sf[2 * p + 1], qh, kh_[p] + 2);
                }
#pragma unroll
                for (int p = 0; p < 4; ++p) {
                    mma16(sf[2 * p],     qh, km_[p]);
                    mma16(sf[2 * p + 1], qh, km_[p] + 2);
                }
#pragma unroll
                for (int p = 0; p < 4; ++p) {
                    mma16(sf[2 * p],     qm, kh_[p]);
                    mma16(sf[2 * p + 1], qm, kh_[p] + 2);
                }
            }

            float t0 = -1e30f, t1 = -1e30f;
#pragma unroll
            for (int nt = 0; nt < 8; ++nt) {
                t0 = fmaxf(t0, fmaxf(sf[nt][0], sf[nt][1]));
                t1 = fmaxf(t1, fmaxf(sf[nt][2], sf[nt][3]));
            }
            t0 = fmaxf(t0, __shfl_xor_sync(0xffffffffu, t0, 1));
            t0 = fmaxf(t0, __shfl_xor_sync(0xffffffffu, t0, 2));
            t1 = fmaxf(t1, __shfl_xor_sync(0xffffffffu, t1, 1));
            t1 = fmaxf(t1, __shfl_xor_sync(0xffffffffu, t1, 2));
            float mn0 = fmaxf(m0, t0), mn1 = fmaxf(m1, t1);
            float a0 = __expf(m0 - mn0), a1 = __expf(m1 - mn1);
            m0 = mn0; m1 = mn1;

            float rs0 = 0.f, rs1 = 0.f;
#pragma unroll
            for (int nt = 0; nt < 8; ++nt) {
                sf[nt][0] = __expf(sf[nt][0] - mn0);
                sf[nt][1] = __expf(sf[nt][1] - mn0);
                sf[nt][2] = __expf(sf[nt][2] - mn1);
                sf[nt][3] = __expf(sf[nt][3] - mn1);
                rs0 += sf[nt][0] + sf[nt][1];
                rs1 += sf[nt][2] + sf[nt][3];
            }
            l0 = l0 * a0 + rs0;
            l1 = l1 * a1 + rs1;
#pragma unroll
            for (int nt = 0; nt < 8; ++nt) {
                oa[nt][0] *= a0; oa[nt][1] *= a0;
                oa[nt][2] *= a1; oa[nt][3] *= a1;
            }

#pragma unroll
            for (int ks = 0; ks < 4; ++ks) {
                uint32_t ph[4], pm[4];
                ph[0] = packh(sf[2 * ks][0],     sf[2 * ks][1]);
                ph[1] = packh(sf[2 * ks][2],     sf[2 * ks][3]);
                ph[2] = packh(sf[2 * ks + 1][0], sf[2 * ks + 1][1]);
                ph[3] = packh(sf[2 * ks + 1][2], sf[2 * ks + 1][3]);
                pm[0] = packm(sf[2 * ks][0],     sf[2 * ks][1],     ph[0]);
                pm[1] = packm(sf[2 * ks][2],     sf[2 * ks][3],     ph[1]);
                pm[2] = packm(sf[2 * ks + 1][0], sf[2 * ks + 1][1], ph[2]);
                pm[3] = packm(sf[2 * ks + 1][2], sf[2 * ks + 1][3], ph[3]);
                const int kv0 = ks * 16 + l7 + l8;
                uint32_t vh_[4][4], vm_[4][4];
#pragma unroll
                for (int p = 0; p < 4; ++p) {
                    int d0 = p * 16 + l16;
                    ldsm4t(vh_[p], smaddr(&sVh[kv0][d0]));
                    ldsm4t(vm_[p], smaddr(&sVm[kv0][d0]));
                }
#pragma unroll
                for (int p = 0; p < 4; ++p) {
                    mma16(oa[2 * p],     ph, vh_[p]);
                    mma16(oa[2 * p + 1], ph, vh_[p] + 2);
                }
#pragma unroll
                for (int p = 0; p < 4; ++p) {
                    mma16(oa[2 * p],     ph, vm_[p]);
                    mma16(oa[2 * p + 1], ph, vm_[p] + 2);
                }
#pragma unroll
                for (int p = 0; p < 4; ++p) {
                    mma16(oa[2 * p],     pm, vh_[p]);
                    mma16(oa[2 * p + 1], pm, vh_[p] + 2);
                }
            }
            __syncthreads();
        }

        float L0 = l0 + __shfl_xor_sync(0xffffffffu, l0, 1);
        L0 += __shfl_xor_sync(0xffffffffu, L0, 2);
        float L1 = l1 + __shfl_xor_sync(0xffffffffu, l1, 1);
        L1 += __shfl_xor_sync(0xffffffffu, L1, 2);
        float i0 = 1.f / L0, i1 = 1.f / L1;
#pragma unroll
        for (int nt = 0; nt < 8; ++nt) {
            int d = nt * 8 + tg * 2;
            size_t base = ((size_t)bb * 1024 + (size_t)(qt * 128 + r0)) * 768 + h * 64 + d;
            float2 v0 = make_float2(oa[nt][0] * i0, oa[nt][1] * i0);
            float2 v1 = make_float2(oa[nt][2] * i1, oa[nt][3] * i1);
            if (brn) {
                float2 o0 = *(float2*)&out[base];
                float2 o1 = *(float2*)&out[base + (size_t)8 * 768];
                v0.x += o0.x; v0.y += o0.y; v1.x += o1.x; v1.y += o1.y;
            }
            *(float2*)&out[base]                   = v0;
            *(float2*)&out[base + (size_t)8 * 768] = v1;
        }
    }
}

// ------------------------------------------------------------------
extern "C" void kernel_launch(void* const* d_in, const int* in_sizes, int n_in,
                              void* d_out, int out_size) {
    (void)in_sizes; (void)n_in; (void)out_size;
    const float* x  = (const float*)d_in[0];
    const float* wq = (const float*)d_in[1];
    const float* bq = (const float*)d_in[2];
    const float* wk = (const float*)d_in[3];
    const float* bk = (const float*)d_in[4];
    const float* wv = (const float*)d_in[5];
    const float* bv = (const float*)d_in[6];
    float* out = (float*)d_out;

    scales_kernel<<<8192, 256>>>(x);
    prep_x_i8<<<1536, 256>>>(x);
    wmax_kernel<<<dim3(768, 9), 256>>>(wq, wk, wv);
    prep_w_i8<<<2592, 256>>>(wq, wk, wv);

    proj_i8<<<dim3(64, 12, 9), 256>>>(bq, bk, bv);

    cudaFuncSetAttribute(attn_kernel, cudaFuncAttributeMaxDynamicSharedMemorySize, A_SMEM);
    attn_kernel<<<dim3(8, 12, 8), 256, A_SMEM>>>(out);
}

// round 8
// speedup vs baseline: 1.7452x; 1.7452x over previous
#include <cuda_runtime.h>
#include <cuda_bf16.h>
#include <cstdint>
#include <cstddef>

#define DEVI __device__ __forceinline__

// ------------------------------------------------------------------
// Scratch (__device__ globals; allocation-free rule)
// ------------------------------------------------------------------
__device__ int g_tickP, g_tickA;
__device__ __nv_bfloat16 g_xh[3ull * 8192 * 768];
__device__ __nv_bfloat16 g_xm[3ull * 8192 * 768];
__device__ __nv_bfloat16 g_Wh[9ull * 768 * 768];
__device__ __nv_bfloat16 g_Wm[9ull * 768 * 768];
__device__ __nv_bfloat16 g_Qh[3ull * 8 * 12 * 1024 * 64];
__device__ __nv_bfloat16 g_Qm[3ull * 8 * 12 * 1024 * 64];
__device__ __nv_bfloat16 g_Kh[3ull * 8 * 12 * 1024 * 64];
__device__ __nv_bfloat16 g_Km[3ull * 8 * 12 * 1024 * 64];
__device__ __nv_bfloat16 g_Vh[3ull * 8 * 12 * 1024 * 64];
__device__ __nv_bfloat16 g_Vm[3ull * 8 * 12 * 1024 * 64];

// ------------------------------------------------------------------
// Helpers
// ------------------------------------------------------------------
DEVI uint32_t smaddr(const void* p) { return (uint32_t)__cvta_generic_to_shared(p); }

DEVI uint32_t packh(float a, float b) {
    __nv_bfloat16 ha = __float2bfloat16(a), hb = __float2bfloat16(b);
    uint16_t ua, ub;
    memcpy(&ua, &ha, 2); memcpy(&ub, &hb, 2);
    return ((uint32_t)ub << 16) | ua;
}
DEVI uint32_t packm(float a, float b, uint32_t h) {
    uint16_t ua = (uint16_t)(h & 0xffffu), ub = (uint16_t)(h >> 16);
    __nv_bfloat16 ha, hb;
    memcpy(&ha, &ua, 2); memcpy(&hb, &ub, 2);
    return packh(a - __bfloat162float(ha), b - __bfloat162float(hb));
}

DEVI void cp16(uint32_t dst, const void* src) {
    asm volatile("cp.async.cg.shared.global [%0], [%1], 16;" :: "r"(dst), "l"(src) : "memory");
}
DEVI void cp_commit() { asm volatile("cp.async.commit_group;" ::: "memory"); }
DEVI void cp_wait0()  { asm volatile("cp.async.wait_group 0;" ::: "memory"); }
DEVI void cp_wait1()  { asm volatile("cp.async.wait_group 1;" ::: "memory"); }

DEVI void ldsm4(uint32_t r[4], uint32_t a) {
    asm volatile("ldmatrix.sync.aligned.m8n8.x4.shared.b16 {%0,%1,%2,%3}, [%4];"
                 : "=r"(r[0]), "=r"(r[1]), "=r"(r[2]), "=r"(r[3]) : "r"(a));
}
DEVI void ldsm4t(uint32_t r[4], uint32_t a) {
    asm volatile("ldmatrix.sync.aligned.m8n8.x4.trans.shared.b16 {%0,%1,%2,%3}, [%4];"
                 : "=r"(r[0]), "=r"(r[1]), "=r"(r[2]), "=r"(r[3]) : "r"(a));
}
DEVI void mma16(float d[4], const uint32_t a[4], const uint32_t b[2]) {
    asm volatile(
        "mma.sync.aligned.m16n8k16.row.col.f32.bf16.bf16.f32 "
        "{%0,%1,%2,%3}, {%4,%5,%6,%7}, {%8,%9}, {%0,%1,%2,%3};"
        : "+f"(d[0]), "+f"(d[1]), "+f"(d[2]), "+f"(d[3])
        : "r"(a[0]), "r"(a[1]), "r"(a[2]), "r"(a[3]), "r"(b[0]), "r"(b[1]));
}

// ------------------------------------------------------------------
// Kernel 1: fused row scalars + branch-scaled bf16 hi/mid split of x.
// Also resets the persistent-tile tickets (block 0).
// ------------------------------------------------------------------
__global__ __launch_bounds__(256) void prep_x_fused(const float* __restrict__ x) {
    __shared__ float red[8];
    __shared__ float sbr[2];
    const int row = blockIdx.x, tid = threadIdx.x;
    if (row == 0 && tid == 0) { g_tickP = 0; g_tickA = 0; }

    float4 v = make_float4(0.f, 0.f, 0.f, 0.f);
    if (tid < 192) v = *(const float4*)&x[(size_t)row * 768 + tid * 4];
    float ss = fmaf(v.x, v.x, fmaf(v.y, v.y, fmaf(v.z, v.z, v.w * v.w)));
#pragma unroll
    for (int o = 16; o; o >>= 1) ss += __shfl_xor_sync(0xffffffffu, ss, o);
    if ((tid & 31) == 0) red[tid >> 5] = ss;
    __syncthreads();
    if (tid == 0) {
        float t = 0.f;
#pragma unroll
        for (int i = 0; i < 8; ++i) t += red[i];
        float n = fmaxf(sqrtf(t), 1e-5f);
        const float sc = 0.316227766016837933f;     // sqrt(0.1)
        float a = sc * n;
        float th = tanhf(a);
        float s_pre = th / a;
        float norm_h = th / sc;
        float maxn = (1.0f - 4e-3f) / sc;
        sbr[0] = (norm_h > maxn) ? s_pre * (maxn / norm_h) : s_pre;
        float arg = fminf(a, 1.0f - 1e-5f);
        float art = 0.5f * logf((1.0f + arg) / (1.0f - arg));
        sbr[1] = art / (n * sc);
    }
    __syncthreads();
    if (tid < 192) {
        const int c = tid * 4;
#pragma unroll
        for (int br = 0; br < 3; ++br) {
            float s = (br == 0) ? 1.0f : sbr[br - 1];
            float4 w = make_float4(v.x * s, v.y * s, v.z * s, v.w * s);
            size_t o = ((size_t)br * 8192 + row) * 768 + c;
            uint32_t h0 = packh(w.x, w.y), h1 = packh(w.z, w.w);
            *(uint32_t*)&g_xh[o]     = h0;
            *(uint32_t*)&g_xh[o + 2] = h1;
            *(uint32_t*)&g_xm[o]     = packm(w.x, w.y, h0);
            *(uint32_t*)&g_xm[o + 2] = packm(w.z, w.w, h1);
        }
    }
}

// ------------------------------------------------------------------
// Kernel 1c: pre-split weights into bf16 planes
// ------------------------------------------------------------------
__global__ __launch_bounds__(192) void prep_w(
    const float* __restrict__ wq, const float* __restrict__ wk, const float* __restrict__ wv) {
    const int row = blockIdx.x, mat = blockIdx.y;
    const int typ = mat / 3, br = mat % 3;
    const float* W = (typ == 0 ? wq : typ == 1 ? wk : wv) + (size_t)br * 768 * 768;
    const int c = threadIdx.x * 4;
    float4 v = *(const float4*)&W[(size_t)row * 768 + c];
    size_t o = ((size_t)mat * 768 + row) * 768 + c;
    uint32_t h0 = packh(v.x, v.y), h1 = packh(v.z, v.w);
    *(uint32_t*)&g_Wh[o]     = h0;
    *(uint32_t*)&g_Wh[o + 2] = h1;
    *(uint32_t*)&g_Wm[o]     = packm(v.x, v.y, h0);
    *(uint32_t*)&g_Wm[o + 2] = packm(v.z, v.w, h1);
}

// ------------------------------------------------------------------
// Kernel 2: persistent projection GEMM, bf16 3-pass, cp.async 2-stage.
// 296 CTAs pull 3456 tiles (128x128) from a ticket counter.
// ------------------------------------------------------------------
#define P_PLANE 5120                 // 128*40 bf16 elems per plane
#define SA_(st, pl) ((__nv_bfloat16(*)[40])(ps + ((st) * 2 + (pl)) * P_PLANE))
#define SB_(st, pl) ((__nv_bfloat16(*)[40])(ps + (4 + (st) * 2 + (pl)) * P_PLANE))
#define P_SMEM (8 * P_PLANE * 2)     // 81920 B
#define P_TILES 3456

__global__ __launch_bounds__(256, 2) void proj_mma(
    const float* __restrict__ bq, const float* __restrict__ bk, const float* __restrict__ bv)
{
    extern __shared__ __nv_bfloat16 ps[];
    __shared__ int s_t;
    const int tid = threadIdx.x, lane = tid & 31, warp = tid >> 5;
    const int wr = warp >> 1, wc = warp & 1;
    const int l7 = lane & 7, l8 = lane & 8, l16 = (lane & 16) >> 1;

    for (;;) {
        __syncthreads();                 // smem stage + s_t reuse guard
        if (tid == 0) s_t = atomicAdd(&g_tickP, 1);
        __syncthreads();
        const int t = s_t;
        if (t >= P_TILES) break;
        const int rt = t & 63, rem = t >> 6;
        const int ct = rem % 6, mat = rem / 6;
        const int br = mat % 3, typ = mat / 3;

        const __nv_bfloat16* Ap[2] = {
            g_xh + ((size_t)br * 8192 + rt * 128) * 768,
            g_xm + ((size_t)br * 8192 + rt * 128) * 768 };
        const __nv_bfloat16* Bp[2] = {
            g_Wh + ((size_t)mat * 768 + ct * 128) * 768,
            g_Wm + ((size_t)mat * 768 + ct * 128) * 768 };

        float acc[2][8][4];
#pragma unroll
        for (int i = 0; i < 2; ++i)
#pragma unroll
            for (int j = 0; j < 8; ++j)
#pragma unroll
                for (int k = 0; k < 4; ++k) acc[i][j][k] = 0.f;

        auto load_chunk = [&](int kt, int st) {
#pragma unroll
            for (int i = 0; i < 4; ++i) {
                int idx = i * 256 + tid;
                int seg = idx & 3, row = (idx >> 2) & 127, pl = idx >> 9;
                cp16(smaddr(&SA_(st, pl)[row][seg * 8]),
                     Ap[pl] + (size_t)row * 768 + kt * 32 + seg * 8);
            }
#pragma unroll
            for (int i = 0; i < 4; ++i) {
                int idx = i * 256 + tid;
                int seg = idx & 3, row = (idx >> 2) & 127, pl = idx >> 9;
                cp16(smaddr(&SB_(st, pl)[row][seg * 8]),
                     Bp[pl] + (size_t)row * 768 + kt * 32 + seg * 8);
            }
        };

        load_chunk(0, 0);
        cp_commit();

        for (int kt = 0; kt < 24; ++kt) {
            const int st = kt & 1;
            if (kt < 23) { load_chunk(kt + 1, st ^ 1); cp_commit(); cp_wait1(); }
            else cp_wait0();
            __syncthreads();

            __nv_bfloat16 (*sAh)[40] = SA_(st, 0), (*sAm)[40] = SA_(st, 1);
            __nv_bfloat16 (*sBh)[40] = SB_(st, 0), (*sBm)[40] = SB_(st, 1);
#pragma unroll
            for (int ks = 0; ks < 2; ++ks) {
                const int k0 = ks * 16;
                uint32_t ah[2][4], am_[2][4];
#pragma unroll
                for (int mt = 0; mt < 2; ++mt) {
                    int r0 = wr * 32 + mt * 16 + l7 + l8;
                    ldsm4(ah[mt],  smaddr(&sAh[r0][k0 + l16]));
                    ldsm4(am_[mt], smaddr(&sAm[r0][k0 + l16]));
                }
                uint32_t bh[4][4], bm_[4][4];
#pragma unroll
                for (int p = 0; p < 4; ++p) {
                    int n0 = wc * 64 + p * 16 + l7 + l16;
                    ldsm4(bh[p],  smaddr(&sBh[n0][k0 + l8]));
                    ldsm4(bm_[p], smaddr(&sBm[n0][k0 + l8]));
                }
#pragma unroll
                for (int p = 0; p < 4; ++p)
#pragma unroll
                    for (int mt = 0; mt < 2; ++mt) {
                        mma16(acc[mt][2 * p],     ah[mt], bh[p]);
                        mma16(acc[mt][2 * p + 1], ah[mt], bh[p] + 2);
                    }
#pragma unroll
                for (int p = 0; p < 4; ++p)
#pragma unroll
                    for (int mt = 0; mt < 2; ++mt) {
                        mma16(acc[mt][2 * p],     ah[mt], bm_[p]);
                        mma16(acc[mt][2 * p + 1], ah[mt], bm_[p] + 2);
                    }
#pragma unroll
                for (int p = 0; p < 4; ++p)
#pragma unroll
                    for (int mt = 0; mt < 2; ++mt) {
                        mma16(acc[mt][2 * p],     am_[mt], bh[p]);
                        mma16(acc[mt][2 * p + 1], am_[mt], bh[p] + 2);
                    }
            }
            __syncthreads();
        }

        // epilogue: bias, split to bf16 hi/mid planes [br][b][h][n][64]
        const float* Bb = (typ == 0 ? bq : typ == 1 ? bk : bv) + br * 768;
        __nv_bfloat16* dh = (typ == 0 ? g_Qh : typ == 1 ? g_Kh : g_Vh);
        __nv_bfloat16* dm = (typ == 0 ? g_Qm : typ == 1 ? g_Km : g_Vm);
        const int h  = ct * 2 + wc;
        const int bb = (rt * 128) >> 10;
        const int nb = (rt * 128) & 1023;
        const int tg = lane & 3, g = lane >> 2;
#pragma unroll
        for (int mt = 0; mt < 2; ++mt) {
            int r = wr * 32 + mt * 16 + g;
#pragma unroll
            for (int nt = 0; nt < 8; ++nt) {
                int d = nt * 8 + tg * 2;
                float2 bi = *(const float2*)&Bb[h * 64 + d];
                float v0 = acc[mt][nt][0] + bi.x, v1 = acc[mt][nt][1] + bi.y;
                float v2 = acc[mt][nt][2] + bi.x, v3 = acc[mt][nt][3] + bi.y;
                size_t base = ((((size_t)br * 8 + bb) * 12 + h) * 1024 + (nb + r)) * 64 + d;
                uint32_t h0 = packh(v0, v1), h1 = packh(v2, v3);
                *(uint32_t*)&dh[base]          = h0;
                *(uint32_t*)&dh[base + 8 * 64] = h1;
                *(uint32_t*)&dm[base]          = packm(v0, v1, h0);
                *(uint32_t*)&dm[base + 8 * 64] = packm(v2, v3, h1);
            }
        }
    }
}

// ------------------------------------------------------------------
// Kernel 3: persistent flash attention, bf16 3-pass, 64-row KV tiles.
// 296 CTAs pull 768 (qt,h,b) tiles; branch loop inside (deterministic).
// ------------------------------------------------------------------
#define AQ_PLANE 9216
#define AKV_PLANE 4608
#define SKV_(st, pl) ((__nv_bfloat16(*)[72])(as_ + 2 * AQ_PLANE + ((st) * 4 + (pl)) * AKV_PLANE))
#define A_SMEM ((2 * AQ_PLANE + 8 * AKV_PLANE) * 2)   // 110592 B
#define A_TILES 768

__global__ __launch_bounds__(256, 2) void attn_kernel(float* __restrict__ out) {
    extern __shared__ __nv_bfloat16 as_[];
    __shared__ int s_t;
    __nv_bfloat16 (*sQh)[72] = (__nv_bfloat16(*)[72])(as_);
    __nv_bfloat16 (*sQm)[72] = (__nv_bfloat16(*)[72])(as_ + AQ_PLANE);

    const int tid = threadIdx.x, lane = tid & 31, warp = tid >> 5;
    const int g = lane >> 2, tg = lane & 3;
    const int l7 = lane & 7, l8 = lane & 8, l16 = (lane & 16) >> 1;
    const int r0 = warp * 16 + g;

    for (;;) {
        __syncthreads();
        if (tid == 0) s_t = atomicAdd(&g_tickA, 1);
        __syncthreads();
        const int t = s_t;
        if (t >= A_TILES) break;
        const int qt = t & 7, h = (t >> 3) % 12, bb = t / 96;

        for (int brn = 0; brn < 3; ++brn) {
            const size_t hb = (((size_t)brn * 8 + bb) * 12 + h) * (size_t)(1024 * 64);
            const __nv_bfloat16* KVp[4] = { g_Kh + hb, g_Km + hb, g_Vh + hb, g_Vm + hb };
            const __nv_bfloat16* Qp[2]  = { g_Qh + hb + (size_t)qt * 128 * 64,
                                            g_Qm + hb + (size_t)qt * 128 * 64 };

            auto loadKV = [&](int jt, int st) {
#pragma unroll
                for (int i = 0; i < 8; ++i) {
                    int idx = i * 256 + tid;
                    int seg = idx & 7, row = (idx >> 3) & 63, pl = idx >> 9;
                    cp16(smaddr(&SKV_(st, pl)[row][seg * 8]),
                         KVp[pl] + (size_t)(jt * 64 + row) * 64 + seg * 8);
                }
            };

#pragma unroll
            for (int i = 0; i < 8; ++i) {
                int idx = i * 256 + tid;
                int seg = idx & 7, row = (idx >> 3) & 127, pl = idx >> 10;
                cp16(smaddr(&(pl ? sQm : sQh)[row][seg * 8]),
                     Qp[pl] + (size_t)row * 64 + seg * 8);
            }
            loadKV(0, 0);
            cp_commit();

            float m0 = -1e30f, m1 = -1e30f, l0 = 0.f, l1 = 0.f;
            float oa[8][4];
#pragma unroll
            for (int i = 0; i < 8; ++i)
#pragma unroll
                for (int j = 0; j < 4; ++j) oa[i][j] = 0.f;

            for (int jt = 0; jt < 16; ++jt) {
                const int st = jt & 1;
                if (jt < 15) { loadKV(jt + 1, st ^ 1); cp_commit(); cp_wait1(); }
                else cp_wait0();
                __syncthreads();

                __nv_bfloat16 (*sKh)[72] = SKV_(st, 0), (*sKm)[72] = SKV_(st, 1);
                __nv_bfloat16 (*sVh)[72] = SKV_(st, 2), (*sVm)[72] = SKV_(st, 3);

                float sf[8][4];
#pragma unroll
                for (int i = 0; i < 8; ++i)
#pragma unroll
                    for (int j = 0; j < 4; ++j) sf[i][j] = 0.f;
#pragma unroll
                for (int ks = 0; ks < 4; ++ks) {
                    const int k0 = ks * 16;
                    uint32_t qh[4], qm[4];
                    ldsm4(qh, smaddr(&sQh[warp * 16 + l7 + l8][k0 + l16]));
                    ldsm4(qm, smaddr(&sQm[warp * 16 + l7 + l8][k0 + l16]));
                    uint32_t kh_[4][4], km_[4][4];
#pragma unroll
                    for (int p = 0; p < 4; ++p) {
                        int n0 = p * 16 + l7 + l16;
                        ldsm4(kh_[p], smaddr(&sKh[n0][k0 + l8]));
                        ldsm4(km_[p], smaddr(&sKm[n0][k0 + l8]));
                    }
#pragma unroll
                    for (int p = 0; p < 4; ++p) {
                        mma16(sf[2 * p],     qh, kh_[p]);
                        mma16(sf[2 * p + 1], qh, kh_[p] + 2);
                    }
#pragma unroll
                    for (int p = 0; p < 4; ++p) {
                        mma16(sf[2 * p],     qh, km_[p]);
                        mma16(sf[2 * p + 1], qh, km_[p] + 2);
                    }
#pragma unroll
                    for (int p = 0; p < 4; ++p) {
                        mma16(sf[2 * p],     qm, kh_[p]);
                        mma16(sf[2 * p + 1], qm, kh_[p] + 2);
                    }
                }

                float t0 = -1e30f, t1 = -1e30f;
#pragma unroll
                for (int nt = 0; nt < 8; ++nt) {
                    t0 = fmaxf(t0, fmaxf(sf[nt][0], sf[nt][1]));
                    t1 = fmaxf(t1, fmaxf(sf[nt][2], sf[nt][3]));
                }
                t0 = fmaxf(t0, __shfl_xor_sync(0xffffffffu, t0, 1));
                t0 = fmaxf(t0, __shfl_xor_sync(0xffffffffu, t0, 2));
                t1 = fmaxf(t1, __shfl_xor_sync(0xffffffffu, t1, 1));
                t1 = fmaxf(t1, __shfl_xor_sync(0xffffffffu, t1, 2));
                float mn0 = fmaxf(m0, t0), mn1 = fmaxf(m1, t1);
                float a0 = __expf(m0 - mn0), a1 = __expf(m1 - mn1);
                m0 = mn0; m1 = mn1;

                float rs0 = 0.f, rs1 = 0.f;
#pragma unroll
                for (int nt = 0; nt < 8; ++nt) {
                    sf[nt][0] = __expf(sf[nt][0] - mn0);
                    sf[nt][1] = __expf(sf[nt][1] - mn0);
                    sf[nt][2] = __expf(sf[nt][2] - mn1);
                    sf[nt][3] = __expf(sf[nt][3] - mn1);
                    rs0 += sf[nt][0] + sf[nt][1];
                    rs1 += sf[nt][2] + sf[nt][3];
                }
                l0 = l0 * a0 + rs0;
                l1 = l1 * a1 + rs1;
#pragma unroll
                for (int nt = 0; nt < 8; ++nt) {
                    oa[nt][0] *= a0; oa[nt][1] *= a0;
                    oa[nt][2] *= a1; oa[nt][3] *= a1;
                }

#pragma unroll
                for (int ks = 0; ks < 4; ++ks) {
                    uint32_t ph[4], pm[4];
                    ph[0] = packh(sf[2 * ks][0],     sf[2 * ks][1]);
                    ph[1] = packh(sf[2 * ks][2],     sf[2 * ks][3]);
                    ph[2] = packh(sf[2 * ks + 1][0], sf[2 * ks + 1][1]);
                    ph[3] = packh(sf[2 * ks + 1][2], sf[2 * ks + 1][3]);
                    pm[0] = packm(sf[2 * ks][0],     sf[2 * ks][1],     ph[0]);
                    pm[1] = packm(sf[2 * ks][2],     sf[2 * ks][3],     ph[1]);
                    pm[2] = packm(sf[2 * ks + 1][0], sf[2 * ks + 1][1], ph[2]);
                    pm[3] = packm(sf[2 * ks + 1][2], sf[2 * ks + 1][3], ph[3]);
                    const int kv0 = ks * 16 + l7 + l8;
                    uint32_t vh_[4][4], vm_[4][4];
#pragma unroll
                    for (int p = 0; p < 4; ++p) {
                        int d0 = p * 16 + l16;
                        ldsm4t(vh_[p], smaddr(&sVh[kv0][d0]));
                        ldsm4t(vm_[p], smaddr(&sVm[kv0][d0]));
                    }
#pragma unroll
                    for (int p = 0; p < 4; ++p) {
                        mma16(oa[2 * p],     ph, vh_[p]);
                        mma16(oa[2 * p + 1], ph, vh_[p] + 2);
                    }
#pragma unroll
                    for (int p = 0; p < 4; ++p) {
                        mma16(oa[2 * p],     ph, vm_[p]);
                        mma16(oa[2 * p + 1], ph, vm_[p] + 2);
                    }
#pragma unroll
                    for (int p = 0; p < 4; ++p) {
                        mma16(oa[2 * p],     pm, vh_[p]);
                        mma16(oa[2 * p + 1], pm, vh_[p] + 2);
                    }
                }
                __syncthreads();
            }

            float L0 = l0 + __shfl_xor_sync(0xffffffffu, l0, 1);
            L0 += __shfl_xor_sync(0xffffffffu, L0, 2);
            float L1 = l1 + __shfl_xor_sync(0xffffffffu, l1, 1);
            L1 += __shfl_xor_sync(0xffffffffu, L1, 2);
            float i0 = 1.f / L0, i1 = 1.f / L1;
#pragma unroll
            for (int nt = 0; nt < 8; ++nt) {
                int d = nt * 8 + tg * 2;
                size_t base = ((size_t)bb * 1024 + (size_t)(qt * 128 + r0)) * 768 + h * 64 + d;
                float2 v0 = make_float2(oa[nt][0] * i0, oa[nt][1] * i0);
                float2 v1 = make_float2(oa[nt][2] * i1, oa[nt][3] * i1);
                if (brn) {
                    float2 o0 = *(float2*)&out[base];
                    float2 o1 = *(float2*)&out[base + (size_t)8 * 768];
                    v0.x += o0.x; v0.y += o0.y; v1.x += o1.x; v1.y += o1.y;
                }
                *(float2*)&out[base]                   = v0;
                *(float2*)&out[base + (size_t)8 * 768] = v1;
            }
        }
    }
}

// ------------------------------------------------------------------
extern "C" void kernel_launch(void* const* d_in, const int* in_sizes, int n_in,
                              void* d_out, int out_size) {
    (void)in_sizes; (void)n_in; (void)out_size;
    const float* x  = (const float*)d_in[0];
    const float* wq = (const float*)d_in[1];
    const float* bq = (const float*)d_in[2];
    const float* wk = (const float*)d_in[3];
    const float* bk = (const float*)d_in[4];
    const float* wv = (const float*)d_in[5];
    const float* bv = (const float*)d_in[6];
    float* out = (float*)d_out;

    prep_x_fused<<<8192, 256>>>(x);
    prep_w<<<dim3(768, 9), 192>>>(wq, wk, wv);

    cudaFuncSetAttribute(proj_mma, cudaFuncAttributeMaxDynamicSharedMemorySize, P_SMEM);
    proj_mma<<<296, 256, P_SMEM>>>(bq, bk, bv);

    cudaFuncSetAttribute(attn_kernel, cudaFuncAttributeMaxDynamicSharedMemorySize, A_SMEM);
    attn_kernel<<<296, 256, A_SMEM>>>(out);
}

// round 9
// speedup vs baseline: 2.0572x; 1.1788x over previous
#include <cuda_runtime.h>
#include <cuda_bf16.h>
#include <cuda_fp16.h>
#include <cstdint>
#include <cstddef>

#define DEVI __device__ __forceinline__

// ------------------------------------------------------------------
// Scratch (__device__ globals; allocation-free rule)
// ------------------------------------------------------------------
__device__ int g_tickP, g_tickA;
__device__ __nv_bfloat16 g_xh[3ull * 8192 * 768];
__device__ __nv_bfloat16 g_xm[3ull * 8192 * 768];
__device__ __nv_bfloat16 g_Wh[9ull * 768 * 768];
__device__ __nv_bfloat16 g_Wm[9ull * 768 * 768];
// attention inputs: fp16. Q,K as hi+lo split; V single plane.
__device__ __half g_Qh[3ull * 8 * 12 * 1024 * 64];
__device__ __half g_Ql[3ull * 8 * 12 * 1024 * 64];
__device__ __half g_Kh[3ull * 8 * 12 * 1024 * 64];
__device__ __half g_Kl[3ull * 8 * 12 * 1024 * 64];
__device__ __half g_V [3ull * 8 * 12 * 1024 * 64];

// ------------------------------------------------------------------
// Helpers
// ------------------------------------------------------------------
DEVI uint32_t smaddr(const void* p) { return (uint32_t)__cvta_generic_to_shared(p); }

DEVI uint32_t packh(float a, float b) {
    __nv_bfloat16 ha = __float2bfloat16(a), hb = __float2bfloat16(b);
    uint16_t ua, ub;
    memcpy(&ua, &ha, 2); memcpy(&ub, &hb, 2);
    return ((uint32_t)ub << 16) | ua;
}
DEVI uint32_t packm(float a, float b, uint32_t h) {
    uint16_t ua = (uint16_t)(h & 0xffffu), ub = (uint16_t)(h >> 16);
    __nv_bfloat16 ha, hb;
    memcpy(&ha, &ua, 2); memcpy(&hb, &ub, 2);
    return packh(a - __bfloat162float(ha), b - __bfloat162float(hb));
}
DEVI uint32_t packf16(float a, float b) {
    __half2 h = __floats2half2_rn(a, b);
    uint32_t u; memcpy(&u, &h, 4); return u;
}
DEVI uint32_t packf16l(float a, float b, uint32_t hbits) {
    __half2 h; memcpy(&h, &hbits, 4);
    float2 f = __half22float2(h);
    return packf16(a - f.x, b - f.y);
}

DEVI void cp16(uint32_t dst, const void* src) {
    asm volatile("cp.async.cg.shared.global [%0], [%1], 16;" :: "r"(dst), "l"(src) : "memory");
}
DEVI void cp_commit() { asm volatile("cp.async.commit_group;" ::: "memory"); }
DEVI void cp_wait0()  { asm volatile("cp.async.wait_group 0;" ::: "memory"); }
DEVI void cp_wait1()  { asm volatile("cp.async.wait_group 1;" ::: "memory"); }

DEVI void ldsm4(uint32_t r[4], uint32_t a) {
    asm volatile("ldmatrix.sync.aligned.m8n8.x4.shared.b16 {%0,%1,%2,%3}, [%4];"
                 : "=r"(r[0]), "=r"(r[1]), "=r"(r[2]), "=r"(r[3]) : "r"(a));
}
DEVI void ldsm4t(uint32_t r[4], uint32_t a) {
    asm volatile("ldmatrix.sync.aligned.m8n8.x4.trans.shared.b16 {%0,%1,%2,%3}, [%4];"
                 : "=r"(r[0]), "=r"(r[1]), "=r"(r[2]), "=r"(r[3]) : "r"(a));
}
DEVI void mma16(float d[4], const uint32_t a[4], const uint32_t b[2]) {
    asm volatile(
        "mma.sync.aligned.m16n8k16.row.col.f32.bf16.bf16.f32 "
        "{%0,%1,%2,%3}, {%4,%5,%6,%7}, {%8,%9}, {%0,%1,%2,%3};"
        : "+f"(d[0]), "+f"(d[1]), "+f"(d[2]), "+f"(d[3])
        : "r"(a[0]), "r"(a[1]), "r"(a[2]), "r"(a[3]), "r"(b[0]), "r"(b[1]));
}
DEVI void mma16h(float d[4], const uint32_t a[4], const uint32_t b[2]) {
    asm volatile(
        "mma.sync.aligned.m16n8k16.row.col.f32.f16.f16.f32 "
        "{%0,%1,%2,%3}, {%4,%5,%6,%7}, {%8,%9}, {%0,%1,%2,%3};"
        : "+f"(d[0]), "+f"(d[1]), "+f"(d[2]), "+f"(d[3])
        : "r"(a[0]), "r"(a[1]), "r"(a[2]), "r"(a[3]), "r"(b[0]), "r"(b[1]));
}

// ------------------------------------------------------------------
// Kernel 1: fused row scalars + branch-scaled bf16 hi/mid split of x.
// Also resets the persistent-tile tickets (block 0).
// ------------------------------------------------------------------
__global__ __launch_bounds__(256) void prep_x_fused(const float* __restrict__ x) {
    __shared__ float red[8];
    __shared__ float sbr[2];
    const int row = blockIdx.x, tid = threadIdx.x;
    if (row == 0 && tid == 0) { g_tickP = 0; g_tickA = 0; }

    float4 v = make_float4(0.f, 0.f, 0.f, 0.f);
    if (tid < 192) v = *(const float4*)&x[(size_t)row * 768 + tid * 4];
    float ss = fmaf(v.x, v.x, fmaf(v.y, v.y, fmaf(v.z, v.z, v.w * v.w)));
#pragma unroll
    for (int o = 16; o; o >>= 1) ss += __shfl_xor_sync(0xffffffffu, ss, o);
    if ((tid & 31) == 0) red[tid >> 5] = ss;
    __syncthreads();
    if (tid == 0) {
        float t = 0.f;
#pragma unroll
        for (int i = 0; i < 8; ++i) t += red[i];
        float n = fmaxf(sqrtf(t), 1e-5f);
        const float sc = 0.316227766016837933f;     // sqrt(0.1)
        float a = sc * n;
        float th = tanhf(a);
        float s_pre = th / a;
        float norm_h = th / sc;
        float maxn = (1.0f - 4e-3f) / sc;
        sbr[0] = (norm_h > maxn) ? s_pre * (maxn / norm_h) : s_pre;
        float arg = fminf(a, 1.0f - 1e-5f);
        float art = 0.5f * logf((1.0f + arg) / (1.0f - arg));
        sbr[1] = art / (n * sc);
    }
    __syncthreads();
    if (tid < 192) {
        const int c = tid * 4;
#pragma unroll
        for (int br = 0; br < 3; ++br) {
            float s = (br == 0) ? 1.0f : sbr[br - 1];
            float4 w = make_float4(v.x * s, v.y * s, v.z * s, v.w * s);
            size_t o = ((size_t)br * 8192 + row) * 768 + c;
            uint32_t h0 = packh(w.x, w.y), h1 = packh(w.z, w.w);
            *(uint32_t*)&g_xh[o]     = h0;
            *(uint32_t*)&g_xh[o + 2] = h1;
            *(uint32_t*)&g_xm[o]     = packm(w.x, w.y, h0);
            *(uint32_t*)&g_xm[o + 2] = packm(w.z, w.w, h1);
        }
    }
}

// ------------------------------------------------------------------
// Kernel 1c: pre-split weights into bf16 planes
// ------------------------------------------------------------------
__global__ __launch_bounds__(192) void prep_w(
    const float* __restrict__ wq, const float* __restrict__ wk, const float* __restrict__ wv) {
    const int row = blockIdx.x, mat = blockIdx.y;
    const int typ = mat / 3, br = mat % 3;
    const float* W = (typ == 0 ? wq : typ == 1 ? wk : wv) + (size_t)br * 768 * 768;
    const int c = threadIdx.x * 4;
    float4 v = *(const float4*)&W[(size_t)row * 768 + c];
    size_t o = ((size_t)mat * 768 + row) * 768 + c;
    uint32_t h0 = packh(v.x, v.y), h1 = packh(v.z, v.w);
    *(uint32_t*)&g_Wh[o]     = h0;
    *(uint32_t*)&g_Wh[o + 2] = h1;
    *(uint32_t*)&g_Wm[o]     = packm(v.x, v.y, h0);
    *(uint32_t*)&g_Wm[o + 2] = packm(v.z, v.w, h1);
}

// ------------------------------------------------------------------
// Kernel 2: persistent projection GEMM, bf16 3-pass, cp.async 2-stage.
// Epilogue emits fp16 planes: Q,K hi+lo split; V single.
// ------------------------------------------------------------------
#define P_PLANE 5120                 // 128*40 bf16 elems per plane
#define SA_(st, pl) ((__nv_bfloat16(*)[40])(ps + ((st) * 2 + (pl)) * P_PLANE))
#define SB_(st, pl) ((__nv_bfloat16(*)[40])(ps + (4 + (st) * 2 + (pl)) * P_PLANE))
#define P_SMEM (8 * P_PLANE * 2)     // 81920 B
#define P_TILES 3456

__global__ __launch_bounds__(256, 2) void proj_mma(
    const float* __restrict__ bq, const float* __restrict__ bk, const float* __restrict__ bv)
{
    extern __shared__ __nv_bfloat16 ps[];
    __shared__ int s_t;
    const int tid = threadIdx.x, lane = tid & 31, warp = tid >> 5;
    const int wr = warp >> 1, wc = warp & 1;
    const int l7 = lane & 7, l8 = lane & 8, l16 = (lane & 16) >> 1;

    for (;;) {
        __syncthreads();
        if (tid == 0) s_t = atomicAdd(&g_tickP, 1);
        __syncthreads();
        const int t = s_t;
        if (t >= P_TILES) break;
        const int rt = t & 63, rem = t >> 6;
        const int ct = rem % 6, mat = rem / 6;
        const int br = mat % 3, typ = mat / 3;

        const __nv_bfloat16* Ap[2] = {
            g_xh + ((size_t)br * 8192 + rt * 128) * 768,
            g_xm + ((size_t)br * 8192 + rt * 128) * 768 };
        const __nv_bfloat16* Bp[2] = {
            g_Wh + ((size_t)mat * 768 + ct * 128) * 768,
            g_Wm + ((size_t)mat * 768 + ct * 128) * 768 };

        float acc[2][8][4];
#pragma unroll
        for (int i = 0; i < 2; ++i)
#pragma unroll
            for (int j = 0; j < 8; ++j)
#pragma unroll
                for (int k = 0; k < 4; ++k) acc[i][j][k] = 0.f;

        auto load_chunk = [&](int kt, int st) {
#pragma unroll
            for (int i = 0; i < 4; ++i) {
                int idx = i * 256 + tid;
                int seg = idx & 3, row = (idx >> 2) & 127, pl = idx >> 9;
                cp16(smaddr(&SA_(st, pl)[row][seg * 8]),
                     Ap[pl] + (size_t)row * 768 + kt * 32 + seg * 8);
            }
#pragma unroll
            for (int i = 0; i < 4; ++i) {
                int idx = i * 256 + tid;
                int seg = idx & 3, row = (idx >> 2) & 127, pl = idx >> 9;
                cp16(smaddr(&SB_(st, pl)[row][seg * 8]),
                     Bp[pl] + (size_t)row * 768 + kt * 32 + seg * 8);
            }
        };

        load_chunk(0, 0);
        cp_commit();

        for (int kt = 0; kt < 24; ++kt) {
            const int st = kt & 1;
            if (kt < 23) { load_chunk(kt + 1, st ^ 1); cp_commit(); cp_wait1(); }
            else cp_wait0();
            __syncthreads();

            __nv_bfloat16 (*sAh)[40] = SA_(st, 0), (*sAm)[40] = SA_(st, 1);
            __nv_bfloat16 (*sBh)[40] = SB_(st, 0), (*sBm)[40] = SB_(st, 1);
#pragma unroll
            for (int ks = 0; ks < 2; ++ks) {
                const int k0 = ks * 16;
                uint32_t ah[2][4], am_[2][4];
#pragma unroll
                for (int mt = 0; mt < 2; ++mt) {
                    int r0 = wr * 32 + mt * 16 + l7 + l8;
                    ldsm4(ah[mt],  smaddr(&sAh[r0][k0 + l16]));
                    ldsm4(am_[mt], smaddr(&sAm[r0][k0 + l16]));
                }
                uint32_t bh[4][4], bm_[4][4];
#pragma unroll
                for (int p = 0; p < 4; ++p) {
                    int n0 = wc * 64 + p * 16 + l7 + l16;
                    ldsm4(bh[p],  smaddr(&sBh[n0][k0 + l8]));
                    ldsm4(bm_[p], smaddr(&sBm[n0][k0 + l8]));
                }
#pragma unroll
                for (int p = 0; p < 4; ++p)
#pragma unroll
                    for (int mt = 0; mt < 2; ++mt) {
                        mma16(acc[mt][2 * p],     ah[mt], bh[p]);
                        mma16(acc[mt][2 * p + 1], ah[mt], bh[p] + 2);
                    }
#pragma unroll
                for (int p = 0; p < 4; ++p)
#pragma unroll
                    for (int mt = 0; mt < 2; ++mt) {
                        mma16(acc[mt][2 * p],     ah[mt], bm_[p]);
                        mma16(acc[mt][2 * p + 1], ah[mt], bm_[p] + 2);
                    }
#pragma unroll
                for (int p = 0; p < 4; ++p)
#pragma unroll
                    for (int mt = 0; mt < 2; ++mt) {
                        mma16(acc[mt][2 * p],     am_[mt], bh[p]);
                        mma16(acc[mt][2 * p + 1], am_[mt], bh[p] + 2);
                    }
            }
            __syncthreads();
        }

        // epilogue: bias, emit fp16 planes [br][b][h][n][64]
        const float* Bb = (typ == 0 ? bq : typ == 1 ? bk : bv) + br * 768;
        __half* dh = (typ == 0 ? g_Qh : typ == 1 ? g_Kh : g_V);
        __half* dl = (typ == 0 ? g_Ql : g_Kl);          // unused when typ==2
        const int h  = ct * 2 + wc;
        const int bb = (rt * 128) >> 10;
        const int nb = (rt * 128) & 1023;
        const int tg = lane & 3, g = lane >> 2;
#pragma unroll
        for (int mt = 0; mt < 2; ++mt) {
            int r = wr * 32 + mt * 16 + g;
#pragma unroll
            for (int nt = 0; nt < 8; ++nt) {
                int d = nt * 8 + tg * 2;
                float2 bi = *(const float2*)&Bb[h * 64 + d];
                float v0 = acc[mt][nt][0] + bi.x, v1 = acc[mt][nt][1] + bi.y;
                float v2 = acc[mt][nt][2] + bi.x, v3 = acc[mt][nt][3] + bi.y;
                size_t base = ((((size_t)br * 8 + bb) * 12 + h) * 1024 + (nb + r)) * 64 + d;
                uint32_t h0 = packf16(v0, v1), h1 = packf16(v2, v3);
                *(uint32_t*)&dh[base]          = h0;
                *(uint32_t*)&dh[base + 8 * 64] = h1;
                if (typ < 2) {
                    *(uint32_t*)&dl[base]          = packf16l(v0, v1, h0);
                    *(uint32_t*)&dl[base + 8 * 64] = packf16l(v2, v3, h1);
                }
            }
        }
    }
}

// ------------------------------------------------------------------
// Kernel 3: persistent flash attention, fp16.
// QK: fp16 hi/lo 3-pass. PV: single fp16 pass. 64-row KV tiles.
// ------------------------------------------------------------------
#define AQ_PLANE 9216                // 128*72 halfs
#define AKV_PLANE 4608               // 64*72 halfs
#define SKV_(st, pl) ((__half(*)[72])(as_ + 2 * AQ_PLANE + ((st) * 3 + (pl)) * AKV_PLANE))
#define A_SMEM ((2 * AQ_PLANE + 6 * AKV_PLANE) * 2)   // 92160 B
#define A_TILES 768

__global__ __launch_bounds__(256, 2) void attn_kernel(float* __restrict__ out) {
    extern __shared__ __half as_[];
    __shared__ int s_t;
    __half (*sQh)[72] = (__half(*)[72])(as_);
    __half (*sQl)[72] = (__half(*)[72])(as_ + AQ_PLANE);

    const int tid = threadIdx.x, lane = tid & 31, warp = tid >> 5;
    const int g = lane >> 2, tg = lane & 3;
    const int l7 = lane & 7, l8 = lane & 8, l16 = (lane & 16) >> 1;
    const int r0 = warp * 16 + g;

    for (;;) {
        __syncthreads();
        if (tid == 0) s_t = atomicAdd(&g_tickA, 1);
        __syncthreads();
        const int t = s_t;
        if (t >= A_TILES) break;
        const int qt = t & 7, h = (t >> 3) % 12, bb = t / 96;

        for (int brn = 0; brn < 3; ++brn) {
            const size_t hb = (((size_t)brn * 8 + bb) * 12 + h) * (size_t)(1024 * 64);
            const __half* KVp[3] = { g_Kh + hb, g_Kl + hb, g_V + hb };
            const __half* Qp[2]  = { g_Qh + hb + (size_t)qt * 128 * 64,
                                     g_Ql + hb + (size_t)qt * 128 * 64 };

            auto loadKV = [&](int jt, int st) {
#pragma unroll
                for (int i = 0; i < 6; ++i) {
                    int idx = i * 256 + tid;
                    int seg = idx & 7, row = (idx >> 3) & 63, pl = idx >> 9;
                    cp16(smaddr(&SKV_(st, pl)[row][seg * 8]),
                         KVp[pl] + (size_t)(jt * 64 + row) * 64 + seg * 8);
                }
            };

#pragma unroll
            for (int i = 0; i < 8; ++i) {
                int idx = i * 256 + tid;
                int seg = idx & 7, row = (idx >> 3) & 127, pl = idx >> 10;
                cp16(smaddr(&(pl ? sQl : sQh)[row][seg * 8]),
                     Qp[pl] + (size_t)row * 64 + seg * 8);
            }
            loadKV(0, 0);
            cp_commit();

            float m0 = -1e30f, m1 = -1e30f, l0 = 0.f, l1 = 0.f;
            float oa[8][4];
#pragma unroll
            for (int i = 0; i < 8; ++i)
#pragma unroll
                for (int j = 0; j < 4; ++j) oa[i][j] = 0.f;

            for (int jt = 0; jt < 16; ++jt) {
                const int st = jt & 1;
                if (jt < 15) { loadKV(jt + 1, st ^ 1); cp_commit(); cp_wait1(); }
                else cp_wait0();
                __syncthreads();

                __half (*sKh)[72] = SKV_(st, 0), (*sKl)[72] = SKV_(st, 1);
                __half (*sV)[72]  = SKV_(st, 2);

                // ---- S = Q K^T : fp16 hi/lo, 3 passes ----
                float sf[8][4];
#pragma unroll
                for (int i = 0; i < 8; ++i)
#pragma unroll
                    for (int j = 0; j < 4; ++j) sf[i][j] = 0.f;
#pragma unroll
                for (int ks = 0; ks < 4; ++ks) {
                    const int k0 = ks * 16;
                    uint32_t qh[4], ql[4];
                    ldsm4(qh, smaddr(&sQh[warp * 16 + l7 + l8][k0 + l16]));
                    ldsm4(ql, smaddr(&sQl[warp * 16 + l7 + l8][k0 + l16]));
                    uint32_t kh_[4][4], kl_[4][4];
#pragma unroll
                    for (int p = 0; p < 4; ++p) {
                        int n0 = p * 16 + l7 + l16;
                        ldsm4(kh_[p], smaddr(&sKh[n0][k0 + l8]));
                        ldsm4(kl_[p], smaddr(&sKl[n0][k0 + l8]));
                    }
#pragma unroll
                    for (int p = 0; p < 4; ++p) {
                        mma16h(sf[2 * p],     qh, kh_[p]);
                        mma16h(sf[2 * p + 1], qh, kh_[p] + 2);
                    }
#pragma unroll
                    for (int p = 0; p < 4; ++p) {
                        mma16h(sf[2 * p],     qh, kl_[p]);
                        mma16h(sf[2 * p + 1], qh, kl_[p] + 2);
                    }
#pragma unroll
                    for (int p = 0; p < 4; ++p) {
                        mma16h(sf[2 * p],     ql, kh_[p]);
                        mma16h(sf[2 * p + 1], ql, kh_[p] + 2);
                    }
                }

                // ---- online softmax ----
                float t0 = -1e30f, t1 = -1e30f;
#pragma unroll
                for (int nt = 0; nt < 8; ++nt) {
                    t0 = fmaxf(t0, fmaxf(sf[nt][0], sf[nt][1]));
                    t1 = fmaxf(t1, fmaxf(sf[nt][2], sf[nt][3]));
                }
                t0 = fmaxf(t0, __shfl_xor_sync(0xffffffffu, t0, 1));
                t0 = fmaxf(t0, __shfl_xor_sync(0xffffffffu, t0, 2));
                t1 = fmaxf(t1, __shfl_xor_sync(0xffffffffu, t1, 1));
                t1 = fmaxf(t1, __shfl_xor_sync(0xffffffffu, t1, 2));
                float mn0 = fmaxf(m0, t0), mn1 = fmaxf(m1, t1);
                float a0 = __expf(m0 - mn0), a1 = __expf(m1 - mn1);
                m0 = mn0; m1 = mn1;

                float rs0 = 0.f, rs1 = 0.f;
#pragma unroll
                for (int nt = 0; nt < 8; ++nt) {
                    sf[nt][0] = __expf(sf[nt][0] - mn0);
                    sf[nt][1] = __expf(sf[nt][1] - mn0);
                    sf[nt][2] = __expf(sf[nt][2] - mn1);
                    sf[nt][3] = __expf(sf[nt][3] - mn1);
                    rs0 += sf[nt][0] + sf[nt][1];
                    rs1 += sf[nt][2] + sf[nt][3];
                }
                l0 = l0 * a0 + rs0;
                l1 = l1 * a1 + rs1;
#pragma unroll
                for (int nt = 0; nt < 8; ++nt) {
                    oa[nt][0] *= a0; oa[nt][1] *= a0;
                    oa[nt][2] *= a1; oa[nt][3] *= a1;
                }

                // ---- O += P V : fp16 single pass ----
#pragma unroll
                for (int ks = 0; ks < 4; ++ks) {
                    uint32_t ph[4];
                    ph[0] = packf16(sf[2 * ks][0],     sf[2 * ks][1]);
                    ph[1] = packf16(sf[2 * ks][2],     sf[2 * ks][3]);
                    ph[2] = packf16(sf[2 * ks + 1][0], sf[2 * ks + 1][1]);
                    ph[3] = packf16(sf[2 * ks + 1][2], sf[2 * ks + 1][3]);
                    const int kv0 = ks * 16 + l7 + l8;
                    uint32_t vh_[4][4];
#pragma unroll
                    for (int p = 0; p < 4; ++p) {
                        int d0 = p * 16 + l16;
                        ldsm4t(vh_[p], smaddr(&sV[kv0][d0]));
                    }
#pragma unroll
                    for (int p = 0; p < 4; ++p) {
                        mma16h(oa[2 * p],     ph, vh_[p]);
                        mma16h(oa[2 * p + 1], ph, vh_[p] + 2);
                    }
                }
                __syncthreads();
            }

            // fold branch into out (RMW; CTA owns its tile across branches)
            float L0 = l0 + __shfl_xor_sync(0xffffffffu, l0, 1);
            L0 += __shfl_xor_sync(0xffffffffu, L0, 2);
            float L1 = l1 + __shfl_xor_sync(0xffffffffu, l1, 1);
            L1 += __shfl_xor_sync(0xffffffffu, L1, 2);
            float i0 = 1.f / L0, i1 = 1.f / L1;
#pragma unroll
            for (int nt = 0; nt < 8; ++nt) {
                int d = nt * 8 + tg * 2;
                size_t base = ((size_t)bb * 1024 + (size_t)(qt * 128 + r0)) * 768 + h * 64 + d;
                float2 v0 = make_float2(oa[nt][0] * i0, oa[nt][1] * i0);
                float2 v1 = make_float2(oa[nt][2] * i1, oa[nt][3] * i1);
                if (brn) {
                    float2 o0 = *(float2*)&out[base];
                    float2 o1 = *(float2*)&out[base + (size_t)8 * 768];
                    v0.x += o0.x; v0.y += o0.y; v1.x += o1.x; v1.y += o1.y;
                }
                *(float2*)&out[base]                   = v0;
                *(float2*)&out[base + (size_t)8 * 768] = v1;
            }
        }
    }
}

// ------------------------------------------------------------------
extern "C" void kernel_launch(void* const* d_in, const int* in_sizes, int n_in,
                              void* d_out, int out_size) {
    (void)in_sizes; (void)n_in; (void)out_size;
    const float* x  = (const float*)d_in[0];
    const float* wq = (const float*)d_in[1];
    const float* bq = (const float*)d_in[2];
    const float* wk = (const float*)d_in[3];
    const float* bk = (const float*)d_in[4];
    const float* wv = (const float*)d_in[5];
    const float* bv = (const float*)d_in[6];
    float* out = (float*)d_out;

    prep_x_fused<<<8192, 256>>>(x);
    prep_w<<<dim3(768, 9), 192>>>(wq, wk, wv);

    cudaFuncSetAttribute(proj_mma, cudaFuncAttributeMaxDynamicSharedMemorySize, P_SMEM);
    proj_mma<<<296, 256, P_SMEM>>>(bq, bk, bv);

    cudaFuncSetAttribute(attn_kernel, cudaFuncAttributeMaxDynamicSharedMemorySize, A_SMEM);
    attn_kernel<<<296, 256, A_SMEM>>>(out);
}

// round 10
// speedup vs baseline: 2.2722x; 1.1045x over previous
#include <cuda_runtime.h>
#include <cuda_bf16.h>
#include <cuda_fp16.h>
#include <cstdint>
#include <cstddef>

#define DEVI __device__ __forceinline__
#define LOG2E 1.4426950408889634f

// ------------------------------------------------------------------
// Scratch (__device__ globals; allocation-free rule)
// ------------------------------------------------------------------
__device__ int g_tickP, g_tickA;
__device__ __nv_bfloat16 g_xh[3ull * 8192 * 768];
__device__ __nv_bfloat16 g_xm[3ull * 8192 * 768];
__device__ __half        g_x16[3ull * 8192 * 768];      // fp16 x (V path)
__device__ __nv_bfloat16 g_Wh[9ull * 768 * 768];        // mats 6-8 hold fp16 bits
__device__ __nv_bfloat16 g_Wm[9ull * 768 * 768];
// attention inputs: fp16. Q,K as hi+lo split; V single plane.
__device__ __half g_Qh[3ull * 8 * 12 * 1024 * 64];      // Q pre-scaled by log2(e)
__device__ __half g_Ql[3ull * 8 * 12 * 1024 * 64];
__device__ __half g_Kh[3ull * 8 * 12 * 1024 * 64];
__device__ __half g_Kl[3ull * 8 * 12 * 1024 * 64];
__device__ __half g_V [3ull * 8 * 12 * 1024 * 64];

// ------------------------------------------------------------------
// Helpers
// ------------------------------------------------------------------
DEVI uint32_t smaddr(const void* p) { return (uint32_t)__cvta_generic_to_shared(p); }

DEVI uint32_t packh(float a, float b) {
    __nv_bfloat16 ha = __float2bfloat16(a), hb = __float2bfloat16(b);
    uint16_t ua, ub;
    memcpy(&ua, &ha, 2); memcpy(&ub, &hb, 2);
    return ((uint32_t)ub << 16) | ua;
}
DEVI uint32_t packm(float a, float b, uint32_t h) {
    uint16_t ua = (uint16_t)(h & 0xffffu), ub = (uint16_t)(h >> 16);
    __nv_bfloat16 ha, hb;
    memcpy(&ha, &ua, 2); memcpy(&hb, &ub, 2);
    return packh(a - __bfloat162float(ha), b - __bfloat162float(hb));
}
DEVI uint32_t packf16(float a, float b) {
    __half2 h = __floats2half2_rn(a, b);
    uint32_t u; memcpy(&u, &h, 4); return u;
}
DEVI uint32_t packf16l(float a, float b, uint32_t hbits) {
    __half2 h; memcpy(&h, &hbits, 4);
    float2 f = __half22float2(h);
    return packf16(a - f.x, b - f.y);
}
DEVI float ex2(float x) { float r; asm("ex2.approx.f32 %0, %1;" : "=f"(r) : "f"(x)); return r; }

DEVI void cp16(uint32_t dst, const void* src) {
    asm volatile("cp.async.cg.shared.global [%0], [%1], 16;" :: "r"(dst), "l"(src) : "memory");
}
DEVI void cp_commit() { asm volatile("cp.async.commit_group;" ::: "memory"); }
DEVI void cp_wait0()  { asm volatile("cp.async.wait_group 0;" ::: "memory"); }
DEVI void cp_wait1()  { asm volatile("cp.async.wait_group 1;" ::: "memory"); }

DEVI void ldsm4(uint32_t r[4], uint32_t a) {
    asm volatile("ldmatrix.sync.aligned.m8n8.x4.shared.b16 {%0,%1,%2,%3}, [%4];"
                 : "=r"(r[0]), "=r"(r[1]), "=r"(r[2]), "=r"(r[3]) : "r"(a));
}
DEVI void ldsm4t(uint32_t r[4], uint32_t a) {
    asm volatile("ldmatrix.sync.aligned.m8n8.x4.trans.shared.b16 {%0,%1,%2,%3}, [%4];"
                 : "=r"(r[0]), "=r"(r[1]), "=r"(r[2]), "=r"(r[3]) : "r"(a));
}
DEVI void mma16(float d[4], const uint32_t a[4], const uint32_t b[2]) {
    asm volatile(
        "mma.sync.aligned.m16n8k16.row.col.f32.bf16.bf16.f32 "
        "{%0,%1,%2,%3}, {%4,%5,%6,%7}, {%8,%9}, {%0,%1,%2,%3};"
        : "+f"(d[0]), "+f"(d[1]), "+f"(d[2]), "+f"(d[3])
        : "r"(a[0]), "r"(a[1]), "r"(a[2]), "r"(a[3]), "r"(b[0]), "r"(b[1]));
}
DEVI void mma16h(float d[4], const uint32_t a[4], const uint32_t b[2]) {
    asm volatile(
        "mma.sync.aligned.m16n8k16.row.col.f32.f16.f16.f32 "
        "{%0,%1,%2,%3}, {%4,%5,%6,%7}, {%8,%9}, {%0,%1,%2,%3};"
        : "+f"(d[0]), "+f"(d[1]), "+f"(d[2]), "+f"(d[3])
        : "r"(a[0]), "r"(a[1]), "r"(a[2]), "r"(a[3]), "r"(b[0]), "r"(b[1]));
}

// ------------------------------------------------------------------
// Kernel 1: fused row scalars + branch-scaled splits of x
// (bf16 hi/mid planes for Q/K GEMMs, fp16 plane for V GEMM).
// Also resets the persistent-tile tickets (block 0).
// ------------------------------------------------------------------
__global__ __launch_bounds__(256) void prep_x_fused(const float* __restrict__ x) {
    __shared__ float red[8];
    __shared__ float sbr[2];
    const int row = blockIdx.x, tid = threadIdx.x;
    if (row == 0 && tid == 0) { g_tickP = 0; g_tickA = 0; }

    float4 v = make_float4(0.f, 0.f, 0.f, 0.f);
    if (tid < 192) v = *(const float4*)&x[(size_t)row * 768 + tid * 4];
    float ss = fmaf(v.x, v.x, fmaf(v.y, v.y, fmaf(v.z, v.z, v.w * v.w)));
#pragma unroll
    for (int o = 16; o; o >>= 1) ss += __shfl_xor_sync(0xffffffffu, ss, o);
    if ((tid & 31) == 0) red[tid >> 5] = ss;
    __syncthreads();
    if (tid == 0) {
        float t = 0.f;
#pragma unroll
        for (int i = 0; i < 8; ++i) t += red[i];
        float n = fmaxf(sqrtf(t), 1e-5f);
        const float sc = 0.316227766016837933f;     // sqrt(0.1)
        float a = sc * n;
        float th = tanhf(a);
        float s_pre = th / a;
        float norm_h = th / sc;
        float maxn = (1.0f - 4e-3f) / sc;
        sbr[0] = (norm_h > maxn) ? s_pre * (maxn / norm_h) : s_pre;
        float arg = fminf(a, 1.0f - 1e-5f);
        float art = 0.5f * logf((1.0f + arg) / (1.0f - arg));
        sbr[1] = art / (n * sc);
    }
    __syncthreads();
    if (tid < 192) {
        const int c = tid * 4;
#pragma unroll
        for (int br = 0; br < 3; ++br) {
            float s = (br == 0) ? 1.0f : sbr[br - 1];
            float4 w = make_float4(v.x * s, v.y * s, v.z * s, v.w * s);
            size_t o = ((size_t)br * 8192 + row) * 768 + c;
            uint32_t h0 = packh(w.x, w.y), h1 = packh(w.z, w.w);
            *(uint32_t*)&g_xh[o]     = h0;
            *(uint32_t*)&g_xh[o + 2] = h1;
            *(uint32_t*)&g_xm[o]     = packm(w.x, w.y, h0);
            *(uint32_t*)&g_xm[o + 2] = packm(w.z, w.w, h1);
            *(uint32_t*)&g_x16[o]     = packf16(w.x, w.y);
            *(uint32_t*)&g_x16[o + 2] = packf16(w.z, w.w);
        }
    }
}

// ------------------------------------------------------------------
// Kernel 1c: pre-split weights. Q/K mats: bf16 hi/mid planes.
// V mats (6-8): fp16 bits stored in g_Wh.
// ------------------------------------------------------------------
__global__ __launch_bounds__(192) void prep_w(
    const float* __restrict__ wq, const float* __restrict__ wk, const float* __restrict__ wv) {
    const int row = blockIdx.x, mat = blockIdx.y;
    const int typ = mat / 3, br = mat % 3;
    const float* W = (typ == 0 ? wq : typ == 1 ? wk : wv) + (size_t)br * 768 * 768;
    const int c = threadIdx.x * 4;
    float4 v = *(const float4*)&W[(size_t)row * 768 + c];
    size_t o = ((size_t)mat * 768 + row) * 768 + c;
    if (typ == 2) {
        *(uint32_t*)&g_Wh[o]     = packf16(v.x, v.y);
        *(uint32_t*)&g_Wh[o + 2] = packf16(v.z, v.w);
    } else {
        uint32_t h0 = packh(v.x, v.y), h1 = packh(v.z, v.w);
        *(uint32_t*)&g_Wh[o]     = h0;
        *(uint32_t*)&g_Wh[o + 2] = h1;
        *(uint32_t*)&g_Wm[o]     = packm(v.x, v.y, h0);
        *(uint32_t*)&g_Wm[o + 2] = packm(v.z, v.w, h1);
    }
}

// ------------------------------------------------------------------
// Kernel 2: persistent projection GEMM, cp.async 2-stage.
// Q/K tiles: bf16 3-pass. V tiles: fp16 single pass (output is fp16).
// ------------------------------------------------------------------
#define P_PLANE 5120                 // 128*40 elems per plane
#define SA_(st, pl) ((__nv_bfloat16(*)[40])(ps + ((st) * 2 + (pl)) * P_PLANE))
#define SB_(st, pl) ((__nv_bfloat16(*)[40])(ps + (4 + (st) * 2 + (pl)) * P_PLANE))
#define P_SMEM (8 * P_PLANE * 2)     // 81920 B
#define P_TILES 3456

__global__ __launch_bounds__(256, 2) void proj_mma(
    const float* __restrict__ bq, const float* __restrict__ bk, const float* __restrict__ bv)
{
    extern __shared__ __nv_bfloat16 ps[];
    __shared__ int s_t;
    const int tid = threadIdx.x, lane = tid & 31, warp = tid >> 5;
    const int wr = warp >> 1, wc = warp & 1;
    const int l7 = lane & 7, l8 = lane & 8, l16 = (lane & 16) >> 1;

    for (;;) {
        __syncthreads();
        if (tid == 0) s_t = atomicAdd(&g_tickP, 1);
        __syncthreads();
        const int t = s_t;
        if (t >= P_TILES) break;
        const int rt = t & 63, rem = t >> 6;
        const int ct = rem % 6, mat = rem / 6;
        const int br = mat % 3, typ = mat / 3;

        const __nv_bfloat16* Ap[2] = {
            (typ == 2) ? (const __nv_bfloat16*)(g_x16 + ((size_t)br * 8192 + rt * 128) * 768)
                       : g_xh + ((size_t)br * 8192 + rt * 128) * 768,
            g_xm + ((size_t)br * 8192 + rt * 128) * 768 };
        const __nv_bfloat16* Bp[2] = {
            g_Wh + ((size_t)mat * 768 + ct * 128) * 768,
            g_Wm + ((size_t)mat * 768 + ct * 128) * 768 };

        float acc[2][8][4];
#pragma unroll
        for (int i = 0; i < 2; ++i)
#pragma unroll
            for (int j = 0; j < 8; ++j)
#pragma unroll
                for (int k = 0; k < 4; ++k) acc[i][j][k] = 0.f;

        auto load_chunk = [&](int kt, int st) {
            const int nit = (typ == 2) ? 2 : 4;      // V: hi planes only
            for (int i = 0; i < nit; ++i) {
                int idx = i * 256 + tid;
                int seg = idx & 3, row = (idx >> 2) & 127, pl = idx >> 9;
                cp16(smaddr(&SA_(st, pl)[row][seg * 8]),
                     Ap[pl] + (size_t)row * 768 + kt * 32 + seg * 8);
            }
            for (int i = 0; i < nit; ++i) {
                int idx = i * 256 + tid;
                int seg = idx & 3, row = (idx >> 2) & 127, pl = idx >> 9;
                cp16(smaddr(&SB_(st, pl)[row][seg * 8]),
                     Bp[pl] + (size_t)row * 768 + kt * 32 + seg * 8);
            }
        };

        load_chunk(0, 0);
        cp_commit();

        for (int kt = 0; kt < 24; ++kt) {
            const int st = kt & 1;
            if (kt < 23) { load_chunk(kt + 1, st ^ 1); cp_commit(); cp_wait1(); }
            else cp_wait0();
            __syncthreads();

            __nv_bfloat16 (*sAh)[40] = SA_(st, 0), (*sAm)[40] = SA_(st, 1);
            __nv_bfloat16 (*sBh)[40] = SB_(st, 0), (*sBm)[40] = SB_(st, 1);
            if (typ == 2) {
                // fp16 single pass
#pragma unroll
                for (int ks = 0; ks < 2; ++ks) {
                    const int k0 = ks * 16;
                    uint32_t ah[2][4];
#pragma unroll
                    for (int mt = 0; mt < 2; ++mt)
                        ldsm4(ah[mt], smaddr(&sAh[wr * 32 + mt * 16 + l7 + l8][k0 + l16]));
                    uint32_t bh[4][4];
#pragma unroll
                    for (int p = 0; p < 4; ++p)
                        ldsm4(bh[p], smaddr(&sBh[wc * 64 + p * 16 + l7 + l16][k0 + l8]));
#pragma unroll
                    for (int p = 0; p < 4; ++p)
#pragma unroll
                        for (int mt = 0; mt < 2; ++mt) {
                            mma16h(acc[mt][2 * p],     ah[mt], bh[p]);
                            mma16h(acc[mt][2 * p + 1], ah[mt], bh[p] + 2);
                        }
                }
            } else {
#pragma unroll
                for (int ks = 0; ks < 2; ++ks) {
                    const int k0 = ks * 16;
                    uint32_t ah[2][4], am_[2][4];
#pragma unroll
                    for (int mt = 0; mt < 2; ++mt) {
                        int r0 = wr * 32 + mt * 16 + l7 + l8;
                        ldsm4(ah[mt],  smaddr(&sAh[r0][k0 + l16]));
                        ldsm4(am_[mt], smaddr(&sAm[r0][k0 + l16]));
                    }
                    uint32_t bh[4][4], bm_[4][4];
#pragma unroll
                    for (int p = 0; p < 4; ++p) {
                        int n0 = wc * 64 + p * 16 + l7 + l16;
                        ldsm4(bh[p],  smaddr(&sBh[n0][k0 + l8]));
                        ldsm4(bm_[p], smaddr(&sBm[n0][k0 + l8]));
                    }
#pragma unroll
                    for (int p = 0; p < 4; ++p)
#pragma unroll
                        for (int mt = 0; mt < 2; ++mt) {
                            mma16(acc[mt][2 * p],     ah[mt], bh[p]);
                            mma16(acc[mt][2 * p + 1], ah[mt], bh[p] + 2);
                        }
#pragma unroll
                    for (int p = 0; p < 4; ++p)
#pragma unroll
                        for (int mt = 0; mt < 2; ++mt) {
                            mma16(acc[mt][2 * p],     ah[mt], bm_[p]);
                            mma16(acc[mt][2 * p + 1], ah[mt], bm_[p] + 2);
                        }
#pragma unroll
                    for (int p = 0; p < 4; ++p)
#pragma unroll
                        for (int mt = 0; mt < 2; ++mt) {
                            mma16(acc[mt][2 * p],     am_[mt], bh[p]);
                            mma16(acc[mt][2 * p + 1], am_[mt], bh[p] + 2);
                        }
                }
            }
            __syncthreads();
        }

        // epilogue: bias, emit fp16 planes [br][b][h][n][64].
        // Q additionally pre-scaled by log2(e) for the ex2 softmax.
        const float* Bb = (typ == 0 ? bq : typ == 1 ? bk : bv) + br * 768;
        __half* dh = (typ == 0 ? g_Qh : typ == 1 ? g_Kh : g_V);
        __half* dl = (typ == 0 ? g_Ql : g_Kl);
        const float qs = (typ == 0) ? LOG2E : 1.0f;
        const int h  = ct * 2 + wc;
        const int bb = (rt * 128) >> 10;
        const int nb = (rt * 128) & 1023;
        const int tg = lane & 3, g = lane >> 2;
#pragma unroll
        for (int mt = 0; mt < 2; ++mt) {
            int r = wr * 32 + mt * 16 + g;
#pragma unroll
            for (int nt = 0; nt < 8; ++nt) {
                int d = nt * 8 + tg * 2;
                float2 bi = *(const float2*)&Bb[h * 64 + d];
                float v0 = (acc[mt][nt][0] + bi.x) * qs, v1 = (acc[mt][nt][1] + bi.y) * qs;
                float v2 = (acc[mt][nt][2] + bi.x) * qs, v3 = (acc[mt][nt][3] + bi.y) * qs;
                size_t base = ((((size_t)br * 8 + bb) * 12 + h) * 1024 + (nb + r)) * 64 + d;
                uint32_t h0 = packf16(v0, v1), h1 = packf16(v2, v3);
                *(uint32_t*)&dh[base]          = h0;
                *(uint32_t*)&dh[base + 8 * 64] = h1;
                if (typ < 2) {
                    *(uint32_t*)&dl[base]          = packf16l(v0, v1, h0);
                    *(uint32_t*)&dl[base + 8 * 64] = packf16l(v2, v3, h1);
                }
            }
        }
    }
}

// ------------------------------------------------------------------
// Kernel 3: persistent flash attention, fp16, ex2 softmax.
// QK: fp16 hi/lo 3-pass. PV: single fp16 pass. 64-row KV tiles.
// ------------------------------------------------------------------
#define AQ_PLANE 9216                // 128*72 halfs
#define AKV_PLANE 4608               // 64*72 halfs
#define SKV_(st, pl) ((__half(*)[72])(as_ + 2 * AQ_PLANE + ((st) * 3 + (pl)) * AKV_PLANE))
#define A_SMEM ((2 * AQ_PLANE + 6 * AKV_PLANE) * 2)   // 92160 B
#define A_TILES 768

__global__ __launch_bounds__(256, 2) void attn_kernel(float* __restrict__ out) {
    extern __shared__ __half as_[];
    __shared__ int s_t;
    __half (*sQh)[72] = (__half(*)[72])(as_);
    __half (*sQl)[72] = (__half(*)[72])(as_ + AQ_PLANE);

    const int tid = threadIdx.x, lane = tid & 31, warp = tid >> 5;
    const int g = lane >> 2, tg = lane & 3;
    const int l7 = lane & 7, l8 = lane & 8, l16 = (lane & 16) >> 1;
    const int r0 = warp * 16 + g;

    for (;;) {
        __syncthreads();
        if (tid == 0) s_t = atomicAdd(&g_tickA, 1);
        __syncthreads();
        const int t = s_t;
        if (t >= A_TILES) break;
        const int qt = t & 7, h = (t >> 3) % 12, bb = t / 96;

        for (int brn = 0; brn < 3; ++brn) {
            const size_t hb = (((size_t)brn * 8 + bb) * 12 + h) * (size_t)(1024 * 64);
            const __half* KVp[3] = { g_Kh + hb, g_Kl + hb, g_V + hb };
            const __half* Qp[2]  = { g_Qh + hb + (size_t)qt * 128 * 64,
                                     g_Ql + hb + (size_t)qt * 128 * 64 };

            auto loadKV = [&](int jt, int st) {
#pragma unroll
                for (int i = 0; i < 6; ++i) {
                    int idx = i * 256 + tid;
                    int seg = idx & 7, row = (idx >> 3) & 63, pl = idx >> 9;
                    cp16(smaddr(&SKV_(st, pl)[row][seg * 8]),
                         KVp[pl] + (size_t)(jt * 64 + row) * 64 + seg * 8);
                }
            };

#pragma unroll
            for (int i = 0; i < 8; ++i) {
                int idx = i * 256 + tid;
                int seg = idx & 7, row = (idx >> 3) & 127, pl = idx >> 10;
                cp16(smaddr(&(pl ? sQl : sQh)[row][seg * 8]),
                     Qp[pl] + (size_t)row * 64 + seg * 8);
            }
            loadKV(0, 0);
            cp_commit();

            float m0 = -1e30f, m1 = -1e30f, l0 = 0.f, l1 = 0.f;
            float oa[8][4];
#pragma unroll
            for (int i = 0; i < 8; ++i)
#pragma unroll
                for (int j = 0; j < 4; ++j) oa[i][j] = 0.f;

            for (int jt = 0; jt < 16; ++jt) {
                const int st = jt & 1;
                if (jt < 15) { loadKV(jt + 1, st ^ 1); cp_commit(); cp_wait1(); }
                else cp_wait0();
                __syncthreads();

                __half (*sKh)[72] = SKV_(st, 0), (*sKl)[72] = SKV_(st, 1);
                __half (*sV)[72]  = SKV_(st, 2);

                // ---- S = Q K^T (log2 domain) : fp16 hi/lo, 3 passes ----
                float sf[8][4];
#pragma unroll
                for (int i = 0; i < 8; ++i)
#pragma unroll
                    for (int j = 0; j < 4; ++j) sf[i][j] = 0.f;
#pragma unroll
                for (int ks = 0; ks < 4; ++ks) {
                    const int k0 = ks * 16;
                    uint32_t qh[4], ql[4];
                    ldsm4(qh, smaddr(&sQh[warp * 16 + l7 + l8][k0 + l16]));
                    ldsm4(ql, smaddr(&sQl[warp * 16 + l7 + l8][k0 + l16]));
                    uint32_t kh_[4][4], kl_[4][4];
#pragma unroll
                    for (int p = 0; p < 4; ++p) {
                        int n0 = p * 16 + l7 + l16;
                        ldsm4(kh_[p], smaddr(&sKh[n0][k0 + l8]));
                        ldsm4(kl_[p], smaddr(&sKl[n0][k0 + l8]));
                    }
#pragma unroll
                    for (int p = 0; p < 4; ++p) {
                        mma16h(sf[2 * p],     qh, kh_[p]);
                        mma16h(sf[2 * p + 1], qh, kh_[p] + 2);
                    }
#pragma unroll
                    for (int p = 0; p < 4; ++p) {
                        mma16h(sf[2 * p],     qh, kl_[p]);
                        mma16h(sf[2 * p + 1], qh, kl_[p] + 2);
                    }
#pragma unroll
                    for (int p = 0; p < 4; ++p) {
                        mma16h(sf[2 * p],     ql, kh_[p]);
                        mma16h(sf[2 * p + 1], ql, kh_[p] + 2);
                    }
                }

                // ---- online softmax (base-2) ----
                float t0 = -1e30f, t1 = -1e30f;
#pragma unroll
                for (int nt = 0; nt < 8; ++nt) {
                    t0 = fmaxf(t0, fmaxf(sf[nt][0], sf[nt][1]));
                    t1 = fmaxf(t1, fmaxf(sf[nt][2], sf[nt][3]));
                }
                t0 = fmaxf(t0, __shfl_xor_sync(0xffffffffu, t0, 1));
                t0 = fmaxf(t0, __shfl_xor_sync(0xffffffffu, t0, 2));
                t1 = fmaxf(t1, __shfl_xor_sync(0xffffffffu, t1, 1));
                t1 = fmaxf(t1, __shfl_xor_sync(0xffffffffu, t1, 2));
                float mn0 = fmaxf(m0, t0), mn1 = fmaxf(m1, t1);
                float a0 = ex2(m0 - mn0), a1 = ex2(m1 - mn1);
                m0 = mn0; m1 = mn1;

                float rs0 = 0.f, rs1 = 0.f;
#pragma unroll
                for (int nt = 0; nt < 8; ++nt) {
                    sf[nt][0] = ex2(sf[nt][0] - mn0);
                    sf[nt][1] = ex2(sf[nt][1] - mn0);
                    sf[nt][2] = ex2(sf[nt][2] - mn1);
                    sf[nt][3] = ex2(sf[nt][3] - mn1);
                    rs0 += sf[nt][0] + sf[nt][1];
                    rs1 += sf[nt][2] + sf[nt][3];
                }
                l0 = l0 * a0 + rs0;
                l1 = l1 * a1 + rs1;
#pragma unroll
                for (int nt = 0; nt < 8; ++nt) {
                    oa[nt][0] *= a0; oa[nt][1] *= a0;
                    oa[nt][2] *= a1; oa[nt][3] *= a1;
                }

                // ---- O += P V : fp16 single pass ----
#pragma unroll
                for (int ks = 0; ks < 4; ++ks) {
                    uint32_t ph[4];
                    ph[0] = packf16(sf[2 * ks][0],     sf[2 * ks][1]);
                    ph[1] = packf16(sf[2 * ks][2],     sf[2 * ks][3]);
                    ph[2] = packf16(sf[2 * ks + 1][0], sf[2 * ks + 1][1]);
                    ph[3] = packf16(sf[2 * ks + 1][2], sf[2 * ks + 1][3]);
                    const int kv0 = ks * 16 + l7 + l8;
                    uint32_t vh_[4][4];
#pragma unroll
                    for (int p = 0; p < 4; ++p) {
                        int d0 = p * 16 + l16;
                        ldsm4t(vh_[p], smaddr(&sV[kv0][d0]));
                    }
#pragma unroll
                    for (int p = 0; p < 4; ++p) {
                        mma16h(oa[2 * p],     ph, vh_[p]);
                        mma16h(oa[2 * p + 1], ph, vh_[p] + 2);
                    }
                }
                __syncthreads();
            }

            // fold branch into out (RMW; CTA owns its tile across branches)
            float L0 = l0 + __shfl_xor_sync(0xffffffffu, l0, 1);
            L0 += __shfl_xor_sync(0xffffffffu, L0, 2);
            float L1 = l1 + __shfl_xor_sync(0xffffffffu, l1, 1);
            L1 += __shfl_xor_sync(0xffffffffu, L1, 2);
            float i0 = 1.f / L0, i1 = 1.f / L1;
#pragma unroll
            for (int nt = 0; nt < 8; ++nt) {
                int d = nt * 8 + tg * 2;
                size_t base = ((size_t)bb * 1024 + (size_t)(qt * 128 + r0)) * 768 + h * 64 + d;
                float2 v0 = make_float2(oa[nt][0] * i0, oa[nt][1] * i0);
                float2 v1 = make_float2(oa[nt][2] * i1, oa[nt][3] * i1);
                if (brn) {
                    float2 o0 = *(float2*)&out[base];
                    float2 o1 = *(float2*)&out[base + (size_t)8 * 768];
                    v0.x += o0.x; v0.y += o0.y; v1.x += o1.x; v1.y += o1.y;
                }
                *(float2*)&out[base]                   = v0;
                *(float2*)&out[base + (size_t)8 * 768] = v1;
            }
        }
    }
}

// ------------------------------------------------------------------
extern "C" void kernel_launch(void* const* d_in, const int* in_sizes, int n_in,
                              void* d_out, int out_size) {
    (void)in_sizes; (void)n_in; (void)out_size;
    const float* x  = (const float*)d_in[0];
    const float* wq = (const float*)d_in[1];
    const float* bq = (const float*)d_in[2];
    const float* wk = (const float*)d_in[3];
    const float* bk = (const float*)d_in[4];
    const float* wv = (const float*)d_in[5];
    const float* bv = (const float*)d_in[6];
    float* out = (float*)d_out;

    prep_x_fused<<<8192, 256>>>(x);
    prep_w<<<dim3(768, 9), 192>>>(wq, wk, wv);

    cudaFuncSetAttribute(proj_mma, cudaFuncAttributeMaxDynamicSharedMemorySize, P_SMEM);
    proj_mma<<<296, 256, P_SMEM>>>(bq, bk, bv);

    cudaFuncSetAttribute(attn_kernel, cudaFuncAttributeMaxDynamicSharedMemorySize, A_SMEM);
    attn_kernel<<<296, 256, A_SMEM>>>(out);
}

// round 11
// speedup vs baseline: 2.7006x; 1.1885x over previous
#include <cuda_runtime.h>
#include <cuda_bf16.h>
#include <cuda_fp16.h>
#include <cstdint>
#include <cstddef>

#define DEVI __device__ __forceinline__
#define LOG2E 1.4426950408889634f

// ------------------------------------------------------------------
// Scratch (__device__ globals; allocation-free rule)
// ------------------------------------------------------------------
__device__ int g_tickP, g_tickA;
__device__ __half g_x16[3ull * 8192 * 768];        // fp16 branch-scaled x (all GEMMs)
__device__ __half g_Wh[9ull * 768 * 768];          // W hi (fp16); mats 6-8: only plane
__device__ __half g_Wl[9ull * 768 * 768];          // W lo (fp16 residual); mats 0-5
// attention inputs: fp16. Q,K as hi+lo split; V single plane.
__device__ __half g_Qh[3ull * 8 * 12 * 1024 * 64]; // Q pre-scaled by log2(e)
__device__ __half g_Ql[3ull * 8 * 12 * 1024 * 64];
__device__ __half g_Kh[3ull * 8 * 12 * 1024 * 64];
__device__ __half g_Kl[3ull * 8 * 12 * 1024 * 64];
__device__ __half g_V [3ull * 8 * 12 * 1024 * 64];

// ------------------------------------------------------------------
// Helpers
// ------------------------------------------------------------------
DEVI uint32_t smaddr(const void* p) { return (uint32_t)__cvta_generic_to_shared(p); }

DEVI uint32_t packf16(float a, float b) {
    __half2 h = __floats2half2_rn(a, b);
    uint32_t u; memcpy(&u, &h, 4); return u;
}
DEVI uint32_t packf16l(float a, float b, uint32_t hbits) {
    __half2 h; memcpy(&h, &hbits, 4);
    float2 f = __half22float2(h);
    return packf16(a - f.x, b - f.y);
}
DEVI float ex2(float x) { float r; asm("ex2.approx.f32 %0, %1;" : "=f"(r) : "f"(x)); return r; }

DEVI void cp16(uint32_t dst, const void* src) {
    asm volatile("cp.async.cg.shared.global [%0], [%1], 16;" :: "r"(dst), "l"(src) : "memory");
}
DEVI void cp_commit() { asm volatile("cp.async.commit_group;" ::: "memory"); }
DEVI void cp_wait0()  { asm volatile("cp.async.wait_group 0;" ::: "memory"); }
DEVI void cp_wait1()  { asm volatile("cp.async.wait_group 1;" ::: "memory"); }

DEVI void ldsm4(uint32_t r[4], uint32_t a) {
    asm volatile("ldmatrix.sync.aligned.m8n8.x4.shared.b16 {%0,%1,%2,%3}, [%4];"
                 : "=r"(r[0]), "=r"(r[1]), "=r"(r[2]), "=r"(r[3]) : "r"(a));
}
DEVI void ldsm4t(uint32_t r[4], uint32_t a) {
    asm volatile("ldmatrix.sync.aligned.m8n8.x4.trans.shared.b16 {%0,%1,%2,%3}, [%4];"
                 : "=r"(r[0]), "=r"(r[1]), "=r"(r[2]), "=r"(r[3]) : "r"(a));
}
DEVI void mma16h(float d[4], const uint32_t a[4], const uint32_t b[2]) {
    asm volatile(
        "mma.sync.aligned.m16n8k16.row.col.f32.f16.f16.f32 "
        "{%0,%1,%2,%3}, {%4,%5,%6,%7}, {%8,%9}, {%0,%1,%2,%3};"
        : "+f"(d[0]), "+f"(d[1]), "+f"(d[2]), "+f"(d[3])
        : "r"(a[0]), "r"(a[1]), "r"(a[2]), "r"(a[3]), "r"(b[0]), "r"(b[1]));
}

// ------------------------------------------------------------------
// Kernel 1: fused row scalars + branch-scaled fp16 x. Resets tickets.
// ------------------------------------------------------------------
__global__ __launch_bounds__(256) void prep_x_fused(const float* __restrict__ x) {
    __shared__ float red[8];
    __shared__ float sbr[2];
    const int row = blockIdx.x, tid = threadIdx.x;
    if (row == 0 && tid == 0) { g_tickP = 0; g_tickA = 0; }

    float4 v = make_float4(0.f, 0.f, 0.f, 0.f);
    if (tid < 192) v = *(const float4*)&x[(size_t)row * 768 + tid * 4];
    float ss = fmaf(v.x, v.x, fmaf(v.y, v.y, fmaf(v.z, v.z, v.w * v.w)));
#pragma unroll
    for (int o = 16; o; o >>= 1) ss += __shfl_xor_sync(0xffffffffu, ss, o);
    if ((tid & 31) == 0) red[tid >> 5] = ss;
    __syncthreads();
    if (tid == 0) {
        float t = 0.f;
#pragma unroll
        for (int i = 0; i < 8; ++i) t += red[i];
        float n = fmaxf(sqrtf(t), 1e-5f);
        const float sc = 0.316227766016837933f;     // sqrt(0.1)
        float a = sc * n;
        float th = tanhf(a);
        float s_pre = th / a;
        float norm_h = th / sc;
        float maxn = (1.0f - 4e-3f) / sc;
        sbr[0] = (norm_h > maxn) ? s_pre * (maxn / norm_h) : s_pre;
        float arg = fminf(a, 1.0f - 1e-5f);
        float art = 0.5f * logf((1.0f + arg) / (1.0f - arg));
        sbr[1] = art / (n * sc);
    }
    __syncthreads();
    if (tid < 192) {
        const int c = tid * 4;
#pragma unroll
        for (int br = 0; br < 3; ++br) {
            float s = (br == 0) ? 1.0f : sbr[br - 1];
            size_t o = ((size_t)br * 8192 + row) * 768 + c;
            *(uint32_t*)&g_x16[o]     = packf16(v.x * s, v.y * s);
            *(uint32_t*)&g_x16[o + 2] = packf16(v.z * s, v.w * s);
        }
    }
}

// ------------------------------------------------------------------
// Kernel 1c: split weights into fp16 hi(+lo) planes.
// ------------------------------------------------------------------
__global__ __launch_bounds__(192) void prep_w(
    const float* __restrict__ wq, const float* __restrict__ wk, const float* __restrict__ wv) {
    const int row = blockIdx.x, mat = blockIdx.y;
    const int typ = mat / 3, br = mat % 3;
    const float* W = (typ == 0 ? wq : typ == 1 ? wk : wv) + (size_t)br * 768 * 768;
    const int c = threadIdx.x * 4;
    float4 v = *(const float4*)&W[(size_t)row * 768 + c];
    size_t o = ((size_t)mat * 768 + row) * 768 + c;
    uint32_t h0 = packf16(v.x, v.y), h1 = packf16(v.z, v.w);
    *(uint32_t*)&g_Wh[o]     = h0;
    *(uint32_t*)&g_Wh[o + 2] = h1;
    if (typ < 2) {
        *(uint32_t*)&g_Wl[o]     = packf16l(v.x, v.y, h0);
        *(uint32_t*)&g_Wl[o + 2] = packf16l(v.z, v.w, h1);
    }
}

// ------------------------------------------------------------------
// Kernel 2: persistent projection GEMM, fp16, cp.async 2-stage.
// A = fp16 x (1 plane). Q/K: 2 passes (W hi + W lo). V: 1 pass.
// ------------------------------------------------------------------
#define P_PLANE 5120                 // 128*40 halfs per plane
#define SA_(st)     ((__half(*)[40])(ps + (st) * P_PLANE))
#define SB_(st, pl) ((__half(*)[40])(ps + (2 + (st) * 2 + (pl)) * P_PLANE))
#define P_SMEM (6 * P_PLANE * 2)     // 61440 B
#define P_TILES 3456

__global__ __launch_bounds__(256, 2) void proj_mma(
    const float* __restrict__ bq, const float* __restrict__ bk, const float* __restrict__ bv)
{
    extern __shared__ __half ps[];
    __shared__ int s_t;
    const int tid = threadIdx.x, lane = tid & 31, warp = tid >> 5;
    const int wr = warp >> 1, wc = warp & 1;
    const int l7 = lane & 7, l8 = lane & 8, l16 = (lane & 16) >> 1;

    for (;;) {
        __syncthreads();
        if (tid == 0) s_t = atomicAdd(&g_tickP, 1);
        __syncthreads();
        const int t = s_t;
        if (t >= P_TILES) break;
        const int rt = t & 63, rem = t >> 6;
        const int ct = rem % 6, mat = rem / 6;
        const int br = mat % 3, typ = mat / 3;

        const __half* Ap = g_x16 + ((size_t)br * 8192 + rt * 128) * 768;
        const __half* Bp[2] = {
            g_Wh + ((size_t)mat * 768 + ct * 128) * 768,
            g_Wl + ((size_t)mat * 768 + ct * 128) * 768 };

        float acc[2][8][4];
#pragma unroll
        for (int i = 0; i < 2; ++i)
#pragma unroll
            for (int j = 0; j < 8; ++j)
#pragma unroll
                for (int k = 0; k < 4; ++k) acc[i][j][k] = 0.f;

        auto load_chunk = [&](int kt, int st) {
#pragma unroll
            for (int i = 0; i < 2; ++i) {            // A: 1 plane
                int idx = i * 256 + tid;
                int seg = idx & 3, row = idx >> 2;
                cp16(smaddr(&SA_(st)[row][seg * 8]),
                     Ap + (size_t)row * 768 + kt * 32 + seg * 8);
            }
            const int nb = (typ == 2) ? 2 : 4;       // B: 1 or 2 planes
            for (int i = 0; i < nb; ++i) {
                int idx = i * 256 + tid;
                int seg = idx & 3, row = (idx >> 2) & 127, pl = idx >> 9;
                cp16(smaddr(&SB_(st, pl)[row][seg * 8]),
                     Bp[pl] + (size_t)row * 768 + kt * 32 + seg * 8);
            }
        };

        load_chunk(0, 0);
        cp_commit();

        for (int kt = 0; kt < 24; ++kt) {
            const int st = kt & 1;
            if (kt < 23) { load_chunk(kt + 1, st ^ 1); cp_commit(); cp_wait1(); }
            else cp_wait0();
            __syncthreads();

            __half (*sA)[40]  = SA_(st);
            __half (*sBh)[40] = SB_(st, 0), (*sBl)[40] = SB_(st, 1);
#pragma unroll
            for (int ks = 0; ks < 2; ++ks) {
                const int k0 = ks * 16;
                uint32_t ah[2][4];
#pragma unroll
                for (int mt = 0; mt < 2; ++mt)
                    ldsm4(ah[mt], smaddr(&sA[wr * 32 + mt * 16 + l7 + l8][k0 + l16]));
                uint32_t bh[4][4];
#pragma unroll
                for (int p = 0; p < 4; ++p)
                    ldsm4(bh[p], smaddr(&sBh[wc * 64 + p * 16 + l7 + l16][k0 + l8]));
#pragma unroll
                for (int p = 0; p < 4; ++p)
#pragma unroll
                    for (int mt = 0; mt < 2; ++mt) {
                        mma16h(acc[mt][2 * p],     ah[mt], bh[p]);
                        mma16h(acc[mt][2 * p + 1], ah[mt], bh[p] + 2);
                    }
                if (typ < 2) {
                    uint32_t bl[4][4];
#pragma unroll
                    for (int p = 0; p < 4; ++p)
                        ldsm4(bl[p], smaddr(&sBl[wc * 64 + p * 16 + l7 + l16][k0 + l8]));
#pragma unroll
                    for (int p = 0; p < 4; ++p)
#pragma unroll
                        for (int mt = 0; mt < 2; ++mt) {
                            mma16h(acc[mt][2 * p],     ah[mt], bl[p]);
                            mma16h(acc[mt][2 * p + 1], ah[mt], bl[p] + 2);
                        }
                }
            }
            __syncthreads();
        }

        // epilogue: bias, emit fp16 planes [br][b][h][n][64].
        // Q pre-scaled by log2(e) for the ex2 softmax.
        const float* Bb = (typ == 0 ? bq : typ == 1 ? bk : bv) + br * 768;
        __half* dh = (typ == 0 ? g_Qh : typ == 1 ? g_Kh : g_V);
        __half* dl = (typ == 0 ? g_Ql : g_Kl);
        const float qs = (typ == 0) ? LOG2E : 1.0f;
        const int h  = ct * 2 + wc;
        const int bb = (rt * 128) >> 10;
        const int nb = (rt * 128) & 1023;
        const int tg = lane & 3, g = lane >> 2;
#pragma unroll
        for (int mt = 0; mt < 2; ++mt) {
            int r = wr * 32 + mt * 16 + g;
#pragma unroll
            for (int nt = 0; nt < 8; ++nt) {
                int d = nt * 8 + tg * 2;
                float2 bi = *(const float2*)&Bb[h * 64 + d];
                float v0 = (acc[mt][nt][0] + bi.x) * qs, v1 = (acc[mt][nt][1] + bi.y) * qs;
                float v2 = (acc[mt][nt][2] + bi.x) * qs, v3 = (acc[mt][nt][3] + bi.y) * qs;
                size_t base = ((((size_t)br * 8 + bb) * 12 + h) * 1024 + (nb + r)) * 64 + d;
                uint32_t h0 = packf16(v0, v1), h1 = packf16(v2, v3);
                *(uint32_t*)&dh[base]          = h0;
                *(uint32_t*)&dh[base + 8 * 64] = h1;
                if (typ < 2) {
                    *(uint32_t*)&dl[base]          = packf16l(v0, v1, h0);
                    *(uint32_t*)&dl[base + 8 * 64] = packf16l(v2, v3, h1);
                }
            }
        }
    }
}

// ------------------------------------------------------------------
// Kernel 3: persistent flash attention, fp16, ex2 softmax.
// QK: fp16 hi/lo 3-pass. PV: single fp16 pass. 64-row KV tiles.
// ------------------------------------------------------------------
#define AQ_PLANE 9216                // 128*72 halfs
#define AKV_PLANE 4608               // 64*72 halfs
#define SKV_(st, pl) ((__half(*)[72])(as_ + 2 * AQ_PLANE + ((st) * 3 + (pl)) * AKV_PLANE))
#define A_SMEM ((2 * AQ_PLANE + 6 * AKV_PLANE) * 2)   // 92160 B
#define A_TILES 768

__global__ __launch_bounds__(256, 2) void attn_kernel(float* __restrict__ out) {
    extern __shared__ __half as_[];
    __shared__ int s_t;
    __half (*sQh)[72] = (__half(*)[72])(as_);
    __half (*sQl)[72] = (__half(*)[72])(as_ + AQ_PLANE);

    const int tid = threadIdx.x, lane = tid & 31, warp = tid >> 5;
    const int g = lane >> 2, tg = lane & 3;
    const int l7 = lane & 7, l8 = lane & 8, l16 = (lane & 16) >> 1;
    const int r0 = warp * 16 + g;

    for (;;) {
        __syncthreads();
        if (tid == 0) s_t = atomicAdd(&g_tickA, 1);
        __syncthreads();
        const int t = s_t;
        if (t >= A_TILES) break;
        const int qt = t & 7, h = (t >> 3) % 12, bb = t / 96;

        for (int brn = 0; brn < 3; ++brn) {
            const size_t hb = (((size_t)brn * 8 + bb) * 12 + h) * (size_t)(1024 * 64);
            const __half* KVp[3] = { g_Kh + hb, g_Kl + hb, g_V + hb };
            const __half* Qp[2]  = { g_Qh + hb + (size_t)qt * 128 * 64,
                                     g_Ql + hb + (size_t)qt * 128 * 64 };

            auto loadKV = [&](int jt, int st) {
#pragma unroll
                for (int i = 0; i < 6; ++i) {
                    int idx = i * 256 + tid;
                    int seg = idx & 7, row = (idx >> 3) & 63, pl = idx >> 9;
                    cp16(smaddr(&SKV_(st, pl)[row][seg * 8]),
                         KVp[pl] + (size_t)(jt * 64 + row) * 64 + seg * 8);
                }
            };

#pragma unroll
            for (int i = 0; i < 8; ++i) {
                int idx = i * 256 + tid;
                int seg = idx & 7, row = (idx >> 3) & 127, pl = idx >> 10;
                cp16(smaddr(&(pl ? sQl : sQh)[row][seg * 8]),
                     Qp[pl] + (size_t)row * 64 + seg * 8);
            }
            loadKV(0, 0);
            cp_commit();

            float m0 = -1e30f, m1 = -1e30f, l0 = 0.f, l1 = 0.f;
            float oa[8][4];
#pragma unroll
            for (int i = 0; i < 8; ++i)
#pragma unroll
                for (int j = 0; j < 4; ++j) oa[i][j] = 0.f;

            for (int jt = 0; jt < 16; ++jt) {
                const int st = jt & 1;
                if (jt < 15) { loadKV(jt + 1, st ^ 1); cp_commit(); cp_wait1(); }
                else cp_wait0();
                __syncthreads();

                __half (*sKh)[72] = SKV_(st, 0), (*sKl)[72] = SKV_(st, 1);
                __half (*sV)[72]  = SKV_(st, 2);

                // ---- S = Q K^T (log2 domain) : fp16 hi/lo, 3 passes ----
                float sf[8][4];
#pragma unroll
                for (int i = 0; i < 8; ++i)
#pragma unroll
                    for (int j = 0; j < 4; ++j) sf[i][j] = 0.f;
#pragma unroll
                for (int ks = 0; ks < 4; ++ks) {
                    const int k0 = ks * 16;
                    uint32_t qh[4], ql[4];
                    ldsm4(qh, smaddr(&sQh[warp * 16 + l7 + l8][k0 + l16]));
                    ldsm4(ql, smaddr(&sQl[warp * 16 + l7 + l8][k0 + l16]));
                    uint32_t kh_[4][4], kl_[4][4];
#pragma unroll
                    for (int p = 0; p < 4; ++p) {
                        int n0 = p * 16 + l7 + l16;
                        ldsm4(kh_[p], smaddr(&sKh[n0][k0 + l8]));
                        ldsm4(kl_[p], smaddr(&sKl[n0][k0 + l8]));
                    }
#pragma unroll
                    for (int p = 0; p < 4; ++p) {
                        mma16h(sf[2 * p],     qh, kh_[p]);
                        mma16h(sf[2 * p + 1], qh, kh_[p] + 2);
                    }
#pragma unroll
                    for (int p = 0; p < 4; ++p) {
                        mma16h(sf[2 * p],     qh, kl_[p]);
                        mma16h(sf[2 * p + 1], qh, kl_[p] + 2);
                    }
#pragma unroll
                    for (int p = 0; p < 4; ++p) {
                        mma16h(sf[2 * p],     ql, kh_[p]);
                        mma16h(sf[2 * p + 1], ql, kh_[p] + 2);
                    }
                }

                // ---- online softmax (base-2) ----
                float t0 = -1e30f, t1 = -1e30f;
#pragma unroll
                for (int nt = 0; nt < 8; ++nt) {
                    t0 = fmaxf(t0, fmaxf(sf[nt][0], sf[nt][1]));
                    t1 = fmaxf(t1, fmaxf(sf[nt][2], sf[nt][3]));
                }
                t0 = fmaxf(t0, __shfl_xor_sync(0xffffffffu, t0, 1));
                t0 = fmaxf(t0, __shfl_xor_sync(0xffffffffu, t0, 2));
                t1 = fmaxf(t1, __shfl_xor_sync(0xffffffffu, t1, 1));
                t1 = fmaxf(t1, __shfl_xor_sync(0xffffffffu, t1, 2));
                float mn0 = fmaxf(m0, t0), mn1 = fmaxf(m1, t1);
                float a0 = ex2(m0 - mn0), a1 = ex2(m1 - mn1);
                m0 = mn0; m1 = mn1;

                float rs0 = 0.f, rs1 = 0.f;
#pragma unroll
                for (int nt = 0; nt < 8; ++nt) {
                    sf[nt][0] = ex2(sf[nt][0] - mn0);
                    sf[nt][1] = ex2(sf[nt][1] - mn0);
                    sf[nt][2] = ex2(sf[nt][2] - mn1);
                    sf[nt][3] = ex2(sf[nt][3] - mn1);
                    rs0 += sf[nt][0] + sf[nt][1];
                    rs1 += sf[nt][2] + sf[nt][3];
                }
                l0 = l0 * a0 + rs0;
                l1 = l1 * a1 + rs1;
#pragma unroll
                for (int nt = 0; nt < 8; ++nt) {
                    oa[nt][0] *= a0; oa[nt][1] *= a0;
                    oa[nt][2] *= a1; oa[nt][3] *= a1;
                }

                // ---- O += P V : fp16 single pass ----
#pragma unroll
                for (int ks = 0; ks < 4; ++ks) {
                    uint32_t ph[4];
                    ph[0] = packf16(sf[2 * ks][0],     sf[2 * ks][1]);
                    ph[1] = packf16(sf[2 * ks][2],     sf[2 * ks][3]);
                    ph[2] = packf16(sf[2 * ks + 1][0], sf[2 * ks + 1][1]);
                    ph[3] = packf16(sf[2 * ks + 1][2], sf[2 * ks + 1][3]);
                    const int kv0 = ks * 16 + l7 + l8;
                    uint32_t vh_[4][4];
#pragma unroll
                    for (int p = 0; p < 4; ++p) {
                        int d0 = p * 16 + l16;
                        ldsm4t(vh_[p], smaddr(&sV[kv0][d0]));
                    }
#pragma unroll
                    for (int p = 0; p < 4; ++p) {
                        mma16h(oa[2 * p],     ph, vh_[p]);
                        mma16h(oa[2 * p + 1], ph, vh_[p] + 2);
                    }
                }
                __syncthreads();
            }

            // fold branch into out (RMW; CTA owns its tile across branches)
            float L0 = l0 + __shfl_xor_sync(0xffffffffu, l0, 1);
            L0 += __shfl_xor_sync(0xffffffffu, L0, 2);
            float L1 = l1 + __shfl_xor_sync(0xffffffffu, l1, 1);
            L1 += __shfl_xor_sync(0xffffffffu, L1, 2);
            float i0 = 1.f / L0, i1 = 1.f / L1;
#pragma unroll
            for (int nt = 0; nt < 8; ++nt) {
                int d = nt * 8 + tg * 2;
                size_t base = ((size_t)bb * 1024 + (size_t)(qt * 128 + r0)) * 768 + h * 64 + d;
                float2 v0 = make_float2(oa[nt][0] * i0, oa[nt][1] * i0);
                float2 v1 = make_float2(oa[nt][2] * i1, oa[nt][3] * i1);
                if (brn) {
                    float2 o0 = *(float2*)&out[base];
                    float2 o1 = *(float2*)&out[base + (size_t)8 * 768];
                    v0.x += o0.x; v0.y += o0.y; v1.x += o1.x; v1.y += o1.y;
                }
                *(float2*)&out[base]                   = v0;
                *(float2*)&out[base + (size_t)8 * 768] = v1;
            }
        }
    }
}

// ------------------------------------------------------------------
extern "C" void kernel_launch(void* const* d_in, const int* in_sizes, int n_in,
                              void* d_out, int out_size) {
    (void)in_sizes; (void)n_in; (void)out_size;
    const float* x  = (const float*)d_in[0];
    const float* wq = (const float*)d_in[1];
    const float* bq = (const float*)d_in[2];
    const float* wk = (const float*)d_in[3];
    const float* bk = (const float*)d_in[4];
    const float* wv = (const float*)d_in[5];
    const float* bv = (const float*)d_in[6];
    float* out = (float*)d_out;

    prep_x_fused<<<8192, 256>>>(x);
    prep_w<<<dim3(768, 9), 192>>>(wq, wk, wv);

    cudaFuncSetAttribute(proj_mma, cudaFuncAttributeMaxDynamicSharedMemorySize, P_SMEM);
    proj_mma<<<296, 256, P_SMEM>>>(bq, bk, bv);

    cudaFuncSetAttribute(attn_kernel, cudaFuncAttributeMaxDynamicSharedMemorySize, A_SMEM);
    attn_kernel<<<296, 256, A_SMEM>>>(out);
}

// round 12
// speedup vs baseline: 2.8118x; 1.0412x over previous
#include <cuda_runtime.h>
#include <cuda_bf16.h>
#include <cuda_fp16.h>
#include <cstdint>
#include <cstddef>

#define DEVI __device__ __forceinline__
#define LOG2E 1.4426950408889634f

// ------------------------------------------------------------------
// Scratch (__device__ globals; allocation-free rule)
// ------------------------------------------------------------------
__device__ int g_tickP, g_tickA;
__device__ int g_cnt[768];                         // per-(qt,h,bb) branch-finish counters
__device__ float g_part[3][8ull * 1024 * 768];     // per-branch attention partials
__device__ __half g_x16[3ull * 8192 * 768];        // fp16 branch-scaled x (all GEMMs)
__device__ __half g_Wh[9ull * 768 * 768];          // W hi (fp16); mats 6-8: only plane
__device__ __half g_Wl[9ull * 768 * 768];          // W lo (fp16 residual); mats 0-5
// attention inputs: fp16. Q,K as hi+lo split; V single plane.
__device__ __half g_Qh[3ull * 8 * 12 * 1024 * 64]; // Q pre-scaled by log2(e)
__device__ __half g_Ql[3ull * 8 * 12 * 1024 * 64];
__device__ __half g_Kh[3ull * 8 * 12 * 1024 * 64];
__device__ __half g_Kl[3ull * 8 * 12 * 1024 * 64];
__device__ __half g_V [3ull * 8 * 12 * 1024 * 64];

// ------------------------------------------------------------------
// Helpers
// ------------------------------------------------------------------
DEVI uint32_t smaddr(const void* p) { return (uint32_t)__cvta_generic_to_shared(p); }

DEVI uint32_t packf16(float a, float b) {
    __half2 h = __floats2half2_rn(a, b);
    uint32_t u; memcpy(&u, &h, 4); return u;
}
DEVI uint32_t packf16l(float a, float b, uint32_t hbits) {
    __half2 h; memcpy(&h, &hbits, 4);
    float2 f = __half22float2(h);
    return packf16(a - f.x, b - f.y);
}
DEVI float ex2(float x) { float r; asm("ex2.approx.f32 %0, %1;" : "=f"(r) : "f"(x)); return r; }

DEVI void cp16(uint32_t dst, const void* src) {
    asm volatile("cp.async.cg.shared.global [%0], [%1], 16;" :: "r"(dst), "l"(src) : "memory");
}
DEVI void cp_commit() { asm volatile("cp.async.commit_group;" ::: "memory"); }
DEVI void cp_wait0()  { asm volatile("cp.async.wait_group 0;" ::: "memory"); }
DEVI void cp_wait1()  { asm volatile("cp.async.wait_group 1;" ::: "memory"); }

DEVI void ldsm4(uint32_t r[4], uint32_t a) {
    asm volatile("ldmatrix.sync.aligned.m8n8.x4.shared.b16 {%0,%1,%2,%3}, [%4];"
                 : "=r"(r[0]), "=r"(r[1]), "=r"(r[2]), "=r"(r[3]) : "r"(a));
}
DEVI void ldsm4t(uint32_t r[4], uint32_t a) {
    asm volatile("ldmatrix.sync.aligned.m8n8.x4.trans.shared.b16 {%0,%1,%2,%3}, [%4];"
                 : "=r"(r[0]), "=r"(r[1]), "=r"(r[2]), "=r"(r[3]) : "r"(a));
}
DEVI void mma16h(float d[4], const uint32_t a[4], const uint32_t b[2]) {
    asm volatile(
        "mma.sync.aligned.m16n8k16.row.col.f32.f16.f16.f32 "
        "{%0,%1,%2,%3}, {%4,%5,%6,%7}, {%8,%9}, {%0,%1,%2,%3};"
        : "+f"(d[0]), "+f"(d[1]), "+f"(d[2]), "+f"(d[3])
        : "r"(a[0]), "r"(a[1]), "r"(a[2]), "r"(a[3]), "r"(b[0]), "r"(b[1]));
}

// ------------------------------------------------------------------
// Kernel 1: fused row scalars + branch-scaled fp16 x.
// Resets tickets and branch-finish counters (graph replay safe).
// ------------------------------------------------------------------
__global__ __launch_bounds__(192) void prep_x_fused(const float* __restrict__ x) {
    __shared__ float red[6];
    __shared__ float sbr[2];
    const int row = blockIdx.x, tid = threadIdx.x;
    if (row == 0 && tid == 0) { g_tickP = 0; g_tickA = 0; }
    if (row < 4) g_cnt[row * 192 + tid] = 0;

    float4 v = *(const float4*)&x[(size_t)row * 768 + tid * 4];
    float ss = fmaf(v.x, v.x, fmaf(v.y, v.y, fmaf(v.z, v.z, v.w * v.w)));
#pragma unroll
    for (int o = 16; o; o >>= 1) ss += __shfl_xor_sync(0xffffffffu, ss, o);
    if ((tid & 31) == 0) red[tid >> 5] = ss;
    __syncthreads();
    if (tid == 0) {
        float t = 0.f;
#pragma unroll
        for (int i = 0; i < 6; ++i) t += red[i];
        float n = fmaxf(sqrtf(t), 1e-5f);
        const float sc = 0.316227766016837933f;     // sqrt(0.1)
        float a = sc * n;
        float th = tanhf(a);
        float s_pre = th / a;
        float norm_h = th / sc;
        float maxn = (1.0f - 4e-3f) / sc;
        sbr[0] = (norm_h > maxn) ? s_pre * (maxn / norm_h) : s_pre;
        float arg = fminf(a, 1.0f - 1e-5f);
        float art = 0.5f * logf((1.0f + arg) / (1.0f - arg));
        sbr[1] = art / (n * sc);
    }
    __syncthreads();
    {
        const int c = tid * 4;
#pragma unroll
        for (int br = 0; br < 3; ++br) {
            float s = (br == 0) ? 1.0f : sbr[br - 1];
            size_t o = ((size_t)br * 8192 + row) * 768 + c;
            *(uint32_t*)&g_x16[o]     = packf16(v.x * s, v.y * s);
            *(uint32_t*)&g_x16[o + 2] = packf16(v.z * s, v.w * s);
        }
    }
}

// ------------------------------------------------------------------
// Kernel 1c: split weights into fp16 hi(+lo) planes.
// ------------------------------------------------------------------
__global__ __launch_bounds__(192) void prep_w(
    const float* __restrict__ wq, const float* __restrict__ wk, const float* __restrict__ wv) {
    const int row = blockIdx.x, mat = blockIdx.y;
    const int typ = mat / 3, br = mat % 3;
    const float* W = (typ == 0 ? wq : typ == 1 ? wk : wv) + (size_t)br * 768 * 768;
    const int c = threadIdx.x * 4;
    float4 v = *(const float4*)&W[(size_t)row * 768 + c];
    size_t o = ((size_t)mat * 768 + row) * 768 + c;
    uint32_t h0 = packf16(v.x, v.y), h1 = packf16(v.z, v.w);
    *(uint32_t*)&g_Wh[o]     = h0;
    *(uint32_t*)&g_Wh[o + 2] = h1;
    if (typ < 2) {
        *(uint32_t*)&g_Wl[o]     = packf16l(v.x, v.y, h0);
        *(uint32_t*)&g_Wl[o + 2] = packf16l(v.z, v.w, h1);
    }
}

// ------------------------------------------------------------------
// Kernel 2: persistent projection GEMM, fp16, cp.async 2-stage.
// A = fp16 x (1 plane). Q/K: 2 passes (W hi + W lo). V: 1 pass.
// ------------------------------------------------------------------
#define P_PLANE 5120                 // 128*40 halfs per plane
#define SA_(st)     ((__half(*)[40])(ps + (st) * P_PLANE))
#define SB_(st, pl) ((__half(*)[40])(ps + (2 + (st) * 2 + (pl)) * P_PLANE))
#define P_SMEM (6 * P_PLANE * 2)     // 61440 B
#define P_TILES 3456

__global__ __launch_bounds__(256, 2) void proj_mma(
    const float* __restrict__ bq, const float* __restrict__ bk, const float* __restrict__ bv)
{
    extern __shared__ __half ps[];
    __shared__ int s_t;
    const int tid = threadIdx.x, lane = tid & 31, warp = tid >> 5;
    const int wr = warp >> 1, wc = warp & 1;
    const int l7 = lane & 7, l8 = lane & 8, l16 = (lane & 16) >> 1;

    for (;;) {
        __syncthreads();
        if (tid == 0) s_t = atomicAdd(&g_tickP, 1);
        __syncthreads();
        const int t = s_t;
        if (t >= P_TILES) break;
        const int rt = t & 63, rem = t >> 6;
        const int ct = rem % 6, mat = rem / 6;
        const int br = mat % 3, typ = mat / 3;

        const __half* Ap = g_x16 + ((size_t)br * 8192 + rt * 128) * 768;
        const __half* Bp[2] = {
            g_Wh + ((size_t)mat * 768 + ct * 128) * 768,
            g_Wl + ((size_t)mat * 768 + ct * 128) * 768 };

        float acc[2][8][4];
#pragma unroll
        for (int i = 0; i < 2; ++i)
#pragma unroll
            for (int j = 0; j < 8; ++j)
#pragma unroll
                for (int k = 0; k < 4; ++k) acc[i][j][k] = 0.f;

        auto load_chunk = [&](int kt, int st) {
#pragma unroll
            for (int i = 0; i < 2; ++i) {            // A: 1 plane
                int idx = i * 256 + tid;
                int seg = idx & 3, row = idx >> 2;
                cp16(smaddr(&SA_(st)[row][seg * 8]),
                     Ap + (size_t)row * 768 + kt * 32 + seg * 8);
            }
            const int nb = (typ == 2) ? 2 : 4;       // B: 1 or 2 planes
            for (int i = 0; i < nb; ++i) {
                int idx = i * 256 + tid;
                int seg = idx & 3, row = (idx >> 2) & 127, pl = idx >> 9;
                cp16(smaddr(&SB_(st, pl)[row][seg * 8]),
                     Bp[pl] + (size_t)row * 768 + kt * 32 + seg * 8);
            }
        };

        load_chunk(0, 0);
        cp_commit();

        for (int kt = 0; kt < 24; ++kt) {
            const int st = kt & 1;
            if (kt < 23) { load_chunk(kt + 1, st ^ 1); cp_commit(); cp_wait1(); }
            else cp_wait0();
            __syncthreads();

            __half (*sA)[40]  = SA_(st);
            __half (*sBh)[40] = SB_(st, 0), (*sBl)[40] = SB_(st, 1);
#pragma unroll
            for (int ks = 0; ks < 2; ++ks) {
                const int k0 = ks * 16;
                uint32_t ah[2][4];
#pragma unroll
                for (int mt = 0; mt < 2; ++mt)
                    ldsm4(ah[mt], smaddr(&sA[wr * 32 + mt * 16 + l7 + l8][k0 + l16]));
                uint32_t bh[4][4];
#pragma unroll
                for (int p = 0; p < 4; ++p)
                    ldsm4(bh[p], smaddr(&sBh[wc * 64 + p * 16 + l7 + l16][k0 + l8]));
#pragma unroll
                for (int p = 0; p < 4; ++p)
#pragma unroll
                    for (int mt = 0; mt < 2; ++mt) {
                        mma16h(acc[mt][2 * p],     ah[mt], bh[p]);
                        mma16h(acc[mt][2 * p + 1], ah[mt], bh[p] + 2);
                    }
                if (typ < 2) {
                    uint32_t bl[4][4];
#pragma unroll
                    for (int p = 0; p < 4; ++p)
                        ldsm4(bl[p], smaddr(&sBl[wc * 64 + p * 16 + l7 + l16][k0 + l8]));
#pragma unroll
                    for (int p = 0; p < 4; ++p)
#pragma unroll
                        for (int mt = 0; mt < 2; ++mt) {
                            mma16h(acc[mt][2 * p],     ah[mt], bl[p]);
                            mma16h(acc[mt][2 * p + 1], ah[mt], bl[p] + 2);
                        }
                }
            }
            __syncthreads();
        }

        // epilogue: bias, emit fp16 planes [br][b][h][n][64].
        const float* Bb = (typ == 0 ? bq : typ == 1 ? bk : bv) + br * 768;
        __half* dh = (typ == 0 ? g_Qh : typ == 1 ? g_Kh : g_V);
        __half* dl = (typ == 0 ? g_Ql : g_Kl);
        const float qs = (typ == 0) ? LOG2E : 1.0f;
        const int h  = ct * 2 + wc;
        const int bb = (rt * 128) >> 10;
        const int nb = (rt * 128) & 1023;
        const int tg = lane & 3, g = lane >> 2;
#pragma unroll
        for (int mt = 0; mt < 2; ++mt) {
            int r = wr * 32 + mt * 16 + g;
#pragma unroll
            for (int nt = 0; nt < 8; ++nt) {
                int d = nt * 8 + tg * 2;
                float2 bi = *(const float2*)&Bb[h * 64 + d];
                float v0 = (acc[mt][nt][0] + bi.x) * qs, v1 = (acc[mt][nt][1] + bi.y) * qs;
                float v2 = (acc[mt][nt][2] + bi.x) * qs, v3 = (acc[mt][nt][3] + bi.y) * qs;
                size_t base = ((((size_t)br * 8 + bb) * 12 + h) * 1024 + (nb + r)) * 64 + d;
                uint32_t h0 = packf16(v0, v1), h1 = packf16(v2, v3);
                *(uint32_t*)&dh[base]          = h0;
                *(uint32_t*)&dh[base + 8 * 64] = h1;
                if (typ < 2) {
                    *(uint32_t*)&dl[base]          = packf16l(v0, v1, h0);
                    *(uint32_t*)&dl[base + 8 * 64] = packf16l(v2, v3, h1);
                }
            }
        }
    }
}

// ------------------------------------------------------------------
// Kernel 3: persistent flash attention, fp16, ex2 softmax.
// Ticket = (brn, qt, h, bb): 2304 fine-grained tiles. Cross-branch sum
// via last-finisher (fixed-order p0+p1+p2 => deterministic).
// ------------------------------------------------------------------
#define AQ_PLANE 9216                // 128*72 halfs
#define AKV_PLANE 4608               // 64*72 halfs
#define SKV_(st, pl) ((__half(*)[72])(as_ + 2 * AQ_PLANE + ((st) * 3 + (pl)) * AKV_PLANE))
#define A_SMEM ((2 * AQ_PLANE + 6 * AKV_PLANE) * 2)   // 92160 B
#define A_TILES 2304

__global__ __launch_bounds__(256, 2) void attn_kernel(float* __restrict__ out) {
    extern __shared__ __half as_[];
    __shared__ int s_t, s_c;
    __half (*sQh)[72] = (__half(*)[72])(as_);
    __half (*sQl)[72] = (__half(*)[72])(as_ + AQ_PLANE);

    const int tid = threadIdx.x, lane = tid & 31, warp = tid >> 5;
    const int g = lane >> 2, tg = lane & 3;
    const int l7 = lane & 7, l8 = lane & 8, l16 = (lane & 16) >> 1;
    const int r0 = warp * 16 + g;

    for (;;) {
        __syncthreads();
        if (tid == 0) s_t = atomicAdd(&g_tickA, 1);
        __syncthreads();
        const int t = s_t;
        if (t >= A_TILES) break;
        const int qt = t & 7, h = (t >> 3) % 12;
        const int r2 = t / 96, bb = r2 & 7, brn = r2 >> 3;
        const int tileid = (bb * 12 + h) * 8 + qt;

        const size_t hb = (((size_t)brn * 8 + bb) * 12 + h) * (size_t)(1024 * 64);
        const __half* KVp[3] = { g_Kh + hb, g_Kl + hb, g_V + hb };
        const __half* Qp[2]  = { g_Qh + hb + (size_t)qt * 128 * 64,
                                 g_Ql + hb + (size_t)qt * 128 * 64 };

        auto loadKV = [&](int jt, int st) {
#pragma unroll
            for (int i = 0; i < 6; ++i) {
                int idx = i * 256 + tid;
                int seg = idx & 7, row = (idx >> 3) & 63, pl = idx >> 9;
                cp16(smaddr(&SKV_(st, pl)[row][seg * 8]),
                     KVp[pl] + (size_t)(jt * 64 + row) * 64 + seg * 8);
            }
        };

#pragma unroll
        for (int i = 0; i < 8; ++i) {
            int idx = i * 256 + tid;
            int seg = idx & 7, row = (idx >> 3) & 127, pl = idx >> 10;
            cp16(smaddr(&(pl ? sQl : sQh)[row][seg * 8]),
                 Qp[pl] + (size_t)row * 64 + seg * 8);
        }
        loadKV(0, 0);
        cp_commit();

        float m0 = -1e30f, m1 = -1e30f, l0 = 0.f, l1 = 0.f;
        float oa[8][4];
#pragma unroll
        for (int i = 0; i < 8; ++i)
#pragma unroll
            for (int j = 0; j < 4; ++j) oa[i][j] = 0.f;

        for (int jt = 0; jt < 16; ++jt) {
            const int st = jt & 1;
            if (jt < 15) { loadKV(jt + 1, st ^ 1); cp_commit(); cp_wait1(); }
            else cp_wait0();
            __syncthreads();

            __half (*sKh)[72] = SKV_(st, 0), (*sKl)[72] = SKV_(st, 1);
            __half (*sV)[72]  = SKV_(st, 2);

            // ---- S = Q K^T (log2 domain) : fp16 hi/lo, 3 passes ----
            float sf[8][4];
#pragma unroll
            for (int i = 0; i < 8; ++i)
#pragma unroll
                for (int j = 0; j < 4; ++j) sf[i][j] = 0.f;
#pragma unroll
            for (int ks = 0; ks < 4; ++ks) {
                const int k0 = ks * 16;
                uint32_t qh[4], ql[4];
                ldsm4(qh, smaddr(&sQh[warp * 16 + l7 + l8][k0 + l16]));
                ldsm4(ql, smaddr(&sQl[warp * 16 + l7 + l8][k0 + l16]));
                uint32_t kh_[4][4], kl_[4][4];
#pragma unroll
                for (int p = 0; p < 4; ++p) {
                    int n0 = p * 16 + l7 + l16;
                    ldsm4(kh_[p], smaddr(&sKh[n0][k0 + l8]));
                    ldsm4(kl_[p], smaddr(&sKl[n0][k0 + l8]));
                }
#pragma unroll
                for (int p = 0; p < 4; ++p) {
                    mma16h(sf[2 * p],     qh, kh_[p]);
                    mma16h(sf[2 * p + 1], qh, kh_[p] + 2);
                }
#pragma unroll
                for (int p = 0; p < 4; ++p) {
                    mma16h(sf[2 * p],     qh, kl_[p]);
                    mma16h(sf[2 * p + 1], qh, kl_[p] + 2);
                }
#pragma unroll
                for (int p = 0; p < 4; ++p) {
                    mma16h(sf[2 * p],     ql, kh_[p]);
                    mma16h(sf[2 * p + 1], ql, kh_[p] + 2);
                }
            }

            // ---- online softmax (base-2) ----
            float t0 = -1e30f, t1 = -1e30f;
#pragma unroll
            for (int nt = 0; nt < 8; ++nt) {
                t0 = fmaxf(t0, fmaxf(sf[nt][0], sf[nt][1]));
                t1 = fmaxf(t1, fmaxf(sf[nt][2], sf[nt][3]));
            }
            t0 = fmaxf(t0, __shfl_xor_sync(0xffffffffu, t0, 1));
            t0 = fmaxf(t0, __shfl_xor_sync(0xffffffffu, t0, 2));
            t1 = fmaxf(t1, __shfl_xor_sync(0xffffffffu, t1, 1));
            t1 = fmaxf(t1, __shfl_xor_sync(0xffffffffu, t1, 2));
            float mn0 = fmaxf(m0, t0), mn1 = fmaxf(m1, t1);
            float a0 = ex2(m0 - mn0), a1 = ex2(m1 - mn1);
            m0 = mn0; m1 = mn1;

            float rs0 = 0.f, rs1 = 0.f;
#pragma unroll
            for (int nt = 0; nt < 8; ++nt) {
                sf[nt][0] = ex2(sf[nt][0] - mn0);
                sf[nt][1] = ex2(sf[nt][1] - mn0);
                sf[nt][2] = ex2(sf[nt][2] - mn1);
                sf[nt][3] = ex2(sf[nt][3] - mn1);
                rs0 += sf[nt][0] + sf[nt][1];
                rs1 += sf[nt][2] + sf[nt][3];
            }
            l0 = l0 * a0 + rs0;
            l1 = l1 * a1 + rs1;
#pragma unroll
            for (int nt = 0; nt < 8; ++nt) {
                oa[nt][0] *= a0; oa[nt][1] *= a0;
                oa[nt][2] *= a1; oa[nt][3] *= a1;
            }

            // ---- O += P V : fp16 single pass ----
#pragma unroll
            for (int ks = 0; ks < 4; ++ks) {
                uint32_t ph[4];
                ph[0] = packf16(sf[2 * ks][0],     sf[2 * ks][1]);
                ph[1] = packf16(sf[2 * ks][2],     sf[2 * ks][3]);
                ph[2] = packf16(sf[2 * ks + 1][0], sf[2 * ks + 1][1]);
                ph[3] = packf16(sf[2 * ks + 1][2], sf[2 * ks + 1][3]);
                const int kv0 = ks * 16 + l7 + l8;
                uint32_t vh_[4][4];
#pragma unroll
                for (int p = 0; p < 4; ++p) {
                    int d0 = p * 16 + l16;
                    ldsm4t(vh_[p], smaddr(&sV[kv0][d0]));
                }
#pragma unroll
                for (int p = 0; p < 4; ++p) {
                    mma16h(oa[2 * p],     ph, vh_[p]);
                    mma16h(oa[2 * p + 1], ph, vh_[p] + 2);
                }
            }
            __syncthreads();
        }

        // normalize branch result
        float L0 = l0 + __shfl_xor_sync(0xffffffffu, l0, 1);
        L0 += __shfl_xor_sync(0xffffffffu, L0, 2);
        float L1 = l1 + __shfl_xor_sync(0xffffffffu, l1, 1);
        L1 += __shfl_xor_sync(0xffffffffu, L1, 2);
        float i0 = 1.f / L0, i1 = 1.f / L1;
#pragma unroll
        for (int nt = 0; nt < 8; ++nt) {
            oa[nt][0] *= i0; oa[nt][1] *= i0;
            oa[nt][2] *= i1; oa[nt][3] *= i1;
        }

        // last-finisher combine: first two branches store partials;
        // the third sums p0+p1+p2 in fixed order and writes out.
        if (tid == 0) { __threadfence(); s_c = atomicAdd(&g_cnt[tileid], 1); }
        __syncthreads();
        const int old = s_c;
        if (old < 2) {
            float* dst = g_part[brn];
#pragma unroll
            for (int nt = 0; nt < 8; ++nt) {
                int d = nt * 8 + tg * 2;
                size_t base = ((size_t)bb * 1024 + (size_t)(qt * 128 + r0)) * 768 + h * 64 + d;
                *(float2*)&dst[base]                   = make_float2(oa[nt][0], oa[nt][1]);
                *(float2*)&dst[base + (size_t)8 * 768] = make_float2(oa[nt][2], oa[nt][3]);
            }
        } else {
            __threadfence();
            const float* pA = g_part[brn == 0 ? 1 : 0];   // smaller other index
            const float* pB = g_part[brn == 2 ? 1 : 2];   // larger other index
#pragma unroll
            for (int nt = 0; nt < 8; ++nt) {
                int d = nt * 8 + tg * 2;
                size_t base = ((size_t)bb * 1024 + (size_t)(qt * 128 + r0)) * 768 + h * 64 + d;
#pragma unroll
                for (int half = 0; half < 2; ++half) {
                    size_t a = base + (size_t)half * 8 * 768;
                    float2 me = make_float2(oa[nt][2 * half], oa[nt][2 * half + 1]);
                    float2 xa = *(const float2*)&pA[a];
                    float2 xb = *(const float2*)&pB[a];
                    // fixed order: idx0 + idx1 + idx2
                    float2 s0 = (brn == 0) ? me : xa;                 // branch 0 value
                    float2 s1 = (brn == 1) ? me : (brn == 0 ? xa : xb); // branch 1 value
                    float2 s2 = (brn == 2) ? me : xb;                 // branch 2 value
                    float2 r;
                    r.x = (s0.x + s1.x) + s2.x;
                    r.y = (s0.y + s1.y) + s2.y;
                    *(float2*)&out[a] = r;
                }
            }
        }
    }
}

// ------------------------------------------------------------------
extern "C" void kernel_launch(void* const* d_in, const int* in_sizes, int n_in,
                              void* d_out, int out_size) {
    (void)in_sizes; (void)n_in; (void)out_size;
    const float* x  = (const float*)d_in[0];
    const float* wq = (const float*)d_in[1];
    const float* bq = (const float*)d_in[2];
    const float* wk = (const float*)d_in[3];
    const float* bk = (const float*)d_in[4];
    const float* wv = (const float*)d_in[5];
    const float* bv = (const float*)d_in[6];
    float* out = (float*)d_out;

    prep_x_fused<<<8192, 192>>>(x);
    prep_w<<<dim3(768, 9), 192>>>(wq, wk, wv);

    cudaFuncSetAttribute(proj_mma, cudaFuncAttributeMaxDynamicSharedMemorySize, P_SMEM);
    proj_mma<<<296, 256, P_SMEM>>>(bq, bk, bv);

    cudaFuncSetAttribute(attn_kernel, cudaFuncAttributeMaxDynamicSharedMemorySize, A_SMEM);
    attn_kernel<<<296, 256, A_SMEM>>>(out);
}

// round 13
// speedup vs baseline: 2.8279x; 1.0057x over previous
#include <cuda_runtime.h>
#include <cuda_bf16.h>
#include <cuda_fp16.h>
#include <cstdint>
#include <cstddef>

#define DEVI __device__ __forceinline__
#define LOG2E 1.4426950408889634f

// ------------------------------------------------------------------
// Scratch (__device__ globals; allocation-free rule)
// ------------------------------------------------------------------
__device__ int g_tickP, g_tickA;
__device__ int g_cnt[768];                         // per-(qt,h,bb) branch-finish counters
__device__ float g_part[3][8ull * 1024 * 768];     // per-branch attention partials
__device__ __half g_x16[3ull * 8192 * 768];        // fp16 branch-scaled x (all GEMMs)
__device__ __half g_Wh[9ull * 768 * 768];          // W hi (fp16); mats 6-8: only plane
__device__ __half g_Wl[9ull * 768 * 768];          // W lo (fp16 residual); mats 0-5
// attention inputs: fp16. Q,K as hi+lo split; V single plane.
__device__ __half g_Qh[3ull * 8 * 12 * 1024 * 64]; // Q pre-scaled by log2(e)
__device__ __half g_Ql[3ull * 8 * 12 * 1024 * 64];
__device__ __half g_Kh[3ull * 8 * 12 * 1024 * 64];
__device__ __half g_Kl[3ull * 8 * 12 * 1024 * 64];
__device__ __half g_V [3ull * 8 * 12 * 1024 * 64];

// ------------------------------------------------------------------
// Helpers
// ------------------------------------------------------------------
DEVI uint32_t smaddr(const void* p) { return (uint32_t)__cvta_generic_to_shared(p); }

DEVI uint32_t packf16(float a, float b) {
    __half2 h = __floats2half2_rn(a, b);
    uint32_t u; memcpy(&u, &h, 4); return u;
}
DEVI uint32_t packf16l(float a, float b, uint32_t hbits) {
    __half2 h; memcpy(&h, &hbits, 4);
    float2 f = __half22float2(h);
    return packf16(a - f.x, b - f.y);
}
DEVI float ex2(float x) { float r; asm("ex2.approx.f32 %0, %1;" : "=f"(r) : "f"(x)); return r; }

DEVI void cp16(uint32_t dst, const void* src) {
    asm volatile("cp.async.cg.shared.global [%0], [%1], 16;" :: "r"(dst), "l"(src) : "memory");
}
DEVI void cp_commit() { asm volatile("cp.async.commit_group;" ::: "memory"); }
DEVI void cp_wait0()  { asm volatile("cp.async.wait_group 0;" ::: "memory"); }
DEVI void cp_wait1()  { asm volatile("cp.async.wait_group 1;" ::: "memory"); }

DEVI void ldsm4(uint32_t r[4], uint32_t a) {
    asm volatile("ldmatrix.sync.aligned.m8n8.x4.shared.b16 {%0,%1,%2,%3}, [%4];"
                 : "=r"(r[0]), "=r"(r[1]), "=r"(r[2]), "=r"(r[3]) : "r"(a));
}
DEVI void ldsm4t(uint32_t r[4], uint32_t a) {
    asm volatile("ldmatrix.sync.aligned.m8n8.x4.trans.shared.b16 {%0,%1,%2,%3}, [%4];"
                 : "=r"(r[0]), "=r"(r[1]), "=r"(r[2]), "=r"(r[3]) : "r"(a));
}
DEVI void mma16h(float d[4], const uint32_t a[4], const uint32_t b[2]) {
    asm volatile(
        "mma.sync.aligned.m16n8k16.row.col.f32.f16.f16.f32 "
        "{%0,%1,%2,%3}, {%4,%5,%6,%7}, {%8,%9}, {%0,%1,%2,%3};"
        : "+f"(d[0]), "+f"(d[1]), "+f"(d[2]), "+f"(d[3])
        : "r"(a[0]), "r"(a[1]), "r"(a[2]), "r"(a[3]), "r"(b[0]), "r"(b[1]));
}

// ------------------------------------------------------------------
// Kernel 1: fused row scalars + branch-scaled fp16 x.
// Resets tickets and branch-finish counters (graph replay safe).
// ------------------------------------------------------------------
__global__ __launch_bounds__(192) void prep_x_fused(const float* __restrict__ x) {
    __shared__ float red[6];
    __shared__ float sbr[2];
    const int row = blockIdx.x, tid = threadIdx.x;
    if (row == 0 && tid == 0) { g_tickP = 0; g_tickA = 0; }
    if (row < 4) g_cnt[row * 192 + tid] = 0;

    float4 v = *(const float4*)&x[(size_t)row * 768 + tid * 4];
    float ss = fmaf(v.x, v.x, fmaf(v.y, v.y, fmaf(v.z, v.z, v.w * v.w)));
#pragma unroll
    for (int o = 16; o; o >>= 1) ss += __shfl_xor_sync(0xffffffffu, ss, o);
    if ((tid & 31) == 0) red[tid >> 5] = ss;
    __syncthreads();
    if (tid == 0) {
        float t = 0.f;
#pragma unroll
        for (int i = 0; i < 6; ++i) t += red[i];
        float n = fmaxf(sqrtf(t), 1e-5f);
        const float sc = 0.316227766016837933f;     // sqrt(0.1)
        float a = sc * n;
        float th = tanhf(a);
        float s_pre = th / a;
        float norm_h = th / sc;
        float maxn = (1.0f - 4e-3f) / sc;
        sbr[0] = (norm_h > maxn) ? s_pre * (maxn / norm_h) : s_pre;
        float arg = fminf(a, 1.0f - 1e-5f);
        float art = 0.5f * logf((1.0f + arg) / (1.0f - arg));
        sbr[1] = art / (n * sc);
    }
    __syncthreads();
    {
        const int c = tid * 4;
#pragma unroll
        for (int br = 0; br < 3; ++br) {
            float s = (br == 0) ? 1.0f : sbr[br - 1];
            size_t o = ((size_t)br * 8192 + row) * 768 + c;
            *(uint32_t*)&g_x16[o]     = packf16(v.x * s, v.y * s);
            *(uint32_t*)&g_x16[o + 2] = packf16(v.z * s, v.w * s);
        }
    }
}

// ------------------------------------------------------------------
// Kernel 1c: split weights into fp16 hi(+lo) planes.
// ------------------------------------------------------------------
__global__ __launch_bounds__(192) void prep_w(
    const float* __restrict__ wq, const float* __restrict__ wk, const float* __restrict__ wv) {
    const int row = blockIdx.x, mat = blockIdx.y;
    const int typ = mat / 3, br = mat % 3;
    const float* W = (typ == 0 ? wq : typ == 1 ? wk : wv) + (size_t)br * 768 * 768;
    const int c = threadIdx.x * 4;
    float4 v = *(const float4*)&W[(size_t)row * 768 + c];
    size_t o = ((size_t)mat * 768 + row) * 768 + c;
    uint32_t h0 = packf16(v.x, v.y), h1 = packf16(v.z, v.w);
    *(uint32_t*)&g_Wh[o]     = h0;
    *(uint32_t*)&g_Wh[o + 2] = h1;
    if (typ < 2) {
        *(uint32_t*)&g_Wl[o]     = packf16l(v.x, v.y, h0);
        *(uint32_t*)&g_Wl[o + 2] = packf16l(v.z, v.w, h1);
    }
}

// ------------------------------------------------------------------
// Kernel 2: persistent projection GEMM, fp16, cp.async 3-stage,
// single barrier per chunk (wait -> BAR -> load-next -> compute).
// A = fp16 x (1 plane). Q/K: 2 passes (W hi + W lo). V: 1 pass.
// ------------------------------------------------------------------
#define P_PLANE 5120                 // 128*40 halfs per plane
#define SA_(st)     ((__half(*)[40])(ps + (st) * P_PLANE))
#define SB_(st, pl) ((__half(*)[40])(ps + (3 + (st) * 2 + (pl)) * P_PLANE))
#define P_SMEM (9 * P_PLANE * 2)     // 92160 B (3 stages x 3 planes)
#define P_TILES 3456

__global__ __launch_bounds__(256, 2) void proj_mma(
    const float* __restrict__ bq, const float* __restrict__ bk, const float* __restrict__ bv)
{
    extern __shared__ __half ps[];
    __shared__ int s_t;
    const int tid = threadIdx.x, lane = tid & 31, warp = tid >> 5;
    const int wr = warp >> 1, wc = warp & 1;
    const int l7 = lane & 7, l8 = lane & 8, l16 = (lane & 16) >> 1;

    for (;;) {
        __syncthreads();
        if (tid == 0) s_t = atomicAdd(&g_tickP, 1);
        __syncthreads();
        const int t = s_t;
        if (t >= P_TILES) break;
        const int rt = t & 63, rem = t >> 6;
        const int ct = rem % 6, mat = rem / 6;
        const int br = mat % 3, typ = mat / 3;

        const __half* Ap = g_x16 + ((size_t)br * 8192 + rt * 128) * 768;
        const __half* Bp[2] = {
            g_Wh + ((size_t)mat * 768 + ct * 128) * 768,
            g_Wl + ((size_t)mat * 768 + ct * 128) * 768 };

        float acc[2][8][4];
#pragma unroll
        for (int i = 0; i < 2; ++i)
#pragma unroll
            for (int j = 0; j < 8; ++j)
#pragma unroll
                for (int k = 0; k < 4; ++k) acc[i][j][k] = 0.f;

        auto load_chunk = [&](int kt, int st) {
#pragma unroll
            for (int i = 0; i < 2; ++i) {            // A: 1 plane
                int idx = i * 256 + tid;
                int seg = idx & 3, row = idx >> 2;
                cp16(smaddr(&SA_(st)[row][seg * 8]),
                     Ap + (size_t)row * 768 + kt * 32 + seg * 8);
            }
            const int nb = (typ == 2) ? 2 : 4;       // B: 1 or 2 planes
            for (int i = 0; i < nb; ++i) {
                int idx = i * 256 + tid;
                int seg = idx & 3, row = (idx >> 2) & 127, pl = idx >> 9;
                cp16(smaddr(&SB_(st, pl)[row][seg * 8]),
                     Bp[pl] + (size_t)row * 768 + kt * 32 + seg * 8);
            }
        };

        load_chunk(0, 0); cp_commit();
        load_chunk(1, 1); cp_commit();

        for (int kt = 0; kt < 24; ++kt) {
            const int st = kt % 3;
            if (kt == 23) cp_wait0(); else cp_wait1();
            __syncthreads();                 // releases compute(kt); proves kt-1 done
            if (kt < 22) { load_chunk(kt + 2, (kt + 2) % 3); cp_commit(); }

            __half (*sA)[40]  = SA_(st);
            __half (*sBh)[40] = SB_(st, 0), (*sBl)[40] = SB_(st, 1);
#pragma unroll
            for (int ks = 0; ks < 2; ++ks) {
                const int k0 = ks * 16;
                uint32_t ah[2][4];
#pragma unroll
                for (int mt = 0; mt < 2; ++mt)
                    ldsm4(ah[mt], smaddr(&sA[wr * 32 + mt * 16 + l7 + l8][k0 + l16]));
                uint32_t bh[4][4];
#pragma unroll
                for (int p = 0; p < 4; ++p)
                    ldsm4(bh[p], smaddr(&sBh[wc * 64 + p * 16 + l7 + l16][k0 + l8]));
#pragma unroll
                for (int p = 0; p < 4; ++p)
#pragma unroll
                    for (int mt = 0; mt < 2; ++mt) {
                        mma16h(acc[mt][2 * p],     ah[mt], bh[p]);
                        mma16h(acc[mt][2 * p + 1], ah[mt], bh[p] + 2);
                    }
                if (typ < 2) {
                    uint32_t bl[4][4];
#pragma unroll
                    for (int p = 0; p < 4; ++p)
                        ldsm4(bl[p], smaddr(&sBl[wc * 64 + p * 16 + l7 + l16][k0 + l8]));
#pragma unroll
                    for (int p = 0; p < 4; ++p)
#pragma unroll
                        for (int mt = 0; mt < 2; ++mt) {
                            mma16h(acc[mt][2 * p],     ah[mt], bl[p]);
                            mma16h(acc[mt][2 * p + 1], ah[mt], bl[p] + 2);
                        }
                }
            }
        }

        // epilogue: bias, emit fp16 planes [br][b][h][n][64].
        const float* Bb = (typ == 0 ? bq : typ == 1 ? bk : bv) + br * 768;
        __half* dh = (typ == 0 ? g_Qh : typ == 1 ? g_Kh : g_V);
        __half* dl = (typ == 0 ? g_Ql : g_Kl);
        const float qs = (typ == 0) ? LOG2E : 1.0f;
        const int h  = ct * 2 + wc;
        const int bb = (rt * 128) >> 10;
        const int nb = (rt * 128) & 1023;
        const int tg = lane & 3, g = lane >> 2;
#pragma unroll
        for (int mt = 0; mt < 2; ++mt) {
            int r = wr * 32 + mt * 16 + g;
#pragma unroll
            for (int nt = 0; nt < 8; ++nt) {
                int d = nt * 8 + tg * 2;
                float2 bi = *(const float2*)&Bb[h * 64 + d];
                float v0 = (acc[mt][nt][0] + bi.x) * qs, v1 = (acc[mt][nt][1] + bi.y) * qs;
                float v2 = (acc[mt][nt][2] + bi.x) * qs, v3 = (acc[mt][nt][3] + bi.y) * qs;
                size_t base = ((((size_t)br * 8 + bb) * 12 + h) * 1024 + (nb + r)) * 64 + d;
                uint32_t h0 = packf16(v0, v1), h1 = packf16(v2, v3);
                *(uint32_t*)&dh[base]          = h0;
                *(uint32_t*)&dh[base + 8 * 64] = h1;
                if (typ < 2) {
                    *(uint32_t*)&dl[base]          = packf16l(v0, v1, h0);
                    *(uint32_t*)&dl[base + 8 * 64] = packf16l(v2, v3, h1);
                }
            }
        }
    }
}

// ------------------------------------------------------------------
// Kernel 3: persistent flash attention, fp16, ex2 softmax.
// Ticket = (brn, qt, h, bb). Single barrier per KV tile.
// Cross-branch sum via last-finisher (fixed-order, deterministic).
// ------------------------------------------------------------------
#define AQ_PLANE 9216                // 128*72 halfs
#define AKV_PLANE 4608               // 64*72 halfs
#define SKV_(st, pl) ((__half(*)[72])(as_ + 2 * AQ_PLANE + ((st) * 3 + (pl)) * AKV_PLANE))
#define A_SMEM ((2 * AQ_PLANE + 6 * AKV_PLANE) * 2)   // 92160 B
#define A_TILES 2304

__global__ __launch_bounds__(256, 2) void attn_kernel(float* __restrict__ out) {
    extern __shared__ __half as_[];
    __shared__ int s_t, s_c;
    __half (*sQh)[72] = (__half(*)[72])(as_);
    __half (*sQl)[72] = (__half(*)[72])(as_ + AQ_PLANE);

    const int tid = threadIdx.x, lane = tid & 31, warp = tid >> 5;
    const int g = lane >> 2, tg = lane & 3;
    const int l7 = lane & 7, l8 = lane & 8, l16 = (lane & 16) >> 1;
    const int r0 = warp * 16 + g;

    for (;;) {
        __syncthreads();
        if (tid == 0) s_t = atomicAdd(&g_tickA, 1);
        __syncthreads();
        const int t = s_t;
        if (t >= A_TILES) break;
        const int qt = t & 7, h = (t >> 3) % 12;
        const int r2 = t / 96, bb = r2 & 7, brn = r2 >> 3;
        const int tileid = (bb * 12 + h) * 8 + qt;

        const size_t hb = (((size_t)brn * 8 + bb) * 12 + h) * (size_t)(1024 * 64);
        const __half* KVp[3] = { g_Kh + hb, g_Kl + hb, g_V + hb };
        const __half* Qp[2]  = { g_Qh + hb + (size_t)qt * 128 * 64,
                                 g_Ql + hb + (size_t)qt * 128 * 64 };

        auto loadKV = [&](int jt, int st) {
#pragma unroll
            for (int i = 0; i < 6; ++i) {
                int idx = i * 256 + tid;
                int seg = idx & 7, row = (idx >> 3) & 63, pl = idx >> 9;
                cp16(smaddr(&SKV_(st, pl)[row][seg * 8]),
                     KVp[pl] + (size_t)(jt * 64 + row) * 64 + seg * 8);
            }
        };

#pragma unroll
        for (int i = 0; i < 8; ++i) {
            int idx = i * 256 + tid;
            int seg = idx & 7, row = (idx >> 3) & 127, pl = idx >> 10;
            cp16(smaddr(&(pl ? sQl : sQh)[row][seg * 8]),
                 Qp[pl] + (size_t)row * 64 + seg * 8);
        }
        loadKV(0, 0);
        cp_commit();

        float m0 = -1e30f, m1 = -1e30f, l0 = 0.f, l1 = 0.f;
        float oa[8][4];
#pragma unroll
        for (int i = 0; i < 8; ++i)
#pragma unroll
            for (int j = 0; j < 4; ++j) oa[i][j] = 0.f;

        for (int jt = 0; jt < 16; ++jt) {
            const int st = jt & 1;
            cp_wait0();
            __syncthreads();                 // releases compute(jt); proves jt-1 done
            if (jt < 15) { loadKV(jt + 1, st ^ 1); cp_commit(); }

            __half (*sKh)[72] = SKV_(st, 0), (*sKl)[72] = SKV_(st, 1);
            __half (*sV)[72]  = SKV_(st, 2);

            // ---- S = Q K^T (log2 domain) : fp16 hi/lo, 3 passes ----
            float sf[8][4];
#pragma unroll
            for (int i = 0; i < 8; ++i)
#pragma unroll
                for (int j = 0; j < 4; ++j) sf[i][j] = 0.f;
#pragma unroll
            for (int ks = 0; ks < 4; ++ks) {
                const int k0 = ks * 16;
                uint32_t qh[4], ql[4];
                ldsm4(qh, smaddr(&sQh[warp * 16 + l7 + l8][k0 + l16]));
                ldsm4(ql, smaddr(&sQl[warp * 16 + l7 + l8][k0 + l16]));
                uint32_t kh_[4][4], kl_[4][4];
#pragma unroll
                for (int p = 0; p < 4; ++p) {
                    int n0 = p * 16 + l7 + l16;
                    ldsm4(kh_[p], smaddr(&sKh[n0][k0 + l8]));
                    ldsm4(kl_[p], smaddr(&sKl[n0][k0 + l8]));
                }
#pragma unroll
                for (int p = 0; p < 4; ++p) {
                    mma16h(sf[2 * p],     qh, kh_[p]);
                    mma16h(sf[2 * p + 1], qh, kh_[p] + 2);
                }
#pragma unroll
                for (int p = 0; p < 4; ++p) {
                    mma16h(sf[2 * p],     qh, kl_[p]);
                    mma16h(sf[2 * p + 1], qh, kl_[p] + 2);
                }
#pragma unroll
                for (int p = 0; p < 4; ++p) {
                    mma16h(sf[2 * p],     ql, kh_[p]);
                    mma16h(sf[2 * p + 1], ql, kh_[p] + 2);
                }
            }

            // ---- online softmax (base-2) ----
            float t0 = -1e30f, t1 = -1e30f;
#pragma unroll
            for (int nt = 0; nt < 8; ++nt) {
                t0 = fmaxf(t0, fmaxf(sf[nt][0], sf[nt][1]));
                t1 = fmaxf(t1, fmaxf(sf[nt][2], sf[nt][3]));
            }
            t0 = fmaxf(t0, __shfl_xor_sync(0xffffffffu, t0, 1));
            t0 = fmaxf(t0, __shfl_xor_sync(0xffffffffu, t0, 2));
            t1 = fmaxf(t1, __shfl_xor_sync(0xffffffffu, t1, 1));
            t1 = fmaxf(t1, __shfl_xor_sync(0xffffffffu, t1, 2));
            float mn0 = fmaxf(m0, t0), mn1 = fmaxf(m1, t1);
            float a0 = ex2(m0 - mn0), a1 = ex2(m1 - mn1);
            m0 = mn0; m1 = mn1;

            float rs0 = 0.f, rs1 = 0.f;
#pragma unroll
            for (int nt = 0; nt < 8; ++nt) {
                sf[nt][0] = ex2(sf[nt][0] - mn0);
                sf[nt][1] = ex2(sf[nt][1] - mn0);
                sf[nt][2] = ex2(sf[nt][2] - mn1);
                sf[nt][3] = ex2(sf[nt][3] - mn1);
                rs0 += sf[nt][0] + sf[nt][1];
                rs1 += sf[nt][2] + sf[nt][3];
            }
            l0 = l0 * a0 + rs0;
            l1 = l1 * a1 + rs1;
#pragma unroll
            for (int nt = 0; nt < 8; ++nt) {
                oa[nt][0] *= a0; oa[nt][1] *= a0;
                oa[nt][2] *= a1; oa[nt][3] *= a1;
            }

            // ---- O += P V : fp16 single pass ----
#pragma unroll
            for (int ks = 0; ks < 4; ++ks) {
                uint32_t ph[4];
                ph[0] = packf16(sf[2 * ks][0],     sf[2 * ks][1]);
                ph[1] = packf16(sf[2 * ks][2],     sf[2 * ks][3]);
                ph[2] = packf16(sf[2 * ks + 1][0], sf[2 * ks + 1][1]);
                ph[3] = packf16(sf[2 * ks + 1][2], sf[2 * ks + 1][3]);
                const int kv0 = ks * 16 + l7 + l8;
                uint32_t vh_[4][4];
#pragma unroll
                for (int p = 0; p < 4; ++p) {
                    int d0 = p * 16 + l16;
                    ldsm4t(vh_[p], smaddr(&sV[kv0][d0]));
                }
#pragma unroll
                for (int p = 0; p < 4; ++p) {
                    mma16h(oa[2 * p],     ph, vh_[p]);
                    mma16h(oa[2 * p + 1], ph, vh_[p] + 2);
                }
            }
        }

        // normalize branch result
        float L0 = l0 + __shfl_xor_sync(0xffffffffu, l0, 1);
        L0 += __shfl_xor_sync(0xffffffffu, L0, 2);
        float L1 = l1 + __shfl_xor_sync(0xffffffffu, l1, 1);
        L1 += __shfl_xor_sync(0xffffffffu, L1, 2);
        float i0 = 1.f / L0, i1 = 1.f / L1;
#pragma unroll
        for (int nt = 0; nt < 8; ++nt) {
            oa[nt][0] *= i0; oa[nt][1] *= i0;
            oa[nt][2] *= i1; oa[nt][3] *= i1;
        }

        // last-finisher combine: first two branches store partials;
        // the third sums p0+p1+p2 in fixed order and writes out.
        if (tid == 0) { __threadfence(); s_c = atomicAdd(&g_cnt[tileid], 1); }
        __syncthreads();
        const int old = s_c;
        if (old < 2) {
            float* dst = g_part[brn];
#pragma unroll
            for (int nt = 0; nt < 8; ++nt) {
                int d = nt * 8 + tg * 2;
                size_t base = ((size_t)bb * 1024 + (size_t)(qt * 128 + r0)) * 768 + h * 64 + d;
                *(float2*)&dst[base]                   = make_float2(oa[nt][0], oa[nt][1]);
                *(float2*)&dst[base + (size_t)8 * 768] = make_float2(oa[nt][2], oa[nt][3]);
            }
        } else {
            __threadfence();
            const float* pA = g_part[brn == 0 ? 1 : 0];
            const float* pB = g_part[brn == 2 ? 1 : 2];
#pragma unroll
            for (int nt = 0; nt < 8; ++nt) {
                int d = nt * 8 + tg * 2;
                size_t base = ((size_t)bb * 1024 + (size_t)(qt * 128 + r0)) * 768 + h * 64 + d;
#pragma unroll
                for (int half = 0; half < 2; ++half) {
                    size_t a = base + (size_t)half * 8 * 768;
                    float2 me = make_float2(oa[nt][2 * half], oa[nt][2 * half + 1]);
                    float2 xa = *(const float2*)&pA[a];
                    float2 xb = *(const float2*)&pB[a];
                    float2 s0 = (brn == 0) ? me : xa;
                    float2 s1 = (brn == 1) ? me : (brn == 0 ? xa : xb);
                    float2 s2 = (brn == 2) ? me : xb;
                    float2 r;
                    r.x = (s0.x + s1.x) + s2.x;
                    r.y = (s0.y + s1.y) + s2.y;
                    *(float2*)&out[a] = r;
                }
            }
        }
    }
}

// ------------------------------------------------------------------
extern "C" void kernel_launch(void* const* d_in, const int* in_sizes, int n_in,
                              void* d_out, int out_size) {
    (void)in_sizes; (void)n_in; (void)out_size;
    const float* x  = (const float*)d_in[0];
    const float* wq = (const float*)d_in[1];
    const float* bq = (const float*)d_in[2];
    const float* wk = (const float*)d_in[3];
    const float* bk = (const float*)d_in[4];
    const float* wv = (const float*)d_in[5];
    const float* bv = (const float*)d_in[6];
    float* out = (float*)d_out;

    prep_x_fused<<<8192, 192>>>(x);
    prep_w<<<dim3(768, 9), 192>>>(wq, wk, wv);

    cudaFuncSetAttribute(proj_mma, cudaFuncAttributeMaxDynamicSharedMemorySize, P_SMEM);
    proj_mma<<<296, 256, P_SMEM>>>(bq, bk, bv);

    cudaFuncSetAttribute(attn_kernel, cudaFuncAttributeMaxDynamicSharedMemorySize, A_SMEM);
    attn_kernel<<<296, 256, A_SMEM>>>(out);
}

// round 14
// speedup vs baseline: 2.9607x; 1.0470x over previous
#include <cuda_runtime.h>
#include <cuda_bf16.h>
#include <cuda_fp16.h>
#include <cstdint>
#include <cstddef>

#define DEVI __device__ __forceinline__
#define LOG2E 1.4426950408889634f
#define NCTA 304                     // 152 SMs x 2 CTAs

// ------------------------------------------------------------------
// Scratch (__device__ globals; allocation-free rule)
// ------------------------------------------------------------------
__device__ int g_tickP, g_tickA;
__device__ int g_cnt[768];                         // per-(qt,h,bb) branch-finish counters
__device__ float g_part[3][8ull * 1024 * 768];     // per-branch attention partials
__device__ __half g_x16[3ull * 8192 * 768];        // fp16 branch-scaled x (all GEMMs)
__device__ __half g_Wh[9ull * 768 * 768];          // W hi (fp16); mats 6-8: only plane
__device__ __half g_Wl[9ull * 768 * 768];          // W lo (fp16 residual); mats 0-5
// attention inputs: fp16. Q,K as hi+lo split; V single plane.
__device__ __half g_Qh[3ull * 8 * 12 * 1024 * 64]; // Q pre-scaled by log2(e)
__device__ __half g_Ql[3ull * 8 * 12 * 1024 * 64];
__device__ __half g_Kh[3ull * 8 * 12 * 1024 * 64];
__device__ __half g_Kl[3ull * 8 * 12 * 1024 * 64];
__device__ __half g_V [3ull * 8 * 12 * 1024 * 64];

// ------------------------------------------------------------------
// Helpers
// ------------------------------------------------------------------
DEVI uint32_t smaddr(const void* p) { return (uint32_t)__cvta_generic_to_shared(p); }

DEVI uint32_t packf16(float a, float b) {
    __half2 h = __floats2half2_rn(a, b);
    uint32_t u; memcpy(&u, &h, 4); return u;
}
DEVI uint32_t packf16l(float a, float b, uint32_t hbits) {
    __half2 h; memcpy(&h, &hbits, 4);
    float2 f = __half22float2(h);
    return packf16(a - f.x, b - f.y);
}
DEVI float ex2(float x) { float r; asm("ex2.approx.f32 %0, %1;" : "=f"(r) : "f"(x)); return r; }

DEVI void cp16(uint32_t dst, const void* src) {
    asm volatile("cp.async.cg.shared.global [%0], [%1], 16;" :: "r"(dst), "l"(src) : "memory");
}
DEVI void cp_commit() { asm volatile("cp.async.commit_group;" ::: "memory"); }
DEVI void cp_wait0()  { asm volatile("cp.async.wait_group 0;" ::: "memory"); }

DEVI void ldsm4(uint32_t r[4], uint32_t a) {
    asm volatile("ldmatrix.sync.aligned.m8n8.x4.shared.b16 {%0,%1,%2,%3}, [%4];"
                 : "=r"(r[0]), "=r"(r[1]), "=r"(r[2]), "=r"(r[3]) : "r"(a));
}
DEVI void ldsm4t(uint32_t r[4], uint32_t a) {
    asm volatile("ldmatrix.sync.aligned.m8n8.x4.trans.shared.b16 {%0,%1,%2,%3}, [%4];"
                 : "=r"(r[0]), "=r"(r[1]), "=r"(r[2]), "=r"(r[3]) : "r"(a));
}
DEVI void mma16h(float d[4], const uint32_t a[4], const uint32_t b[2]) {
    asm volatile(
        "mma.sync.aligned.m16n8k16.row.col.f32.f16.f16.f32 "
        "{%0,%1,%2,%3}, {%4,%5,%6,%7}, {%8,%9}, {%0,%1,%2,%3};"
        : "+f"(d[0]), "+f"(d[1]), "+f"(d[2]), "+f"(d[3])
        : "r"(a[0]), "r"(a[1]), "r"(a[2]), "r"(a[3]), "r"(b[0]), "r"(b[1]));
}

// ------------------------------------------------------------------
// Kernel 1: fused row scalars + branch-scaled fp16 x.
// Resets tickets and branch-finish counters (graph replay safe).
// ------------------------------------------------------------------
__global__ __launch_bounds__(192) void prep_x_fused(const float* __restrict__ x) {
    __shared__ float red[6];
    __shared__ float sbr[2];
    const int row = blockIdx.x, tid = threadIdx.x;
    if (row == 0 && tid == 0) { g_tickP = 0; g_tickA = 0; }
    if (row < 4) g_cnt[row * 192 + tid] = 0;

    float4 v = *(const float4*)&x[(size_t)row * 768 + tid * 4];
    float ss = fmaf(v.x, v.x, fmaf(v.y, v.y, fmaf(v.z, v.z, v.w * v.w)));
#pragma unroll
    for (int o = 16; o; o >>= 1) ss += __shfl_xor_sync(0xffffffffu, ss, o);
    if ((tid & 31) == 0) red[tid >> 5] = ss;
    __syncthreads();
    if (tid == 0) {
        float t = 0.f;
#pragma unroll
        for (int i = 0; i < 6; ++i) t += red[i];
        float n = fmaxf(sqrtf(t), 1e-5f);
        const float sc = 0.316227766016837933f;     // sqrt(0.1)
        float a = sc * n;
        float th = tanhf(a);
        float s_pre = th / a;
        float norm_h = th / sc;
        float maxn = (1.0f - 4e-3f) / sc;
        sbr[0] = (norm_h > maxn) ? s_pre * (maxn / norm_h) : s_pre;
        float arg = fminf(a, 1.0f - 1e-5f);
        float art = 0.5f * logf((1.0f + arg) / (1.0f - arg));
        sbr[1] = art / (n * sc);
    }
    __syncthreads();
    {
        const int c = tid * 4;
#pragma unroll
        for (int br = 0; br < 3; ++br) {
            float s = (br == 0) ? 1.0f : sbr[br - 1];
            size_t o = ((size_t)br * 8192 + row) * 768 + c;
            *(uint32_t*)&g_x16[o]     = packf16(v.x * s, v.y * s);
            *(uint32_t*)&g_x16[o + 2] = packf16(v.z * s, v.w * s);
        }
    }
}

// ------------------------------------------------------------------
// Kernel 1c: split weights into fp16 hi(+lo) planes.
// ------------------------------------------------------------------
__global__ __launch_bounds__(192) void prep_w(
    const float* __restrict__ wq, const float* __restrict__ wk, const float* __restrict__ wv) {
    const int row = blockIdx.x, mat = blockIdx.y;
    const int typ = mat / 3, br = mat % 3;
    const float* W = (typ == 0 ? wq : typ == 1 ? wk : wv) + (size_t)br * 768 * 768;
    const int c = threadIdx.x * 4;
    float4 v = *(const float4*)&W[(size_t)row * 768 + c];
    size_t o = ((size_t)mat * 768 + row) * 768 + c;
    uint32_t h0 = packf16(v.x, v.y), h1 = packf16(v.z, v.w);
    *(uint32_t*)&g_Wh[o]     = h0;
    *(uint32_t*)&g_Wh[o + 2] = h1;
    if (typ < 2) {
        *(uint32_t*)&g_Wl[o]     = packf16l(v.x, v.y, h0);
        *(uint32_t*)&g_Wl[o + 2] = packf16l(v.z, v.w, h1);
    }
}

// ------------------------------------------------------------------
// Kernel 2: persistent projection GEMM, fp16, cp.async 2-stage,
// K-chunk 64 (12 chunks, 1 barrier each).
// A = fp16 x (1 plane). Q/K: 2 passes (W hi + W lo). V: 1 pass.
// ------------------------------------------------------------------
#define P_PLANE 9216                 // 128*72 halfs per plane (k64 + 8 pad)
#define SA_(st)     ((__half(*)[72])(ps + (st) * P_PLANE))
#define SB_(st, pl) ((__half(*)[72])(ps + (2 + (st) * 2 + (pl)) * P_PLANE))
#define P_SMEM (6 * P_PLANE * 2)     // 110592 B
#define P_TILES 3456

__global__ __launch_bounds__(256, 2) void proj_mma(
    const float* __restrict__ bq, const float* __restrict__ bk, const float* __restrict__ bv)
{
    extern __shared__ __half ps[];
    __shared__ int s_t;
    const int tid = threadIdx.x, lane = tid & 31, warp = tid >> 5;
    const int wr = warp >> 1, wc = warp & 1;
    const int l7 = lane & 7, l8 = lane & 8, l16 = (lane & 16) >> 1;

    for (;;) {
        __syncthreads();
        if (tid == 0) s_t = atomicAdd(&g_tickP, 1);
        __syncthreads();
        const int t = s_t;
        if (t >= P_TILES) break;
        const int rt = t & 63, rem = t >> 6;
        const int ct = rem % 6, mat = rem / 6;
        const int br = mat % 3, typ = mat / 3;

        const __half* Ap = g_x16 + ((size_t)br * 8192 + rt * 128) * 768;
        const __half* Bp[2] = {
            g_Wh + ((size_t)mat * 768 + ct * 128) * 768,
            g_Wl + ((size_t)mat * 768 + ct * 128) * 768 };

        float acc[2][8][4];
#pragma unroll
        for (int i = 0; i < 2; ++i)
#pragma unroll
            for (int j = 0; j < 8; ++j)
#pragma unroll
                for (int k = 0; k < 4; ++k) acc[i][j][k] = 0.f;

        auto load_chunk = [&](int kt, int st) {
#pragma unroll
            for (int i = 0; i < 4; ++i) {            // A: 128 rows x 8 segs
                int idx = i * 256 + tid;
                int seg = idx & 7, row = idx >> 3;
                cp16(smaddr(&SA_(st)[row][seg * 8]),
                     Ap + (size_t)row * 768 + kt * 64 + seg * 8);
            }
            const int nb = (typ == 2) ? 4 : 8;       // B: 1 or 2 planes
            for (int i = 0; i < nb; ++i) {
                int idx = i * 256 + tid;
                int seg = idx & 7, row = (idx >> 3) & 127, pl = idx >> 10;
                cp16(smaddr(&SB_(st, pl)[row][seg * 8]),
                     Bp[pl] + (size_t)row * 768 + kt * 64 + seg * 8);
            }
        };

        load_chunk(0, 0); cp_commit();

        for (int kt = 0; kt < 12; ++kt) {
            const int st = kt & 1;
            cp_wait0();
            __syncthreads();                 // releases compute(kt); proves kt-1 done
            if (kt < 11) { load_chunk(kt + 1, st ^ 1); cp_commit(); }

            __half (*sA)[72]  = SA_(st);
            __half (*sBh)[72] = SB_(st, 0), (*sBl)[72] = SB_(st, 1);
#pragma unroll
            for (int ks = 0; ks < 4; ++ks) {
                const int k0 = ks * 16;
                uint32_t ah[2][4];
#pragma unroll
                for (int mt = 0; mt < 2; ++mt)
                    ldsm4(ah[mt], smaddr(&sA[wr * 32 + mt * 16 + l7 + l8][k0 + l16]));
                uint32_t bh[4][4];
#pragma unroll
                for (int p = 0; p < 4; ++p)
                    ldsm4(bh[p], smaddr(&sBh[wc * 64 + p * 16 + l7 + l16][k0 + l8]));
#pragma unroll
                for (int p = 0; p < 4; ++p)
#pragma unroll
                    for (int mt = 0; mt < 2; ++mt) {
                        mma16h(acc[mt][2 * p],     ah[mt], bh[p]);
                        mma16h(acc[mt][2 * p + 1], ah[mt], bh[p] + 2);
                    }
                if (typ < 2) {
                    uint32_t bl[4][4];
#pragma unroll
                    for (int p = 0; p < 4; ++p)
                        ldsm4(bl[p], smaddr(&sBl[wc * 64 + p * 16 + l7 + l16][k0 + l8]));
#pragma unroll
                    for (int p = 0; p < 4; ++p)
#pragma unroll
                        for (int mt = 0; mt < 2; ++mt) {
                            mma16h(acc[mt][2 * p],     ah[mt], bl[p]);
                            mma16h(acc[mt][2 * p + 1], ah[mt], bl[p] + 2);
                        }
                }
            }
        }

        // epilogue: bias, emit fp16 planes [br][b][h][n][64].
        const float* Bb = (typ == 0 ? bq : typ == 1 ? bk : bv) + br * 768;
        __half* dh = (typ == 0 ? g_Qh : typ == 1 ? g_Kh : g_V);
        __half* dl = (typ == 0 ? g_Ql : g_Kl);
        const float qs = (typ == 0) ? LOG2E : 1.0f;
        const int h  = ct * 2 + wc;
        const int bb = (rt * 128) >> 10;
        const int nb = (rt * 128) & 1023;
        const int tg = lane & 3, g = lane >> 2;
#pragma unroll
        for (int mt = 0; mt < 2; ++mt) {
            int r = wr * 32 + mt * 16 + g;
#pragma unroll
            for (int nt = 0; nt < 8; ++nt) {
                int d = nt * 8 + tg * 2;
                float2 bi = *(const float2*)&Bb[h * 64 + d];
                float v0 = (acc[mt][nt][0] + bi.x) * qs, v1 = (acc[mt][nt][1] + bi.y) * qs;
                float v2 = (acc[mt][nt][2] + bi.x) * qs, v3 = (acc[mt][nt][3] + bi.y) * qs;
                size_t base = ((((size_t)br * 8 + bb) * 12 + h) * 1024 + (nb + r)) * 64 + d;
                uint32_t h0 = packf16(v0, v1), h1 = packf16(v2, v3);
                *(uint32_t*)&dh[base]          = h0;
                *(uint32_t*)&dh[base + 8 * 64] = h1;
                if (typ < 2) {
                    *(uint32_t*)&dl[base]          = packf16l(v0, v1, h0);
                    *(uint32_t*)&dl[base + 8 * 64] = packf16l(v2, v3, h1);
                }
            }
        }
    }
}

// ------------------------------------------------------------------
// Kernel 3: persistent flash attention, fp16, ex2 softmax.
// Ticket = (brn, qt, h, bb). Single barrier per KV tile.
// Cross-branch sum via last-finisher (fixed-order, deterministic).
// ------------------------------------------------------------------
#define AQ_PLANE 9216                // 128*72 halfs
#define AKV_PLANE 4608               // 64*72 halfs
#define SKV_(st, pl) ((__half(*)[72])(as_ + 2 * AQ_PLANE + ((st) * 3 + (pl)) * AKV_PLANE))
#define A_SMEM ((2 * AQ_PLANE + 6 * AKV_PLANE) * 2)   // 92160 B
#define A_TILES 2304

__global__ __launch_bounds__(256, 2) void attn_kernel(float* __restrict__ out) {
    extern __shared__ __half as_[];
    __shared__ int s_t, s_c;
    __half (*sQh)[72] = (__half(*)[72])(as_);
    __half (*sQl)[72] = (__half(*)[72])(as_ + AQ_PLANE);

    const int tid = threadIdx.x, lane = tid & 31, warp = tid >> 5;
    const int g = lane >> 2, tg = lane & 3;
    const int l7 = lane & 7, l8 = lane & 8, l16 = (lane & 16) >> 1;
    const int r0 = warp * 16 + g;

    for (;;) {
        __syncthreads();
        if (tid == 0) s_t = atomicAdd(&g_tickA, 1);
        __syncthreads();
        const int t = s_t;
        if (t >= A_TILES) break;
        const int qt = t & 7, h = (t >> 3) % 12;
        const int r2 = t / 96, bb = r2 & 7, brn = r2 >> 3;
        const int tileid = (bb * 12 + h) * 8 + qt;

        const size_t hb = (((size_t)brn * 8 + bb) * 12 + h) * (size_t)(1024 * 64);
        const __half* KVp[3] = { g_Kh + hb, g_Kl + hb, g_V + hb };
        const __half* Qp[2]  = { g_Qh + hb + (size_t)qt * 128 * 64,
                                 g_Ql + hb + (size_t)qt * 128 * 64 };

        auto loadKV = [&](int jt, int st) {
#pragma unroll
            for (int i = 0; i < 6; ++i) {
                int idx = i * 256 + tid;
                int seg = idx & 7, row = (idx >> 3) & 63, pl = idx >> 9;
                cp16(smaddr(&SKV_(st, pl)[row][seg * 8]),
                     KVp[pl] + (size_t)(jt * 64 + row) * 64 + seg * 8);
            }
        };

#pragma unroll
        for (int i = 0; i < 8; ++i) {
            int idx = i * 256 + tid;
            int seg = idx & 7, row = (idx >> 3) & 127, pl = idx >> 10;
            cp16(smaddr(&(pl ? sQl : sQh)[row][seg * 8]),
                 Qp[pl] + (size_t)row * 64 + seg * 8);
        }
        loadKV(0, 0);
        cp_commit();

        float m0 = -1e30f, m1 = -1e30f, l0 = 0.f, l1 = 0.f;
        float oa[8][4];
#pragma unroll
        for (int i = 0; i < 8; ++i)
#pragma unroll
            for (int j = 0; j < 4; ++j) oa[i][j] = 0.f;

        for (int jt = 0; jt < 16; ++jt) {
            const int st = jt & 1;
            cp_wait0();
            __syncthreads();                 // releases compute(jt); proves jt-1 done
            if (jt < 15) { loadKV(jt + 1, st ^ 1); cp_commit(); }

            __half (*sKh)[72] = SKV_(st, 0), (*sKl)[72] = SKV_(st, 1);
            __half (*sV)[72]  = SKV_(st, 2);

            // ---- S = Q K^T (log2 domain) : fp16 hi/lo, 3 passes ----
            float sf[8][4];
#pragma unroll
            for (int i = 0; i < 8; ++i)
#pragma unroll
                for (int j = 0; j < 4; ++j) sf[i][j] = 0.f;
#pragma unroll
            for (int ks = 0; ks < 4; ++ks) {
                const int k0 = ks * 16;
                uint32_t qh[4], ql[4];
                ldsm4(qh, smaddr(&sQh[warp * 16 + l7 + l8][k0 + l16]));
                ldsm4(ql, smaddr(&sQl[warp * 16 + l7 + l8][k0 + l16]));
                uint32_t kh_[4][4], kl_[4][4];
#pragma unroll
                for (int p = 0; p < 4; ++p) {
                    int n0 = p * 16 + l7 + l16;
                    ldsm4(kh_[p], smaddr(&sKh[n0][k0 + l8]));
                    ldsm4(kl_[p], smaddr(&sKl[n0][k0 + l8]));
                }
#pragma unroll
                for (int p = 0; p < 4; ++p) {
                    mma16h(sf[2 * p],     qh, kh_[p]);
                    mma16h(sf[2 * p + 1], qh, kh_[p] + 2);
                }
#pragma unroll
                for (int p = 0; p < 4; ++p) {
                    mma16h(sf[2 * p],     qh, kl_[p]);
                    mma16h(sf[2 * p + 1], qh, kl_[p] + 2);
                }
#pragma unroll
                for (int p = 0; p < 4; ++p) {
                    mma16h(sf[2 * p],     ql, kh_[p]);
                    mma16h(sf[2 * p + 1], ql, kh_[p] + 2);
                }
            }

            // ---- online softmax (base-2) ----
            float t0 = -1e30f, t1 = -1e30f;
#pragma unroll
            for (int nt = 0; nt < 8; ++nt) {
                t0 = fmaxf(t0, fmaxf(sf[nt][0], sf[nt][1]));
                t1 = fmaxf(t1, fmaxf(sf[nt][2], sf[nt][3]));
            }
            t0 = fmaxf(t0, __shfl_xor_sync(0xffffffffu, t0, 1));
            t0 = fmaxf(t0, __shfl_xor_sync(0xffffffffu, t0, 2));
            t1 = fmaxf(t1, __shfl_xor_sync(0xffffffffu, t1, 1));
            t1 = fmaxf(t1, __shfl_xor_sync(0xffffffffu, t1, 2));
            float mn0 = fmaxf(m0, t0), mn1 = fmaxf(m1, t1);
            float a0 = ex2(m0 - mn0), a1 = ex2(m1 - mn1);
            m0 = mn0; m1 = mn1;

            float rs0 = 0.f, rs1 = 0.f;
#pragma unroll
            for (int nt = 0; nt < 8; ++nt) {
                sf[nt][0] = ex2(sf[nt][0] - mn0);
                sf[nt][1] = ex2(sf[nt][1] - mn0);
                sf[nt][2] = ex2(sf[nt][2] - mn1);
                sf[nt][3] = ex2(sf[nt][3] - mn1);
                rs0 += sf[nt][0] + sf[nt][1];
                rs1 += sf[nt][2] + sf[nt][3];
            }
            l0 = l0 * a0 + rs0;
            l1 = l1 * a1 + rs1;
#pragma unroll
            for (int nt = 0; nt < 8; ++nt) {
                oa[nt][0] *= a0; oa[nt][1] *= a0;
                oa[nt][2] *= a1; oa[nt][3] *= a1;
            }

            // ---- O += P V : fp16 single pass ----
#pragma unroll
            for (int ks = 0; ks < 4; ++ks) {
                uint32_t ph[4];
                ph[0] = packf16(sf[2 * ks][0],     sf[2 * ks][1]);
                ph[1] = packf16(sf[2 * ks][2],     sf[2 * ks][3]);
                ph[2] = packf16(sf[2 * ks + 1][0], sf[2 * ks + 1][1]);
                ph[3] = packf16(sf[2 * ks + 1][2], sf[2 * ks + 1][3]);
                const int kv0 = ks * 16 + l7 + l8;
                uint32_t vh_[4][4];
#pragma unroll
                for (int p = 0; p < 4; ++p) {
                    int d0 = p * 16 + l16;
                    ldsm4t(vh_[p], smaddr(&sV[kv0][d0]));
                }
#pragma unroll
                for (int p = 0; p < 4; ++p) {
                    mma16h(oa[2 * p],     ph, vh_[p]);
                    mma16h(oa[2 * p + 1], ph, vh_[p] + 2);
                }
            }
        }

        // normalize branch result
        float L0 = l0 + __shfl_xor_sync(0xffffffffu, l0, 1);
        L0 += __shfl_xor_sync(0xffffffffu, L0, 2);
        float L1 = l1 + __shfl_xor_sync(0xffffffffu, l1, 1);
        L1 += __shfl_xor_sync(0xffffffffu, L1, 2);
        float i0 = 1.f / L0, i1 = 1.f / L1;
#pragma unroll
        for (int nt = 0; nt < 8; ++nt) {
            oa[nt][0] *= i0; oa[nt][1] *= i0;
            oa[nt][2] *= i1; oa[nt][3] *= i1;
        }

        // last-finisher combine: first two branches store partials;
        // the third sums p0+p1+p2 in fixed order and writes out.
        if (tid == 0) { __threadfence(); s_c = atomicAdd(&g_cnt[tileid], 1); }
        __syncthreads();
        const int old = s_c;
        if (old < 2) {
            float* dst = g_part[brn];
#pragma unroll
            for (int nt = 0; nt < 8; ++nt) {
                int d = nt * 8 + tg * 2;
                size_t base = ((size_t)bb * 1024 + (size_t)(qt * 128 + r0)) * 768 + h * 64 + d;
                *(float2*)&dst[base]                   = make_float2(oa[nt][0], oa[nt][1]);
                *(float2*)&dst[base + (size_t)8 * 768] = make_float2(oa[nt][2], oa[nt][3]);
            }
        } else {
            __threadfence();
            const float* pA = g_part[brn == 0 ? 1 : 0];
            const float* pB = g_part[brn == 2 ? 1 : 2];
#pragma unroll
            for (int nt = 0; nt < 8; ++nt) {
                int d = nt * 8 + tg * 2;
                size_t base = ((size_t)bb * 1024 + (size_t)(qt * 128 + r0)) * 768 + h * 64 + d;
#pragma unroll
                for (int half = 0; half < 2; ++half) {
                    size_t a = base + (size_t)half * 8 * 768;
                    float2 me = make_float2(oa[nt][2 * half], oa[nt][2 * half + 1]);
                    float2 xa = *(const float2*)&pA[a];
                    float2 xb = *(const float2*)&pB[a];
                    float2 s0 = (brn == 0) ? me : xa;
                    float2 s1 = (brn == 1) ? me : (brn == 0 ? xa : xb);
                    float2 s2 = (brn == 2) ? me : xb;
                    float2 r;
                    r.x = (s0.x + s1.x) + s2.x;
                    r.y = (s0.y + s1.y) + s2.y;
                    *(float2*)&out[a] = r;
                }
            }
        }
    }
}

// ------------------------------------------------------------------
extern "C" void kernel_launch(void* const* d_in, const int* in_sizes, int n_in,
                              void* d_out, int out_size) {
    (void)in_sizes; (void)n_in; (void)out_size;
    const float* x  = (const float*)d_in[0];
    const float* wq = (const float*)d_in[1];
    const float* bq = (const float*)d_in[2];
    const float* wk = (const float*)d_in[3];
    const float* bk = (const float*)d_in[4];
    const float* wv = (const float*)d_in[5];
    const float* bv = (const float*)d_in[6];
    float* out = (float*)d_out;

    prep_x_fused<<<8192, 192>>>(x);
    prep_w<<<dim3(768, 9), 192>>>(wq, wk, wv);

    cudaFuncSetAttribute(proj_mma, cudaFuncAttributeMaxDynamicSharedMemorySize, P_SMEM);
    proj_mma<<<NCTA, 256, P_SMEM>>>(bq, bk, bv);

    cudaFuncSetAttribute(attn_kernel, cudaFuncAttributeMaxDynamicSharedMemorySize, A_SMEM);
    attn_kernel<<<NCTA, 256, A_SMEM>>>(out);
}